// round 4
// baseline (speedup 1.0000x reference)
#include <cuda_runtime.h>
#include <math.h>

#define NS 131072           // N_SAMPLES
#define NEV 64              // B*E
#define MF 262144           // FFT length = 2*NS
#define NFRAMES 128
#define CPD 16

struct EvScalars { int vidx; int ridx; float av0; float av1; };

__device__ EvScalars g_sc[NEV];
__device__ unsigned  g_normbits[NEV];   // max |mixed|
__device__ unsigned  g_hmaxbits[NEV];   // max |h|
__device__ float     g_cpw[NEV * 3 * CPD * NFRAMES];   // smix-weighted cp_out
__device__ float     g_mixed[NEV * NS];
__device__ float     g_h[NEV * NS];
__device__ float2    g_tw[MF];
__device__ float2    g_zA[NEV * MF];
__device__ float2    g_zB[NEV * MF];

__device__ __forceinline__ float2 cmul(float2 a, float2 b) {
    return make_float2(a.x * b.x - a.y * b.y, a.x * b.y + a.y * b.x);
}

// ---------------------------------------------------------------------------
// Twiddle table: W[t] = exp(-2*pi*i*t/MF), computed in double for accuracy.
// ---------------------------------------------------------------------------
__global__ void k_tw() {
    int t = blockIdx.x * blockDim.x + threadIdx.x;
    if (t < MF) {
        double ang = -2.0 * 3.14159265358979323846 * (double)t / (double)MF;
        double s, c;
        sincos(ang, &s, &c);
        g_tw[t] = make_float2((float)c, (float)s);
    }
}

// ---------------------------------------------------------------------------
// Per-event prep: argmaxes, softmaxes, cp select + sparsify, 3-block stack.
// One CTA (256 threads) per event.
// ---------------------------------------------------------------------------
__global__ void k_prep(const float* __restrict__ voice, const float* __restrict__ cpc,
                       const float* __restrict__ amp,   const float* __restrict__ rooml,
                       const float* __restrict__ rmix,  const float* __restrict__ cp_items,
                       const float* __restrict__ w1,    const float* __restrict__ w2,
                       const float* __restrict__ decays,const float* __restrict__ gains,
                       const float* __restrict__ mix) {
    int e = blockIdx.x, tid = threadIdx.x;
    __shared__ float s_cp[2048];   // raw cp values
    __shared__ float s_wc[2048];   // working control plane [16][128]
    __shared__ float s_x[2048];
    __shared__ float s_y[2048];
    __shared__ float s_w1[256], s_w2[256];
    __shared__ float s_d[16], s_g[16];
    __shared__ float s_red[256];
    __shared__ float s_smix[3];
    __shared__ int   s_vidx, s_cidx;

    if (tid == 0) {
        const float* v = voice + e * 8;
        int vi = 0; float bv = v[0];
        for (int i = 1; i < 8; i++) if (v[i] > bv) { bv = v[i]; vi = i; }
        s_vidx = vi;
        const float* c = cpc + e * 512;
        int ci = 0; float bc = c[0];
        for (int i = 1; i < 512; i++) if (c[i] > bc) { bc = c[i]; ci = i; }
        s_cidx = ci;
        const float* r = rooml + e * 8;
        int ri = 0; float br = r[0];
        for (int i = 1; i < 8; i++) if (r[i] > br) { br = r[i]; ri = i; }
        // softmax over room_mix (2)
        float m0 = rmix[e * 2 + 0], m1 = rmix[e * 2 + 1];
        float mx = fmaxf(m0, m1);
        float e0 = expf(m0 - mx), e1 = expf(m1 - mx);
        float vm0 = e0 / (e0 + e1), vm1 = e1 / (e0 + e1);
        float a = fabsf(amp[e]);
        g_sc[e].vidx = vi; g_sc[e].ridx = ri;
        g_sc[e].av0 = a * vm0; g_sc[e].av1 = a * vm1;
        // softmax over mix[vi] (3)
        float q0 = mix[vi * 3 + 0], q1 = mix[vi * 3 + 1], q2 = mix[vi * 3 + 2];
        float qm = fmaxf(q0, fmaxf(q1, q2));
        float f0 = expf(q0 - qm), f1 = expf(q1 - qm), f2 = expf(q2 - qm);
        float fs = f0 + f1 + f2;
        s_smix[0] = f0 / fs; s_smix[1] = f1 / fs; s_smix[2] = f2 / fs;
        g_normbits[e] = 0u;
        g_hmaxbits[e] = 0u;
    }
    __syncthreads();
    int vi = s_vidx, ci = s_cidx;

    // load cp row + sum
    float ls = 0.f;
    for (int i = tid; i < 2048; i += 256) {
        float v = cp_items[ci * 2048 + i];
        s_cp[i] = v; ls += v;
    }
    s_red[tid] = ls; __syncthreads();
    for (int o = 128; o > 0; o >>= 1) {
        if (tid < o) s_red[tid] += s_red[tid + o];
        __syncthreads();
    }
    float inv = 1.0f / (s_red[0] + 1e-8f);

    // sparsify: keep entries with rank < 32 (exact top-k; values distinct a.s.)
    float vloc[8]; int cnt[8];
#pragma unroll
    for (int u = 0; u < 8; u++) { vloc[u] = s_cp[tid + 256 * u]; cnt[u] = 0; }
    for (int j = 0; j < 2048; j++) {
        float vj = s_cp[j];
#pragma unroll
        for (int u = 0; u < 8; u++) cnt[u] += (vj > vloc[u]) ? 1 : 0;
    }
#pragma unroll
    for (int u = 0; u < 8; u++)
        s_wc[tid + 256 * u] = (cnt[u] < 32) ? vloc[u] * inv : 0.f;
    __syncthreads();

    // 3 blocks
    for (int blk = 0; blk < 3; blk++) {
        s_w1[tid] = w1[(vi * 3 + blk) * 256 + tid];
        s_w2[tid] = w2[(vi * 3 + blk) * 256 + tid];
        if (tid < 16) {
            float dp = decays[(vi * 3 + blk) * 16 + tid];
            s_d[tid] = 0.5f + (1.f / (1.f + expf(-dp))) * 0.5f;
            float gp = gains[(vi * 3 + blk) * 16 + tid];
            s_g[tid] = (1.f / (1.f + expf(-gp))) * 5.f;
        }
        __syncthreads();
        // x = w1 @ relu(wc)
#pragma unroll
        for (int u = 0; u < 8; u++) {
            int idx = tid + 256 * u;
            int c = idx >> 7, f = idx & 127;
            float acc = 0.f;
#pragma unroll
            for (int k = 0; k < 16; k++)
                acc += s_w1[c * 16 + k] * fmaxf(s_wc[k * 128 + f], 0.f);
            s_x[idx] = acc;
        }
        __syncthreads();
        // decay recurrence: y[t] = d*(x[t] + y[t-1])  == conv with env d^(t+1)
        if (tid < 16) {
            float d = s_d[tid];
            float y = 0.f;
            for (int f = 0; f < 128; f++) {
                y = d * (s_x[tid * 128 + f] + y);
                s_y[tid * 128 + f] = y;
            }
        }
        __syncthreads();
        // x2 = w2 @ y + x;  cp_out = tanh(x2*g);  store smix*cp_out; wc = cp_out
#pragma unroll
        for (int u = 0; u < 8; u++) {
            int idx = tid + 256 * u;
            int c = idx >> 7, f = idx & 127;
            float acc = s_x[idx];
#pragma unroll
            for (int k = 0; k < 16; k++)
                acc += s_w2[c * 16 + k] * s_y[k * 128 + f];
            float co = tanhf(acc * s_g[c]);
            g_cpw[((e * 3 + blk) * 16 + c) * 128 + f] = s_smix[blk] * co;
            s_wc[idx] = co;
        }
        __syncthreads();
    }
}

// ---------------------------------------------------------------------------
// Audio synthesis + mix + per-event max(|mixed|). CTA per (frame, event).
// ---------------------------------------------------------------------------
__global__ void k_audio(const float* __restrict__ audio_maps) {
    int f = blockIdx.x, e = blockIdx.y, tid = threadIdx.x;
    __shared__ float s_c[48];
    __shared__ float s_red[256];
    __shared__ int s_v;
    if (tid == 0) s_v = g_sc[e].vidx;
    if (tid < 48) {
        int i = tid >> 4, c = tid & 15;
        s_c[tid] = g_cpw[((e * 3 + i) * 16 + c) * 128 + f];
    }
    __syncthreads();
    const float* am = audio_maps + (size_t)s_v * 3 * 1024 * 16;
    float lmax = 0.f;
#pragma unroll
    for (int q = 0; q < 4; q++) {
        int w = tid + q * 256;
        float acc = 0.f;
#pragma unroll
        for (int i = 0; i < 3; i++) {
            const float4* row = reinterpret_cast<const float4*>(am + (i * 1024 + w) * 16);
#pragma unroll
            for (int r = 0; r < 4; r++) {
                float4 a4 = __ldg(row + r);
                acc += a4.x * s_c[i * 16 + 4 * r + 0] + a4.y * s_c[i * 16 + 4 * r + 1]
                     + a4.z * s_c[i * 16 + 4 * r + 2] + a4.w * s_c[i * 16 + 4 * r + 3];
            }
        }
        g_mixed[e * NS + f * 1024 + w] = acc;
        lmax = fmaxf(lmax, fabsf(acc));
    }
    s_red[tid] = lmax; __syncthreads();
    for (int o = 128; o > 0; o >>= 1) {
        if (tid < o) s_red[tid] = fmaxf(s_red[tid], s_red[tid + o]);
        __syncthreads();
    }
    if (tid == 0) atomicMax(&g_normbits[e], __float_as_uint(s_red[0]));
}

// ---------------------------------------------------------------------------
// Combined kernel h = amp*(vm0*(verb (x) impulse) + vm1*impulse), 128 taps.
// Also tracks max|h| per event for FFT pre-scaling.
// ---------------------------------------------------------------------------
__global__ void k_h(const float* __restrict__ verbs, const float* __restrict__ times) {
    int e = blockIdx.y, tid = threadIdx.x;
    int t0 = blockIdx.x * 1024;
    __shared__ float s_t[128];
    __shared__ float s_red[256];
    __shared__ EvScalars sc;
    if (tid == 0) sc = g_sc[e];
    if (tid < 128) s_t[tid] = times[e * 128 + tid];
    __syncthreads();
    const float* vb = verbs + sc.ridx * NS;
    float lmax = 0.f;
#pragma unroll
    for (int q = 0; q < 4; q++) {
        int t = t0 + tid + q * 256;
        int fm = t >> 10;
        float acc = 0.f;
        for (int f = 0; f <= fm; f++) acc += s_t[f] * vb[t - 1024 * f];
        float val = sc.av0 * acc;
        if ((t & 1023) == 0) val += sc.av1 * s_t[t >> 10];
        g_h[e * NS + t] = val;
        lmax = fmaxf(lmax, fabsf(val));
    }
    s_red[tid] = lmax; __syncthreads();
    for (int o = 128; o > 0; o >>= 1) {
        if (tid < o) s_red[tid] = fmaxf(s_red[tid], s_red[tid + o]);
        __syncthreads();
    }
    if (tid == 0) atomicMax(&g_hmaxbits[e], __float_as_uint(s_red[0]));
}

// ---------------------------------------------------------------------------
// 4-step FFT (262144 = 512 x 512), shared-memory Stockham radix-2 per 512.
// z = (m/mmax) + i*(h/hmax): both components scaled to O(1) so complex
// butterfly roundoff does not leak the large component into the small one.
// MODE 0: fwd pass1 (pack z, column FFT, twiddle, transpose out)
// MODE 1: fwd pass2 (row FFT) + pointwise square -> zB (natural order)
// MODE 2: inv pass1 (conjugate twiddles) on zB -> zA
// MODE 3: inv pass2 + epilogue: out[t] = Im * 0.5/MF * hscale, t < NS
// ---------------------------------------------------------------------------
template <int MODE>
__global__ void k_fft(float* __restrict__ out) {
    __shared__ float2 buf[2][4][512];
    int e = blockIdx.y;
    int tile = blockIdx.x;     // 128 tiles of 4 columns/rows
    int tid = threadIdx.x;
    int fft = tid >> 6;
    int lane = tid & 63;
    const bool INV = (MODE >= 2);
    int c0 = tile * 4;

    if (MODE == 0) {
        float rs = 1.0f / (__uint_as_float(g_normbits[e]) + 1e-8f);   // reference norm
        float hs = __uint_as_float(g_hmaxbits[e]) + 1e-20f;
        float is = 1.0f / hs;
#pragma unroll
        for (int it = 0; it < 8; it++) {
            int r = (tid >> 2) + 64 * it;
            int c = tid & 3;
            int n = (c0 + c) + 512 * r;
            float re = 0.f, im = 0.f;
            if (n < NS) { re = g_mixed[e * NS + n] * rs; im = g_h[e * NS + n] * is; }
            buf[0][c][r] = make_float2(re, im);
        }
    } else if (MODE == 2) {
#pragma unroll
        for (int it = 0; it < 8; it++) {
            int r = (tid >> 2) + 64 * it;
            int c = tid & 3;
            buf[0][c][r] = g_zB[e * MF + (c0 + c) + 512 * r];
        }
    } else {
#pragma unroll
        for (int it = 0; it < 8; it++) {
            int n1 = lane + 64 * it;
            buf[0][fft][n1] = g_zA[e * MF + (c0 + fft) * 512 + n1];
        }
    }

    int src = 0;
    int fac = 512;
#pragma unroll
    for (int s = 0; s < 9; s++) {
        int m = 1 << s;
        __syncthreads();
#pragma unroll
        for (int u = 0; u < 4; u++) {
            int p = lane + 64 * u;          // butterfly id 0..255
            int j = p >> s;
            float2 w = g_tw[j * fac];
            if (INV) w.y = -w.y;
            float2 a = buf[src][fft][p];
            float2 b = buf[src][fft][p + 256];
            float2 sum = make_float2(a.x + b.x, a.y + b.y);
            float2 dif = make_float2(a.x - b.x, a.y - b.y);
            float2 wd = cmul(w, dif);
            int q0 = p + j * m;
            buf[src ^ 1][fft][q0] = sum;
            buf[src ^ 1][fft][q0 + m] = wd;
        }
        src ^= 1;
        fac <<= 1;
    }
    __syncthreads();

    if (MODE == 0 || MODE == 2) {
        // inter-pass twiddle W^(n1*k2), store transposed
#pragma unroll
        for (int it = 0; it < 8; it++) {
            int k2 = (tid >> 2) + 64 * it;
            int c = tid & 3;
            int n1 = c0 + c;
            float2 v = buf[src][c][k2];
            float2 w = g_tw[n1 * k2];
            if (INV) w.y = -w.y;
            g_zA[e * MF + k2 * 512 + n1] = cmul(v, w);
        }
    } else if (MODE == 1) {
        // natural-order spectrum, pointwise square (Im(IFFT(Z^2)) = 2*m(x)h)
#pragma unroll
        for (int it = 0; it < 8; it++) {
            int k1 = (tid >> 2) + 64 * it;
            int c = tid & 3;
            float2 z = buf[src][c][k1];
            g_zB[e * MF + (c0 + c) + 512 * k1] =
                make_float2(z.x * z.x - z.y * z.y, 2.f * z.x * z.y);
        }
    } else {
        float hs = __uint_as_float(g_hmaxbits[e]) + 1e-20f;
        const float scale = 0.5f / (float)MF;
#pragma unroll
        for (int it = 0; it < 4; it++) {   // only k1 < 256 -> t < NS
            int k1 = (tid >> 2) + 64 * it;
            int c = tid & 3;
            int t = (c0 + c) + 512 * k1;
            float2 z = buf[src][c][k1];
            out[e * NS + t] = z.y * scale * hs;
        }
    }
}

// ---------------------------------------------------------------------------
extern "C" void kernel_launch(void* const* d_in, const int* in_sizes, int n_in,
                              void* d_out, int out_size) {
    const float* voice    = (const float*)d_in[0];
    const float* cpc      = (const float*)d_in[1];
    const float* amp      = (const float*)d_in[2];
    const float* rooml    = (const float*)d_in[3];
    const float* rmix     = (const float*)d_in[4];
    const float* times    = (const float*)d_in[5];
    const float* cp_items = (const float*)d_in[6];
    const float* verbs    = (const float*)d_in[7];
    const float* w1       = (const float*)d_in[8];
    const float* w2       = (const float*)d_in[9];
    const float* amaps    = (const float*)d_in[10];
    const float* decays   = (const float*)d_in[11];
    const float* gains    = (const float*)d_in[12];
    const float* mix      = (const float*)d_in[13];
    float* out = (float*)d_out;

    k_tw<<<1024, 256>>>();
    k_prep<<<64, 256>>>(voice, cpc, amp, rooml, rmix, cp_items, w1, w2, decays, gains, mix);
    k_audio<<<dim3(128, 64), 256>>>(amaps);
    k_h<<<dim3(128, 64), 256>>>(verbs, times);
    k_fft<0><<<dim3(128, 64), 256>>>(out);
    k_fft<1><<<dim3(128, 64), 256>>>(out);
    k_fft<2><<<dim3(128, 64), 256>>>(out);
    k_fft<3><<<dim3(128, 64), 256>>>(out);
}

// round 5
// speedup vs baseline: 1.4582x; 1.4582x over previous
#include <cuda_runtime.h>
#include <math.h>

#define NS 131072           // N_SAMPLES
#define NEV 64              // B*E
#define MF 262144           // FFT length = 2*NS
#define NFRAMES 128
#define CPD 16

struct EvScalars { int vidx; int ridx; float av0; float av1; };

__device__ EvScalars g_sc[NEV];
__device__ unsigned  g_normbits[NEV];   // max |mixed|
__device__ unsigned  g_hmaxbits[NEV];   // max |h|
__device__ float     g_cpw[NEV * 3 * CPD * NFRAMES];   // smix-weighted cp_out
__device__ float     g_mixed[NEV * NS];
__device__ float     g_h[NEV * NS];
__device__ float2    g_tw[MF];
__device__ float2    g_zA[NEV * MF];
__device__ float2    g_zB[NEV * MF];

__device__ __forceinline__ float2 cmul(float2 a, float2 b) {
    return make_float2(a.x * b.x - a.y * b.y, a.x * b.y + a.y * b.x);
}
__device__ __forceinline__ float2 cadd(float2 a, float2 b){return make_float2(a.x+b.x,a.y+b.y);}
__device__ __forceinline__ float2 csub(float2 a, float2 b){return make_float2(a.x-b.x,a.y-b.y);}

template<bool INV>
__device__ __forceinline__ float2 mulj(float2 a) {  // * (-i) fwd, * (+i) inv
    return INV ? make_float2(-a.y, a.x) : make_float2(a.y, -a.x);
}
template<bool INV>
__device__ __forceinline__ float2 twmul(float2 a, float2 w) {
    if (INV) w.y = -w.y;
    return cmul(a, w);
}

// 8-point DFT, natural-order in/out (DIF radix-2 x3 with bit-reversal folded in)
template<bool INV>
__device__ __forceinline__ void dft8(float2 v[8]) {
    const float C = 0.70710678118654752f;
    float2 b0=cadd(v[0],v[4]), b4=csub(v[0],v[4]);
    float2 b1=cadd(v[1],v[5]), b5=csub(v[1],v[5]);
    float2 b2=cadd(v[2],v[6]), b6=csub(v[2],v[6]);
    float2 b3=cadd(v[3],v[7]), b7=csub(v[3],v[7]);
    b5 = INV ? make_float2(C*(b5.x-b5.y), C*(b5.x+b5.y))
             : make_float2(C*(b5.x+b5.y), C*(b5.y-b5.x));
    b6 = mulj<INV>(b6);
    b7 = INV ? make_float2(-C*(b7.x+b7.y), C*(b7.x-b7.y))
             : make_float2(C*(b7.y-b7.x), -C*(b7.x+b7.y));
    float2 c0=cadd(b0,b2), c2=csub(b0,b2);
    float2 c1=cadd(b1,b3), c3=mulj<INV>(csub(b1,b3));
    float2 c4=cadd(b4,b6), c6=csub(b4,b6);
    float2 c5=cadd(b5,b7), c7=mulj<INV>(csub(b5,b7));
    v[0]=cadd(c0,c1); v[4]=csub(c0,c1);
    v[2]=cadd(c2,c3); v[6]=csub(c2,c3);
    v[1]=cadd(c4,c5); v[5]=csub(c4,c5);
    v[3]=cadd(c6,c7); v[7]=csub(c6,c7);
}

// ---------------------------------------------------------------------------
// 512-point FFT, radix-8^3, 64 threads per FFT (8 FFTs per 512-thread CTA).
// Data in sRe/sIm planes at [f*584 + n] natural order on entry and exit.
// Padded exchange layouts (stride 72 / 9) are conflict-free for all phases.
// ---------------------------------------------------------------------------
template<bool INV>
__device__ __forceinline__ void fft512(float* sRe, float* sIm, const float2* sW, int tid) {
    int t = tid & 63;
    int base = (tid >> 6) * 584;
    float2 v[8];
    // pass 1: m = t, radix-8 over n2 (stride 64), twiddle W512^(m*k0)
#pragma unroll
    for (int j = 0; j < 8; j++) {
        int a = base + t + 64 * j;
        v[j] = make_float2(sRe[a], sIm[a]);
    }
    dft8<INV>(v);
#pragma unroll
    for (int k0 = 1; k0 < 8; k0++) v[k0] = twmul<INV>(v[k0], sW[t * k0]);
    __syncthreads();
#pragma unroll
    for (int k0 = 0; k0 < 8; k0++) {
        int a = base + 72 * k0 + t;
        sRe[a] = v[k0].x; sIm[a] = v[k0].y;
    }
    __syncthreads();
    int k0 = t >> 3, r = t & 7;
    // pass 2: radix-8 over m1, twiddle W64^(m0*k1)
#pragma unroll
    for (int m1 = 0; m1 < 8; m1++) {
        int a = base + 72 * k0 + r + 8 * m1;
        v[m1] = make_float2(sRe[a], sIm[a]);
    }
    dft8<INV>(v);
#pragma unroll
    for (int k1 = 1; k1 < 8; k1++) v[k1] = twmul<INV>(v[k1], sW[8 * r * k1]);
    __syncthreads();
#pragma unroll
    for (int k1 = 0; k1 < 8; k1++) {
        int a = base + 72 * k0 + 9 * k1 + r;
        sRe[a] = v[k1].x; sIm[a] = v[k1].y;
    }
    __syncthreads();
    // pass 3: radix-8 over m0; output k = k0 + 8*k1 + 64*k2 natural
#pragma unroll
    for (int m0 = 0; m0 < 8; m0++) {
        int a = base + 72 * k0 + 9 * r + m0;
        v[m0] = make_float2(sRe[a], sIm[a]);
    }
    dft8<INV>(v);
    __syncthreads();
#pragma unroll
    for (int k2 = 0; k2 < 8; k2++) {
        int a = base + k0 + 8 * r + 64 * k2;
        sRe[a] = v[k2].x; sIm[a] = v[k2].y;
    }
    __syncthreads();
}

// ---------------------------------------------------------------------------
// Twiddle table: W[t] = exp(-2*pi*i*t/MF), computed in double for accuracy.
// ---------------------------------------------------------------------------
__global__ void k_tw() {
    int t = blockIdx.x * blockDim.x + threadIdx.x;
    if (t < MF) {
        double ang = -2.0 * 3.14159265358979323846 * (double)t / (double)MF;
        double s, c;
        sincos(ang, &s, &c);
        g_tw[t] = make_float2((float)c, (float)s);
    }
}

// ---------------------------------------------------------------------------
// Per-event prep: argmaxes, softmaxes, cp select + sparsify, 3-block stack.
// ---------------------------------------------------------------------------
__global__ void k_prep(const float* __restrict__ voice, const float* __restrict__ cpc,
                       const float* __restrict__ amp,   const float* __restrict__ rooml,
                       const float* __restrict__ rmix,  const float* __restrict__ cp_items,
                       const float* __restrict__ w1,    const float* __restrict__ w2,
                       const float* __restrict__ decays,const float* __restrict__ gains,
                       const float* __restrict__ mix) {
    int e = blockIdx.x, tid = threadIdx.x;
    __shared__ float s_cp[2048];
    __shared__ float s_wc[2048];
    __shared__ float s_x[2048];
    __shared__ float s_y[2048];
    __shared__ float s_w1[256], s_w2[256];
    __shared__ float s_d[16], s_g[16];
    __shared__ float s_red[256];
    __shared__ float s_smix[3];
    __shared__ int   s_vidx, s_cidx;

    if (tid == 0) {
        const float* v = voice + e * 8;
        int vi = 0; float bv = v[0];
        for (int i = 1; i < 8; i++) if (v[i] > bv) { bv = v[i]; vi = i; }
        s_vidx = vi;
        const float* c = cpc + e * 512;
        int ci = 0; float bc = c[0];
        for (int i = 1; i < 512; i++) if (c[i] > bc) { bc = c[i]; ci = i; }
        s_cidx = ci;
        const float* r = rooml + e * 8;
        int ri = 0; float br = r[0];
        for (int i = 1; i < 8; i++) if (r[i] > br) { br = r[i]; ri = i; }
        float m0 = rmix[e * 2 + 0], m1 = rmix[e * 2 + 1];
        float mx = fmaxf(m0, m1);
        float e0 = expf(m0 - mx), e1 = expf(m1 - mx);
        float vm0 = e0 / (e0 + e1), vm1 = e1 / (e0 + e1);
        float a = fabsf(amp[e]);
        g_sc[e].vidx = vi; g_sc[e].ridx = ri;
        g_sc[e].av0 = a * vm0; g_sc[e].av1 = a * vm1;
        float q0 = mix[vi * 3 + 0], q1 = mix[vi * 3 + 1], q2 = mix[vi * 3 + 2];
        float qm = fmaxf(q0, fmaxf(q1, q2));
        float f0 = expf(q0 - qm), f1 = expf(q1 - qm), f2 = expf(q2 - qm);
        float fs = f0 + f1 + f2;
        s_smix[0] = f0 / fs; s_smix[1] = f1 / fs; s_smix[2] = f2 / fs;
        g_normbits[e] = 0u;
        g_hmaxbits[e] = 0u;
    }
    __syncthreads();
    int vi = s_vidx, ci = s_cidx;

    float ls = 0.f;
    for (int i = tid; i < 2048; i += 256) {
        float v = cp_items[ci * 2048 + i];
        s_cp[i] = v; ls += v;
    }
    s_red[tid] = ls; __syncthreads();
    for (int o = 128; o > 0; o >>= 1) {
        if (tid < o) s_red[tid] += s_red[tid + o];
        __syncthreads();
    }
    float inv = 1.0f / (s_red[0] + 1e-8f);

    float vloc[8]; int cnt[8];
#pragma unroll
    for (int u = 0; u < 8; u++) { vloc[u] = s_cp[tid + 256 * u]; cnt[u] = 0; }
    for (int j = 0; j < 2048; j++) {
        float vj = s_cp[j];
#pragma unroll
        for (int u = 0; u < 8; u++) cnt[u] += (vj > vloc[u]) ? 1 : 0;
    }
#pragma unroll
    for (int u = 0; u < 8; u++)
        s_wc[tid + 256 * u] = (cnt[u] < 32) ? vloc[u] * inv : 0.f;
    __syncthreads();

    for (int blk = 0; blk < 3; blk++) {
        s_w1[tid] = w1[(vi * 3 + blk) * 256 + tid];
        s_w2[tid] = w2[(vi * 3 + blk) * 256 + tid];
        if (tid < 16) {
            float dp = decays[(vi * 3 + blk) * 16 + tid];
            s_d[tid] = 0.5f + (1.f / (1.f + expf(-dp))) * 0.5f;
            float gp = gains[(vi * 3 + blk) * 16 + tid];
            s_g[tid] = (1.f / (1.f + expf(-gp))) * 5.f;
        }
        __syncthreads();
#pragma unroll
        for (int u = 0; u < 8; u++) {
            int idx = tid + 256 * u;
            int c = idx >> 7, f = idx & 127;
            float acc = 0.f;
#pragma unroll
            for (int k = 0; k < 16; k++)
                acc += s_w1[c * 16 + k] * fmaxf(s_wc[k * 128 + f], 0.f);
            s_x[idx] = acc;
        }
        __syncthreads();
        if (tid < 16) {
            float d = s_d[tid];
            float y = 0.f;
            for (int f = 0; f < 128; f++) {
                y = d * (s_x[tid * 128 + f] + y);
                s_y[tid * 128 + f] = y;
            }
        }
        __syncthreads();
#pragma unroll
        for (int u = 0; u < 8; u++) {
            int idx = tid + 256 * u;
            int c = idx >> 7, f = idx & 127;
            float acc = s_x[idx];
#pragma unroll
            for (int k = 0; k < 16; k++)
                acc += s_w2[c * 16 + k] * s_y[k * 128 + f];
            float co = tanhf(acc * s_g[c]);
            g_cpw[((e * 3 + blk) * 16 + c) * 128 + f] = s_smix[blk] * co;
            s_wc[idx] = co;
        }
        __syncthreads();
    }
}

// ---------------------------------------------------------------------------
// Audio synthesis + mix + per-event max(|mixed|).
// ---------------------------------------------------------------------------
__global__ void k_audio(const float* __restrict__ audio_maps) {
    int f = blockIdx.x, e = blockIdx.y, tid = threadIdx.x;
    __shared__ float s_c[48];
    __shared__ float s_red[256];
    __shared__ int s_v;
    if (tid == 0) s_v = g_sc[e].vidx;
    if (tid < 48) {
        int i = tid >> 4, c = tid & 15;
        s_c[tid] = g_cpw[((e * 3 + i) * 16 + c) * 128 + f];
    }
    __syncthreads();
    const float* am = audio_maps + (size_t)s_v * 3 * 1024 * 16;
    float lmax = 0.f;
#pragma unroll
    for (int q = 0; q < 4; q++) {
        int w = tid + q * 256;
        float acc = 0.f;
#pragma unroll
        for (int i = 0; i < 3; i++) {
            const float4* row = reinterpret_cast<const float4*>(am + (i * 1024 + w) * 16);
#pragma unroll
            for (int r = 0; r < 4; r++) {
                float4 a4 = __ldg(row + r);
                acc += a4.x * s_c[i * 16 + 4 * r + 0] + a4.y * s_c[i * 16 + 4 * r + 1]
                     + a4.z * s_c[i * 16 + 4 * r + 2] + a4.w * s_c[i * 16 + 4 * r + 3];
            }
        }
        g_mixed[e * NS + f * 1024 + w] = acc;
        lmax = fmaxf(lmax, fabsf(acc));
    }
    s_red[tid] = lmax; __syncthreads();
    for (int o = 128; o > 0; o >>= 1) {
        if (tid < o) s_red[tid] = fmaxf(s_red[tid], s_red[tid + o]);
        __syncthreads();
    }
    if (tid == 0) atomicMax(&g_normbits[e], __float_as_uint(s_red[0]));
}

// ---------------------------------------------------------------------------
// h = amp*(vm0*(verb (x) impulse) + vm1*impulse), 128 taps. 4 accumulators.
// ---------------------------------------------------------------------------
__global__ void k_h(const float* __restrict__ verbs, const float* __restrict__ times) {
    int e = blockIdx.y, tid = threadIdx.x;
    int t0 = blockIdx.x * 1024;
    __shared__ float s_t[128];
    __shared__ float s_red[256];
    __shared__ EvScalars sc;
    if (tid == 0) sc = g_sc[e];
    if (tid < 128) s_t[tid] = times[e * 128 + tid];
    __syncthreads();
    const float* vb = verbs + sc.ridx * NS;
    float lmax = 0.f;
#pragma unroll
    for (int q = 0; q < 4; q++) {
        int t = t0 + tid + q * 256;
        int fm = t >> 10;          // taps 0..fm inclusive
        float a0 = 0.f, a1 = 0.f, a2 = 0.f, a3 = 0.f;
        const float* vp = vb + t;
        int f = 0;
        int nf = fm + 1;
        for (; f + 4 <= nf; f += 4) {
            a0 += s_t[f + 0] * vp[-1024 * (f + 0)];
            a1 += s_t[f + 1] * vp[-1024 * (f + 1)];
            a2 += s_t[f + 2] * vp[-1024 * (f + 2)];
            a3 += s_t[f + 3] * vp[-1024 * (f + 3)];
        }
        for (; f < nf; f++) a0 += s_t[f] * vp[-1024 * f];
        float acc = (a0 + a1) + (a2 + a3);
        float val = sc.av0 * acc;
        if ((t & 1023) == 0) val += sc.av1 * s_t[t >> 10];
        g_h[e * NS + t] = val;
        lmax = fmaxf(lmax, fabsf(val));
    }
    s_red[tid] = lmax; __syncthreads();
    for (int o = 128; o > 0; o >>= 1) {
        if (tid < o) s_red[tid] = fmaxf(s_red[tid], s_red[tid + o]);
        __syncthreads();
    }
    if (tid == 0) atomicMax(&g_hmaxbits[e], __float_as_uint(s_red[0]));
}

// ---------------------------------------------------------------------------
// 4-step FFT (262144 = 512 x 512), radix-8 inner FFT, 8 columns/rows per CTA.
// z = (m/mmax) + i*(h/hmax) so butterfly roundoff cannot leak the large
// component into the small one.
// MODE 0: fwd pass1 (pack z, column FFT, twiddle, transpose out)
// MODE 1: fwd pass2 (row FFT) + pointwise square -> zB (natural order)
// MODE 2: inv pass1 (conjugate twiddles) on zB -> zA
// MODE 3: inv pass2 + epilogue: out[t] = Im * 0.5/MF * hscale, t < NS
// ---------------------------------------------------------------------------
template <int MODE>
__global__ void __launch_bounds__(512) k_fft2(float* __restrict__ out) {
    __shared__ float sRe[8 * 584];
    __shared__ float sIm[8 * 584];
    __shared__ float2 sW[512];
    int e = blockIdx.y, tile = blockIdx.x, tid = threadIdx.x;
    int c0 = tile * 8;
    const bool INV = (MODE >= 2);

    if (tid < 512) sW[tid] = g_tw[tid * 512];

    if (MODE == 0) {
        float rs = 1.0f / (__uint_as_float(g_normbits[e]) + 1e-8f);
        float is = 1.0f / (__uint_as_float(g_hmaxbits[e]) + 1e-20f);
#pragma unroll
        for (int it = 0; it < 8; it++) {
            int lin = tid + 512 * it;
            int f = lin & 7, r = lin >> 3;
            int n = c0 + f + 512 * r;
            float re = 0.f, im = 0.f;
            if (n < NS) { re = g_mixed[e * NS + n] * rs; im = g_h[e * NS + n] * is; }
            sRe[f * 584 + r] = re; sIm[f * 584 + r] = im;
        }
    } else if (MODE == 2) {
#pragma unroll
        for (int it = 0; it < 8; it++) {
            int lin = tid + 512 * it;
            int f = lin & 7, r = lin >> 3;
            float2 z = g_zB[e * MF + (c0 + f) + 512 * r];
            sRe[f * 584 + r] = z.x; sIm[f * 584 + r] = z.y;
        }
    } else {   // MODE 1, 3: rows of zA, fully contiguous
#pragma unroll
        for (int it = 0; it < 8; it++) {
            int lin = tid + 512 * it;
            int f = lin >> 9, n1 = lin & 511;
            float2 z = g_zA[e * MF + (c0 + f) * 512 + n1];
            sRe[f * 584 + n1] = z.x; sIm[f * 584 + n1] = z.y;
        }
    }
    __syncthreads();

    fft512<INV>(sRe, sIm, sW, tid);   // ends with __syncthreads()

    if (MODE == 0 || MODE == 2) {
#pragma unroll
        for (int it = 0; it < 8; it++) {
            int lin = tid + 512 * it;
            int f = lin & 7, k = lin >> 3;
            float2 v = make_float2(sRe[f * 584 + k], sIm[f * 584 + k]);
            float2 w = g_tw[(c0 + f) * k];
            if (INV) w.y = -w.y;
            g_zA[e * MF + k * 512 + (c0 + f)] = cmul(v, w);
        }
    } else if (MODE == 1) {
#pragma unroll
        for (int it = 0; it < 8; it++) {
            int lin = tid + 512 * it;
            int f = lin & 7, k = lin >> 3;
            float2 z = make_float2(sRe[f * 584 + k], sIm[f * 584 + k]);
            g_zB[e * MF + (c0 + f) + 512 * k] =
                make_float2(z.x * z.x - z.y * z.y, 2.f * z.x * z.y);
        }
    } else {
        float hs = __uint_as_float(g_hmaxbits[e]) + 1e-20f;
        const float scale = 0.5f / (float)MF;
#pragma unroll
        for (int it = 0; it < 4; it++) {   // only k < 256 -> t < NS
            int lin = tid + 512 * it;
            int f = lin & 7, k = lin >> 3;
            out[e * NS + (c0 + f) + 512 * k] = sIm[f * 584 + k] * scale * hs;
        }
    }
}

// ---------------------------------------------------------------------------
extern "C" void kernel_launch(void* const* d_in, const int* in_sizes, int n_in,
                              void* d_out, int out_size) {
    const float* voice    = (const float*)d_in[0];
    const float* cpc      = (const float*)d_in[1];
    const float* amp      = (const float*)d_in[2];
    const float* rooml    = (const float*)d_in[3];
    const float* rmix     = (const float*)d_in[4];
    const float* times    = (const float*)d_in[5];
    const float* cp_items = (const float*)d_in[6];
    const float* verbs    = (const float*)d_in[7];
    const float* w1       = (const float*)d_in[8];
    const float* w2       = (const float*)d_in[9];
    const float* amaps    = (const float*)d_in[10];
    const float* decays   = (const float*)d_in[11];
    const float* gains    = (const float*)d_in[12];
    const float* mix      = (const float*)d_in[13];
    float* out = (float*)d_out;

    k_tw<<<1024, 256>>>();
    k_prep<<<64, 256>>>(voice, cpc, amp, rooml, rmix, cp_items, w1, w2, decays, gains, mix);
    k_audio<<<dim3(128, 64), 256>>>(amaps);
    k_h<<<dim3(128, 64), 256>>>(verbs, times);
    k_fft2<0><<<dim3(64, 64), 512>>>(out);
    k_fft2<1><<<dim3(64, 64), 512>>>(out);
    k_fft2<2><<<dim3(64, 64), 512>>>(out);
    k_fft2<3><<<dim3(64, 64), 512>>>(out);
}

// round 7
// speedup vs baseline: 1.8810x; 1.2899x over previous
#include <cuda_runtime.h>
#include <math.h>

#define NS 131072           // N_SAMPLES
#define NEV 64              // B*E
#define MF 262144           // FFT length = 2*NS
#define NFRAMES 128
#define CPD 16

struct EvScalars { int vidx; int ridx; float av0; float av1; };

__device__ EvScalars g_sc[NEV];
__device__ unsigned  g_normbits[NEV];   // max |mixed|
__device__ unsigned  g_hmaxbits[NEV];   // max |h|
__device__ float     g_cpw[NEV * 3 * CPD * NFRAMES];   // smix-weighted cp_out
__device__ float     g_mixed[NEV * NS];
__device__ float     g_h[NEV * NS];
__device__ float2    g_tw[MF];
// zA: inter-pass scratch (64 slots). zB: spectra, natural frequency order:
//   slots 0..31  = packed (m_{2p}, m_{2p+1}) spectra -> product spectra (in place)
//   slots 32..63 = packed (h_{2p}, h_{2p+1}) spectra
__device__ float2    g_zA[NEV * MF];
__device__ float2    g_zB[NEV * MF];

__device__ __forceinline__ float2 cmul(float2 a, float2 b) {
    return make_float2(a.x * b.x - a.y * b.y, a.x * b.y + a.y * b.x);
}
__device__ __forceinline__ float2 cadd(float2 a, float2 b){return make_float2(a.x+b.x,a.y+b.y);}
__device__ __forceinline__ float2 csub(float2 a, float2 b){return make_float2(a.x-b.x,a.y-b.y);}

template<bool INV>
__device__ __forceinline__ float2 mulj(float2 a) {  // * (-i) fwd, * (+i) inv
    return INV ? make_float2(-a.y, a.x) : make_float2(a.y, -a.x);
}
template<bool INV>
__device__ __forceinline__ float2 twmul(float2 a, float2 w) {
    if (INV) w.y = -w.y;
    return cmul(a, w);
}

// 8-point DFT, natural-order in/out
template<bool INV>
__device__ __forceinline__ void dft8(float2 v[8]) {
    const float C = 0.70710678118654752f;
    float2 b0=cadd(v[0],v[4]), b4=csub(v[0],v[4]);
    float2 b1=cadd(v[1],v[5]), b5=csub(v[1],v[5]);
    float2 b2=cadd(v[2],v[6]), b6=csub(v[2],v[6]);
    float2 b3=cadd(v[3],v[7]), b7=csub(v[3],v[7]);
    b5 = INV ? make_float2(C*(b5.x-b5.y), C*(b5.x+b5.y))
             : make_float2(C*(b5.x+b5.y), C*(b5.y-b5.x));
    b6 = mulj<INV>(b6);
    b7 = INV ? make_float2(-C*(b7.x+b7.y), C*(b7.x-b7.y))
             : make_float2(C*(b7.y-b7.x), -C*(b7.x+b7.y));
    float2 c0=cadd(b0,b2), c2=csub(b0,b2);
    float2 c1=cadd(b1,b3), c3=mulj<INV>(csub(b1,b3));
    float2 c4=cadd(b4,b6), c6=csub(b4,b6);
    float2 c5=cadd(b5,b7), c7=mulj<INV>(csub(b5,b7));
    v[0]=cadd(c0,c1); v[4]=csub(c0,c1);
    v[2]=cadd(c2,c3); v[6]=csub(c2,c3);
    v[1]=cadd(c4,c5); v[5]=csub(c4,c5);
    v[3]=cadd(c6,c7); v[7]=csub(c6,c7);
}

// ---------------------------------------------------------------------------
// 512-point FFT, radix-8^3, 64 threads per FFT (8 FFTs per 512-thread CTA).
// ---------------------------------------------------------------------------
template<bool INV>
__device__ __forceinline__ void fft512(float* sRe, float* sIm, const float2* sW, int tid) {
    int t = tid & 63;
    int base = (tid >> 6) * 584;
    float2 v[8];
#pragma unroll
    for (int j = 0; j < 8; j++) {
        int a = base + t + 64 * j;
        v[j] = make_float2(sRe[a], sIm[a]);
    }
    dft8<INV>(v);
#pragma unroll
    for (int k0 = 1; k0 < 8; k0++) v[k0] = twmul<INV>(v[k0], sW[t * k0]);
    __syncthreads();
#pragma unroll
    for (int k0 = 0; k0 < 8; k0++) {
        int a = base + 72 * k0 + t;
        sRe[a] = v[k0].x; sIm[a] = v[k0].y;
    }
    __syncthreads();
    int k0 = t >> 3, r = t & 7;
#pragma unroll
    for (int m1 = 0; m1 < 8; m1++) {
        int a = base + 72 * k0 + r + 8 * m1;
        v[m1] = make_float2(sRe[a], sIm[a]);
    }
    dft8<INV>(v);
#pragma unroll
    for (int k1 = 1; k1 < 8; k1++) v[k1] = twmul<INV>(v[k1], sW[8 * r * k1]);
    __syncthreads();
#pragma unroll
    for (int k1 = 0; k1 < 8; k1++) {
        int a = base + 72 * k0 + 9 * k1 + r;
        sRe[a] = v[k1].x; sIm[a] = v[k1].y;
    }
    __syncthreads();
#pragma unroll
    for (int m0 = 0; m0 < 8; m0++) {
        int a = base + 72 * k0 + 9 * r + m0;
        v[m0] = make_float2(sRe[a], sIm[a]);
    }
    dft8<INV>(v);
    __syncthreads();
#pragma unroll
    for (int k2 = 0; k2 < 8; k2++) {
        int a = base + k0 + 8 * r + 64 * k2;
        sRe[a] = v[k2].x; sIm[a] = v[k2].y;
    }
    __syncthreads();
}

// ---------------------------------------------------------------------------
__global__ void k_tw() {
    int t = blockIdx.x * blockDim.x + threadIdx.x;
    if (t < MF) {
        double ang = -2.0 * 3.14159265358979323846 * (double)t / (double)MF;
        double s, c;
        sincos(ang, &s, &c);
        g_tw[t] = make_float2((float)c, (float)s);
    }
}

// ---------------------------------------------------------------------------
// Per-event prep: argmaxes, softmaxes, cp select + sparsify, 3-block stack.
// ---------------------------------------------------------------------------
__global__ void k_prep(const float* __restrict__ voice, const float* __restrict__ cpc,
                       const float* __restrict__ amp,   const float* __restrict__ rooml,
                       const float* __restrict__ rmix,  const float* __restrict__ cp_items,
                       const float* __restrict__ w1,    const float* __restrict__ w2,
                       const float* __restrict__ decays,const float* __restrict__ gains,
                       const float* __restrict__ mix) {
    int e = blockIdx.x, tid = threadIdx.x;
    __shared__ float s_cp[2048];
    __shared__ float s_wc[2048];
    __shared__ float s_x[2048];
    __shared__ float s_y[2048];
    __shared__ float s_w1[256], s_w2[256];
    __shared__ float s_d[16], s_g[16];
    __shared__ float s_red[256];
    __shared__ float s_smix[3];
    __shared__ int   s_vidx, s_cidx;

    if (tid == 0) {
        const float* v = voice + e * 8;
        int vi = 0; float bv = v[0];
        for (int i = 1; i < 8; i++) if (v[i] > bv) { bv = v[i]; vi = i; }
        s_vidx = vi;
        const float* c = cpc + e * 512;
        int ci = 0; float bc = c[0];
        for (int i = 1; i < 512; i++) if (c[i] > bc) { bc = c[i]; ci = i; }
        s_cidx = ci;
        const float* r = rooml + e * 8;
        int ri = 0; float br = r[0];
        for (int i = 1; i < 8; i++) if (r[i] > br) { br = r[i]; ri = i; }
        float m0 = rmix[e * 2 + 0], m1 = rmix[e * 2 + 1];
        float mx = fmaxf(m0, m1);
        float e0 = expf(m0 - mx), e1 = expf(m1 - mx);
        float vm0 = e0 / (e0 + e1), vm1 = e1 / (e0 + e1);
        float a = fabsf(amp[e]);
        g_sc[e].vidx = vi; g_sc[e].ridx = ri;
        g_sc[e].av0 = a * vm0; g_sc[e].av1 = a * vm1;
        float q0 = mix[vi * 3 + 0], q1 = mix[vi * 3 + 1], q2 = mix[vi * 3 + 2];
        float qm = fmaxf(q0, fmaxf(q1, q2));
        float f0 = expf(q0 - qm), f1 = expf(q1 - qm), f2 = expf(q2 - qm);
        float fs = f0 + f1 + f2;
        s_smix[0] = f0 / fs; s_smix[1] = f1 / fs; s_smix[2] = f2 / fs;
        g_normbits[e] = 0u;
        g_hmaxbits[e] = 0u;
    }
    __syncthreads();
    int vi = s_vidx, ci = s_cidx;

    float ls = 0.f;
    for (int i = tid; i < 2048; i += 256) {
        float v = cp_items[ci * 2048 + i];
        s_cp[i] = v; ls += v;
    }
    s_red[tid] = ls; __syncthreads();
    for (int o = 128; o > 0; o >>= 1) {
        if (tid < o) s_red[tid] += s_red[tid + o];
        __syncthreads();
    }
    float inv = 1.0f / (s_red[0] + 1e-8f);

    float vloc[8]; int cnt[8];
#pragma unroll
    for (int u = 0; u < 8; u++) { vloc[u] = s_cp[tid + 256 * u]; cnt[u] = 0; }
    for (int j = 0; j < 2048; j++) {
        float vj = s_cp[j];
#pragma unroll
        for (int u = 0; u < 8; u++) cnt[u] += (vj > vloc[u]) ? 1 : 0;
    }
#pragma unroll
    for (int u = 0; u < 8; u++)
        s_wc[tid + 256 * u] = (cnt[u] < 32) ? vloc[u] * inv : 0.f;
    __syncthreads();

    for (int blk = 0; blk < 3; blk++) {
        s_w1[tid] = w1[(vi * 3 + blk) * 256 + tid];
        s_w2[tid] = w2[(vi * 3 + blk) * 256 + tid];
        if (tid < 16) {
            float dp = decays[(vi * 3 + blk) * 16 + tid];
            s_d[tid] = 0.5f + (1.f / (1.f + expf(-dp))) * 0.5f;
            float gp = gains[(vi * 3 + blk) * 16 + tid];
            s_g[tid] = (1.f / (1.f + expf(-gp))) * 5.f;
        }
        __syncthreads();
#pragma unroll
        for (int u = 0; u < 8; u++) {
            int idx = tid + 256 * u;
            int c = idx >> 7, f = idx & 127;
            float acc = 0.f;
#pragma unroll
            for (int k = 0; k < 16; k++)
                acc += s_w1[c * 16 + k] * fmaxf(s_wc[k * 128 + f], 0.f);
            s_x[idx] = acc;
        }
        __syncthreads();
        if (tid < 16) {
            float d = s_d[tid];
            float y = 0.f;
            for (int f = 0; f < 128; f++) {
                y = d * (s_x[tid * 128 + f] + y);
                s_y[tid * 128 + f] = y;
            }
        }
        __syncthreads();
#pragma unroll
        for (int u = 0; u < 8; u++) {
            int idx = tid + 256 * u;
            int c = idx >> 7, f = idx & 127;
            float acc = s_x[idx];
#pragma unroll
            for (int k = 0; k < 16; k++)
                acc += s_w2[c * 16 + k] * s_y[k * 128 + f];
            float co = tanhf(acc * s_g[c]);
            g_cpw[((e * 3 + blk) * 16 + c) * 128 + f] = s_smix[blk] * co;
            s_wc[idx] = co;
        }
        __syncthreads();
    }
}

// ---------------------------------------------------------------------------
// Audio synthesis + mix + per-event max(|mixed|). 8 frames per CTA:
// each audio_map element is loaded once and reused across 8 frames.
// ---------------------------------------------------------------------------
__global__ void k_audio(const float* __restrict__ audio_maps) {
    int fg = blockIdx.x, e = blockIdx.y, tid = threadIdx.x;
    __shared__ float s_c[8][48];
    __shared__ float s_red[256];
    __shared__ int s_v;
    if (tid == 0) s_v = g_sc[e].vidx;
    for (int s = tid; s < 384; s += 256) {
        int fr = s / 48, ic = s % 48;
        int i = ic >> 4, c = ic & 15;
        s_c[fr][ic] = g_cpw[((e * 3 + i) * 16 + c) * 128 + (fg * 8 + fr)];
    }
    __syncthreads();
    const float* am = audio_maps + (size_t)s_v * 3 * 1024 * 16;
    float lmax = 0.f;
    for (int q = 0; q < 4; q++) {
        int w = tid + q * 256;
        float acc[8];
#pragma unroll
        for (int fr = 0; fr < 8; fr++) acc[fr] = 0.f;
#pragma unroll
        for (int i = 0; i < 3; i++) {
            const float4* row = reinterpret_cast<const float4*>(am + (i * 1024 + w) * 16);
#pragma unroll
            for (int r = 0; r < 4; r++) {
                float4 a4 = __ldg(row + r);
#pragma unroll
                for (int fr = 0; fr < 8; fr++) {
                    acc[fr] += a4.x * s_c[fr][i * 16 + 4 * r + 0]
                             + a4.y * s_c[fr][i * 16 + 4 * r + 1]
                             + a4.z * s_c[fr][i * 16 + 4 * r + 2]
                             + a4.w * s_c[fr][i * 16 + 4 * r + 3];
                }
            }
        }
#pragma unroll
        for (int fr = 0; fr < 8; fr++) {
            g_mixed[e * NS + (fg * 8 + fr) * 1024 + w] = acc[fr];
            lmax = fmaxf(lmax, fabsf(acc[fr]));
        }
    }
    s_red[tid] = lmax; __syncthreads();
    for (int o = 128; o > 0; o >>= 1) {
        if (tid < o) s_red[tid] = fmaxf(s_red[tid], s_red[tid + o]);
        __syncthreads();
    }
    if (tid == 0) atomicMax(&g_normbits[e], __float_as_uint(s_red[0]));
}

// ---------------------------------------------------------------------------
// h = amp*(vm0*(verb (x) impulse) + vm1*impulse), 128 taps (R4 version).
// ---------------------------------------------------------------------------
__global__ void k_h(const float* __restrict__ verbs, const float* __restrict__ times) {
    int e = blockIdx.y, tid = threadIdx.x;
    int t0 = blockIdx.x * 1024;
    __shared__ float s_t[128];
    __shared__ float s_red[256];
    __shared__ EvScalars sc;
    if (tid == 0) sc = g_sc[e];
    if (tid < 128) s_t[tid] = times[e * 128 + tid];
    __syncthreads();
    const float* vb = verbs + sc.ridx * NS;
    float lmax = 0.f;
#pragma unroll
    for (int q = 0; q < 4; q++) {
        int t = t0 + tid + q * 256;
        int fm = t >> 10;
        float acc = 0.f;
        for (int f = 0; f <= fm; f++) acc += s_t[f] * vb[t - 1024 * f];
        float val = sc.av0 * acc;
        if ((t & 1023) == 0) val += sc.av1 * s_t[t >> 10];
        g_h[e * NS + t] = val;
        lmax = fmaxf(lmax, fabsf(val));
    }
    s_red[tid] = lmax; __syncthreads();
    for (int o = 128; o > 0; o >>= 1) {
        if (tid < o) s_red[tid] = fmaxf(s_red[tid], s_red[tid + o]);
        __syncthreads();
    }
    if (tid == 0) atomicMax(&g_hmaxbits[e], __float_as_uint(s_red[0]));
}

// ---------------------------------------------------------------------------
// 4-step FFT passes (262144 = 512 x 512). zB holds spectra in NATURAL
// frequency order (verified: MODE1 stores zB[k1 + 512*k2], true k = k1+512*k2).
// MODE 0: fwd pass1. slot<32: pack (m_{2s}, m_{2s+1}) normalized;
//                    slot>=32: pack (h_{2q}, h_{2q+1}) scaled by 1/hmax.
// MODE 1: fwd pass2 -> zB[slot] raw spectrum.
// MODE 2: inv pass1 on product spectra (zB slots 0..31) -> zA.
// MODE 3: inv pass2 + epilogue: Re -> event 2s (x hmax/MF), Im -> event 2s+1.
// ---------------------------------------------------------------------------
template <int MODE>
__global__ void __launch_bounds__(512) k_fft2(float* __restrict__ out) {
    __shared__ float sRe[8 * 584];
    __shared__ float sIm[8 * 584];
    __shared__ float2 sW[512];
    int slot = blockIdx.y, tile = blockIdx.x, tid = threadIdx.x;
    int c0 = tile * 8;
    const bool INV = (MODE >= 2);

    if (tid < 512) sW[tid] = g_tw[tid * 512];

    if (MODE == 0) {
        const float *s1, *s2;
        float f1, f2;
        if (slot < 32) {
            int e1 = 2 * slot, e2 = 2 * slot + 1;
            s1 = g_mixed + (size_t)e1 * NS;
            s2 = g_mixed + (size_t)e2 * NS;
            f1 = 1.0f / (__uint_as_float(g_normbits[e1]) + 1e-8f);
            f2 = 1.0f / (__uint_as_float(g_normbits[e2]) + 1e-8f);
        } else {
            int e1 = 2 * (slot - 32), e2 = e1 + 1;
            s1 = g_h + (size_t)e1 * NS;
            s2 = g_h + (size_t)e2 * NS;
            f1 = 1.0f / (__uint_as_float(g_hmaxbits[e1]) + 1e-20f);
            f2 = 1.0f / (__uint_as_float(g_hmaxbits[e2]) + 1e-20f);
        }
#pragma unroll
        for (int it = 0; it < 8; it++) {
            int lin = tid + 512 * it;
            int f = lin & 7, r = lin >> 3;
            int n = c0 + f + 512 * r;
            float re = 0.f, im = 0.f;
            if (n < NS) { re = s1[n] * f1; im = s2[n] * f2; }
            sRe[f * 584 + r] = re; sIm[f * 584 + r] = im;
        }
    } else if (MODE == 2) {
#pragma unroll
        for (int it = 0; it < 8; it++) {
            int lin = tid + 512 * it;
            int f = lin & 7, r = lin >> 3;
            float2 z = g_zB[(size_t)slot * MF + (c0 + f) + 512 * r];
            sRe[f * 584 + r] = z.x; sIm[f * 584 + r] = z.y;
        }
    } else {   // MODE 1, 3: rows of zA, contiguous
#pragma unroll
        for (int it = 0; it < 8; it++) {
            int lin = tid + 512 * it;
            int f = lin >> 9, n1 = lin & 511;
            float2 z = g_zA[(size_t)slot * MF + (c0 + f) * 512 + n1];
            sRe[f * 584 + n1] = z.x; sIm[f * 584 + n1] = z.y;
        }
    }
    __syncthreads();

    fft512<INV>(sRe, sIm, sW, tid);

    if (MODE == 0 || MODE == 2) {
#pragma unroll
        for (int it = 0; it < 8; it++) {
            int lin = tid + 512 * it;
            int f = lin & 7, k = lin >> 3;
            float2 v = make_float2(sRe[f * 584 + k], sIm[f * 584 + k]);
            float2 w = g_tw[(c0 + f) * k];
            if (INV) w.y = -w.y;
            g_zA[(size_t)slot * MF + k * 512 + (c0 + f)] = cmul(v, w);
        }
    } else if (MODE == 1) {
#pragma unroll
        for (int it = 0; it < 8; it++) {
            int lin = tid + 512 * it;
            int f = lin & 7, k = lin >> 3;
            g_zB[(size_t)slot * MF + (c0 + f) + 512 * k] =
                make_float2(sRe[f * 584 + k], sIm[f * 584 + k]);
        }
    } else {
        int e1 = 2 * slot, e2 = 2 * slot + 1;
        const float invm = 1.0f / (float)MF;
        float sc1 = (__uint_as_float(g_hmaxbits[e1]) + 1e-20f) * invm;
        float sc2 = (__uint_as_float(g_hmaxbits[e2]) + 1e-20f) * invm;
        float* o1 = out + (size_t)e1 * NS;
        float* o2 = out + (size_t)e2 * NS;
#pragma unroll
        for (int it = 0; it < 4; it++) {   // only k < 256 -> t < NS
            int lin = tid + 512 * it;
            int f = lin & 7, k = lin >> 3;
            int t = (c0 + f) + 512 * k;
            o1[t] = sRe[f * 584 + k] * sc1;
            o2[t] = sIm[f * 584 + k] * sc2;
        }
    }
}

// ---------------------------------------------------------------------------
// Combine: unpack (M1,M2) and (H1,H2) via conjugate symmetry at the natural
// mirror jp = (MF-k) & (MF-1); P_e = M_e * H_e; repack (P1 + i*P2) in place
// into zB slot p. Each {j, jp} pair is owned by exactly one thread (k <= MF/2)
// -> no cross-thread hazard. Self-pairs (k=0, MF/2) are exactly real.
// ---------------------------------------------------------------------------
__global__ void __launch_bounds__(512) k_combine() {
    int p = blockIdx.y;
    int k = blockIdx.x * 512 + threadIdx.x;    // [0, MF/2)
    float2* Zm = g_zB + (size_t)p * MF;
    const float2* Zh = g_zB + (size_t)(32 + p) * MF;
    int reps = (k == 0) ? 2 : 1;               // thread 0 also handles Nyquist
    for (int rep = 0; rep < reps; rep++) {
        int kk = (rep == 0) ? k : (MF / 2);
        int j = kk, jp = (MF - kk) & (MF - 1);
        float2 Za = Zm[j], Zb = Zm[jp];
        float2 Ha = Zh[j], Hb = Zh[jp];
        float2 M1 = make_float2(0.5f * (Za.x + Zb.x), 0.5f * (Za.y - Zb.y));
        float2 M2 = make_float2(0.5f * (Za.y + Zb.y), 0.5f * (Zb.x - Za.x));
        float2 H1 = make_float2(0.5f * (Ha.x + Hb.x), 0.5f * (Ha.y - Hb.y));
        float2 H2 = make_float2(0.5f * (Ha.y + Hb.y), 0.5f * (Hb.x - Ha.x));
        float2 P1 = cmul(M1, H1);
        float2 P2 = cmul(M2, H2);
        Zm[j] = make_float2(P1.x - P2.y, P1.y + P2.x);            // P1 + i*P2
        if (jp != j)
            Zm[jp] = make_float2(P1.x + P2.y, P2.x - P1.y);       // conj(P1) + i*conj(P2)
    }
}

// ---------------------------------------------------------------------------
extern "C" void kernel_launch(void* const* d_in, const int* in_sizes, int n_in,
                              void* d_out, int out_size) {
    const float* voice    = (const float*)d_in[0];
    const float* cpc      = (const float*)d_in[1];
    const float* amp      = (const float*)d_in[2];
    const float* rooml    = (const float*)d_in[3];
    const float* rmix     = (const float*)d_in[4];
    const float* times    = (const float*)d_in[5];
    const float* cp_items = (const float*)d_in[6];
    const float* verbs    = (const float*)d_in[7];
    const float* w1       = (const float*)d_in[8];
    const float* w2       = (const float*)d_in[9];
    const float* amaps    = (const float*)d_in[10];
    const float* decays   = (const float*)d_in[11];
    const float* gains    = (const float*)d_in[12];
    const float* mix      = (const float*)d_in[13];
    float* out = (float*)d_out;

    k_tw<<<1024, 256>>>();
    k_prep<<<64, 256>>>(voice, cpc, amp, rooml, rmix, cp_items, w1, w2, decays, gains, mix);
    k_audio<<<dim3(16, 64), 256>>>(amaps);
    k_h<<<dim3(128, 64), 256>>>(verbs, times);
    k_fft2<0><<<dim3(64, 64), 512>>>(out);   // 32 m-pairs + 32 h-pairs
    k_fft2<1><<<dim3(64, 64), 512>>>(out);
    k_combine<<<dim3(256, 32), 512>>>();
    k_fft2<2><<<dim3(64, 32), 512>>>(out);   // 32 product pairs
    k_fft2<3><<<dim3(64, 32), 512>>>(out);
}

// round 8
// speedup vs baseline: 2.3120x; 1.2292x over previous
#include <cuda_runtime.h>
#include <math.h>

#define NS 131072           // N_SAMPLES
#define NEV 64              // B*E
#define MF 262144           // FFT length = 2*NS
#define NFRAMES 128
#define CPD 16

struct EvScalars { int vidx; int ridx; float av0; float av1; };

__device__ EvScalars g_sc[NEV];
__device__ unsigned  g_normbits[NEV];   // max |mixed|
__device__ unsigned  g_hmaxbits[NEV];   // max |h|
__device__ int       g_vcount[8];       // events per verb
__device__ int       g_vlist[8 * 64];   // event ids grouped by verb
__device__ float     g_cpw[NEV * 3 * CPD * NFRAMES];   // smix-weighted cp_out
__device__ float     g_mixed[NEV * NS];
__device__ float     g_h[NEV * NS];
__device__ float2    g_twA[512];        // W_512^a  (= W_MF^(512a))
__device__ float2    g_twB[512];        // W_MF^b
__device__ float2    g_tw2[MF];         // [n1*512+k2] = W_MF^(n1*k2), transposed layout
// zA: inter-pass scratch (64 slots). zB: spectra, natural frequency order:
//   slots 0..31  = packed (m_{2p}, m_{2p+1}) spectra -> product spectra (in place)
//   slots 32..63 = packed (h_{2p}, h_{2p+1}) spectra
__device__ float2    g_zA[NEV * MF];
__device__ float2    g_zB[NEV * MF];

__device__ __forceinline__ float2 cmul(float2 a, float2 b) {
    return make_float2(a.x * b.x - a.y * b.y, a.x * b.y + a.y * b.x);
}
__device__ __forceinline__ float2 cadd(float2 a, float2 b){return make_float2(a.x+b.x,a.y+b.y);}
__device__ __forceinline__ float2 csub(float2 a, float2 b){return make_float2(a.x-b.x,a.y-b.y);}

template<bool INV>
__device__ __forceinline__ float2 mulj(float2 a) {  // * (-i) fwd, * (+i) inv
    return INV ? make_float2(-a.y, a.x) : make_float2(a.y, -a.x);
}

// 8-point DFT, natural-order in/out
template<bool INV>
__device__ __forceinline__ void dft8(float2 v[8]) {
    const float C = 0.70710678118654752f;
    float2 b0=cadd(v[0],v[4]), b4=csub(v[0],v[4]);
    float2 b1=cadd(v[1],v[5]), b5=csub(v[1],v[5]);
    float2 b2=cadd(v[2],v[6]), b6=csub(v[2],v[6]);
    float2 b3=cadd(v[3],v[7]), b7=csub(v[3],v[7]);
    b5 = INV ? make_float2(C*(b5.x-b5.y), C*(b5.x+b5.y))
             : make_float2(C*(b5.x+b5.y), C*(b5.y-b5.x));
    b6 = mulj<INV>(b6);
    b7 = INV ? make_float2(-C*(b7.x+b7.y), C*(b7.x-b7.y))
             : make_float2(C*(b7.y-b7.x), -C*(b7.x+b7.y));
    float2 c0=cadd(b0,b2), c2=csub(b0,b2);
    float2 c1=cadd(b1,b3), c3=mulj<INV>(csub(b1,b3));
    float2 c4=cadd(b4,b6), c6=csub(b4,b6);
    float2 c5=cadd(b5,b7), c7=mulj<INV>(csub(b5,b7));
    v[0]=cadd(c0,c1); v[4]=csub(c0,c1);
    v[2]=cadd(c2,c3); v[6]=csub(c2,c3);
    v[1]=cadd(c4,c5); v[5]=csub(c4,c5);
    v[3]=cadd(c6,c7); v[7]=csub(c6,c7);
}

// ---------------------------------------------------------------------------
// 512-point FFT, radix-8^3, 64 threads per FFT (8 FFTs per 512-thread CTA).
// Twiddles via register power chains (conflict-free; sW read only at stride 1).
// ---------------------------------------------------------------------------
template<bool INV>
__device__ __forceinline__ void fft512(float* sRe, float* sIm, const float2* sW, int tid) {
    int t = tid & 63;
    int base = (tid >> 6) * 584;
    float2 v[8];
#pragma unroll
    for (int j = 0; j < 8; j++) {
        int a = base + t + 64 * j;
        v[j] = make_float2(sRe[a], sIm[a]);
    }
    dft8<INV>(v);
    {
        float2 w1 = sW[t];                 // W_512^t
        if (INV) w1.y = -w1.y;
        float2 wc = w1;
        v[1] = cmul(v[1], wc);
#pragma unroll
        for (int k0 = 2; k0 < 8; k0++) { wc = cmul(wc, w1); v[k0] = cmul(v[k0], wc); }
    }
    __syncthreads();
#pragma unroll
    for (int k0 = 0; k0 < 8; k0++) {
        int a = base + 72 * k0 + t;
        sRe[a] = v[k0].x; sIm[a] = v[k0].y;
    }
    __syncthreads();
    int k0 = t >> 3, r = t & 7;
#pragma unroll
    for (int m1 = 0; m1 < 8; m1++) {
        int a = base + 72 * k0 + r + 8 * m1;
        v[m1] = make_float2(sRe[a], sIm[a]);
    }
    dft8<INV>(v);
    {
        float2 w1 = sW[8 * r];             // W_64^r
        if (INV) w1.y = -w1.y;
        float2 wc = w1;
        v[1] = cmul(v[1], wc);
#pragma unroll
        for (int k1 = 2; k1 < 8; k1++) { wc = cmul(wc, w1); v[k1] = cmul(v[k1], wc); }
    }
    __syncthreads();
#pragma unroll
    for (int k1 = 0; k1 < 8; k1++) {
        int a = base + 72 * k0 + 9 * k1 + r;
        sRe[a] = v[k1].x; sIm[a] = v[k1].y;
    }
    __syncthreads();
#pragma unroll
    for (int m0 = 0; m0 < 8; m0++) {
        int a = base + 72 * k0 + 9 * r + m0;
        v[m0] = make_float2(sRe[a], sIm[a]);
    }
    dft8<INV>(v);
    __syncthreads();
#pragma unroll
    for (int k2 = 0; k2 < 8; k2++) {
        int a = base + k0 + 8 * r + 64 * k2;
        sRe[a] = v[k2].x; sIm[a] = v[k2].y;
    }
    __syncthreads();
}

// ---------------------------------------------------------------------------
// Base twiddle tables (double-precision sincos, 1024 entries total) + zero
// the verb-grouping counters.
// ---------------------------------------------------------------------------
__global__ void k_tw1() {
    int t = threadIdx.x;   // 512
    double s, c;
    double angA = -2.0 * 3.14159265358979323846 * (double)t / 512.0;
    sincos(angA, &s, &c);
    g_twA[t] = make_float2((float)c, (float)s);
    double angB = -2.0 * 3.14159265358979323846 * (double)t / (double)MF;
    sincos(angB, &s, &c);
    g_twB[t] = make_float2((float)c, (float)s);
    if (t < 8) g_vcount[t] = 0;
}

// Transposed inter-pass twiddle: g_tw2[n1*512+k2] = W_MF^(n1*k2).
__global__ void k_tw2() {
    int n1 = blockIdx.x, k2 = threadIdx.x;
    int p = n1 * k2;                       // < 512*512 = MF, no reduction needed
    g_tw2[n1 * 512 + k2] = cmul(g_twA[p >> 9], g_twB[p & 511]);
}

// ---------------------------------------------------------------------------
// Per-event prep: argmaxes, softmaxes, cp select + sparsify, 3-block stack.
// Also builds the verb -> event list.
// ---------------------------------------------------------------------------
__global__ void k_prep(const float* __restrict__ voice, const float* __restrict__ cpc,
                       const float* __restrict__ amp,   const float* __restrict__ rooml,
                       const float* __restrict__ rmix,  const float* __restrict__ cp_items,
                       const float* __restrict__ w1,    const float* __restrict__ w2,
                       const float* __restrict__ decays,const float* __restrict__ gains,
                       const float* __restrict__ mix) {
    int e = blockIdx.x, tid = threadIdx.x;
    __shared__ float s_cp[2048];
    __shared__ float s_wc[2048];
    __shared__ float s_x[2048];
    __shared__ float s_y[2048];
    __shared__ float s_w1[256], s_w2[256];
    __shared__ float s_d[16], s_g[16];
    __shared__ float s_red[256];
    __shared__ float s_smix[3];
    __shared__ int   s_vidx, s_cidx;

    if (tid == 0) {
        const float* v = voice + e * 8;
        int vi = 0; float bv = v[0];
        for (int i = 1; i < 8; i++) if (v[i] > bv) { bv = v[i]; vi = i; }
        s_vidx = vi;
        const float* c = cpc + e * 512;
        int ci = 0; float bc = c[0];
        for (int i = 1; i < 512; i++) if (c[i] > bc) { bc = c[i]; ci = i; }
        s_cidx = ci;
        const float* r = rooml + e * 8;
        int ri = 0; float br = r[0];
        for (int i = 1; i < 8; i++) if (r[i] > br) { br = r[i]; ri = i; }
        float m0 = rmix[e * 2 + 0], m1 = rmix[e * 2 + 1];
        float mx = fmaxf(m0, m1);
        float e0 = expf(m0 - mx), e1 = expf(m1 - mx);
        float vm0 = e0 / (e0 + e1), vm1 = e1 / (e0 + e1);
        float a = fabsf(amp[e]);
        g_sc[e].vidx = vi; g_sc[e].ridx = ri;
        g_sc[e].av0 = a * vm0; g_sc[e].av1 = a * vm1;
        int pos = atomicAdd(&g_vcount[ri], 1);
        g_vlist[ri * 64 + pos] = e;
        float q0 = mix[vi * 3 + 0], q1 = mix[vi * 3 + 1], q2 = mix[vi * 3 + 2];
        float qm = fmaxf(q0, fmaxf(q1, q2));
        float f0 = expf(q0 - qm), f1 = expf(q1 - qm), f2 = expf(q2 - qm);
        float fs = f0 + f1 + f2;
        s_smix[0] = f0 / fs; s_smix[1] = f1 / fs; s_smix[2] = f2 / fs;
        g_normbits[e] = 0u;
        g_hmaxbits[e] = 0u;
    }
    __syncthreads();
    int vi = s_vidx, ci = s_cidx;

    float ls = 0.f;
    for (int i = tid; i < 2048; i += 256) {
        float v = cp_items[ci * 2048 + i];
        s_cp[i] = v; ls += v;
    }
    s_red[tid] = ls; __syncthreads();
    for (int o = 128; o > 0; o >>= 1) {
        if (tid < o) s_red[tid] += s_red[tid + o];
        __syncthreads();
    }
    float inv = 1.0f / (s_red[0] + 1e-8f);

    float vloc[8]; int cnt[8];
#pragma unroll
    for (int u = 0; u < 8; u++) { vloc[u] = s_cp[tid + 256 * u]; cnt[u] = 0; }
    for (int j = 0; j < 2048; j++) {
        float vj = s_cp[j];
#pragma unroll
        for (int u = 0; u < 8; u++) cnt[u] += (vj > vloc[u]) ? 1 : 0;
    }
#pragma unroll
    for (int u = 0; u < 8; u++)
        s_wc[tid + 256 * u] = (cnt[u] < 32) ? vloc[u] * inv : 0.f;
    __syncthreads();

    for (int blk = 0; blk < 3; blk++) {
        s_w1[tid] = w1[(vi * 3 + blk) * 256 + tid];
        s_w2[tid] = w2[(vi * 3 + blk) * 256 + tid];
        if (tid < 16) {
            float dp = decays[(vi * 3 + blk) * 16 + tid];
            s_d[tid] = 0.5f + (1.f / (1.f + expf(-dp))) * 0.5f;
            float gp = gains[(vi * 3 + blk) * 16 + tid];
            s_g[tid] = (1.f / (1.f + expf(-gp))) * 5.f;
        }
        __syncthreads();
#pragma unroll
        for (int u = 0; u < 8; u++) {
            int idx = tid + 256 * u;
            int c = idx >> 7, f = idx & 127;
            float acc = 0.f;
#pragma unroll
            for (int k = 0; k < 16; k++)
                acc += s_w1[c * 16 + k] * fmaxf(s_wc[k * 128 + f], 0.f);
            s_x[idx] = acc;
        }
        __syncthreads();
        if (tid < 16) {
            float d = s_d[tid];
            float y = 0.f;
            for (int f = 0; f < 128; f++) {
                y = d * (s_x[tid * 128 + f] + y);
                s_y[tid * 128 + f] = y;
            }
        }
        __syncthreads();
#pragma unroll
        for (int u = 0; u < 8; u++) {
            int idx = tid + 256 * u;
            int c = idx >> 7, f = idx & 127;
            float acc = s_x[idx];
#pragma unroll
            for (int k = 0; k < 16; k++)
                acc += s_w2[c * 16 + k] * s_y[k * 128 + f];
            float co = tanhf(acc * s_g[c]);
            g_cpw[((e * 3 + blk) * 16 + c) * 128 + f] = s_smix[blk] * co;
            s_wc[idx] = co;
        }
        __syncthreads();
    }
}

// ---------------------------------------------------------------------------
// Audio synthesis + mix + per-event max(|mixed|). 16 frames per CTA.
// ---------------------------------------------------------------------------
__global__ void k_audio(const float* __restrict__ audio_maps) {
    int fg = blockIdx.x, e = blockIdx.y, tid = threadIdx.x;
    __shared__ float s_c[16][48];
    __shared__ float s_red[256];
    __shared__ int s_v;
    if (tid == 0) s_v = g_sc[e].vidx;
    for (int s = tid; s < 768; s += 256) {
        int fr = s / 48, ic = s % 48;
        int i = ic >> 4, c = ic & 15;
        s_c[fr][ic] = g_cpw[((e * 3 + i) * 16 + c) * 128 + (fg * 16 + fr)];
    }
    __syncthreads();
    const float* am = audio_maps + (size_t)s_v * 3 * 1024 * 16;
    float lmax = 0.f;
    for (int q = 0; q < 4; q++) {
        int w = tid + q * 256;
        float acc[16];
#pragma unroll
        for (int fr = 0; fr < 16; fr++) acc[fr] = 0.f;
#pragma unroll
        for (int i = 0; i < 3; i++) {
            const float4* row = reinterpret_cast<const float4*>(am + (i * 1024 + w) * 16);
#pragma unroll
            for (int r = 0; r < 4; r++) {
                float4 a4 = __ldg(row + r);
#pragma unroll
                for (int fr = 0; fr < 16; fr++) {
                    acc[fr] += a4.x * s_c[fr][i * 16 + 4 * r + 0]
                             + a4.y * s_c[fr][i * 16 + 4 * r + 1]
                             + a4.z * s_c[fr][i * 16 + 4 * r + 2]
                             + a4.w * s_c[fr][i * 16 + 4 * r + 3];
                }
            }
        }
#pragma unroll
        for (int fr = 0; fr < 16; fr++) {
            g_mixed[e * NS + (fg * 16 + fr) * 1024 + w] = acc[fr];
            lmax = fmaxf(lmax, fabsf(acc[fr]));
        }
    }
    s_red[tid] = lmax; __syncthreads();
    for (int o = 128; o > 0; o >>= 1) {
        if (tid < o) s_red[tid] = fmaxf(s_red[tid], s_red[tid + o]);
        __syncthreads();
    }
    if (tid == 0) atomicMax(&g_normbits[e], __float_as_uint(s_red[0]));
}

// ---------------------------------------------------------------------------
// h = amp*(vm0*(verb (x) impulse) + vm1*impulse), grouped by verb: each verb's
// samples are loaded once and reused across up to 8 events per batch.
// grid (128 chunks, 8 verbs). Within a chunk, every t has fm = chunk.
// ---------------------------------------------------------------------------
__global__ void k_h2(const float* __restrict__ verbs, const float* __restrict__ times) {
    int r = blockIdx.y;
    int cnt = g_vcount[r];
    if (cnt == 0) return;
    int chunk = blockIdx.x;
    int t0 = chunk << 10;
    int tid = threadIdx.x;
    __shared__ float s_t[8][128];
    __shared__ int   s_ei[8];
    __shared__ float s_av0[8], s_av1[8];
    __shared__ float s_wm[8][8];
    const float* vb = verbs + (size_t)r * NS;

    for (int b = 0; b < cnt; b += 8) {
        int nb = min(8, cnt - b);
        if (tid < 8) {
            if (tid < nb) {
                int e = g_vlist[r * 64 + b + tid];
                s_ei[tid] = e;
                s_av0[tid] = g_sc[e].av0;
                s_av1[tid] = g_sc[e].av1;
            } else s_ei[tid] = -1;
        }
        __syncthreads();
        for (int s = tid; s < 1024; s += 256) {
            int i = s >> 7, f = s & 127;
            s_t[i][f] = (i < nb) ? times[(size_t)g_vlist[r * 64 + b + i] * 128 + f] : 0.f;
        }
        __syncthreads();

        float acc0[8], acc1[8], acc2[8], acc3[8];
#pragma unroll
        for (int i = 0; i < 8; i++) { acc0[i]=0.f; acc1[i]=0.f; acc2[i]=0.f; acc3[i]=0.f; }
        const float* vbase = vb + t0 + tid;
        for (int f = 0; f <= chunk; f++) {
            const float* vp = vbase - (f << 10);
            float v0 = vp[0], v1 = vp[256], v2 = vp[512], v3 = vp[768];
#pragma unroll
            for (int i = 0; i < 8; i++) {
                float tf = s_t[i][f];
                acc0[i] += v0 * tf; acc1[i] += v1 * tf;
                acc2[i] += v2 * tf; acc3[i] += v3 * tf;
            }
        }

        float lm[8];
#pragma unroll
        for (int i = 0; i < 8; i++) lm[i] = 0.f;
        for (int i = 0; i < nb; i++) {
            int e = s_ei[i];
            float a0 = s_av0[i];
            float v0 = a0 * acc0[i];
            if (tid == 0) v0 += s_av1[i] * s_t[i][chunk];   // t % 1024 == 0 sample
            float v1 = a0 * acc1[i], v2 = a0 * acc2[i], v3 = a0 * acc3[i];
            size_t o = (size_t)e * NS + t0 + tid;
            g_h[o] = v0; g_h[o + 256] = v1; g_h[o + 512] = v2; g_h[o + 768] = v3;
            lm[i] = fmaxf(fmaxf(fabsf(v0), fabsf(v1)), fmaxf(fabsf(v2), fabsf(v3)));
        }
#pragma unroll
        for (int i = 0; i < 8; i++) {
#pragma unroll
            for (int off = 16; off; off >>= 1)
                lm[i] = fmaxf(lm[i], __shfl_xor_sync(0xffffffffu, lm[i], off));
        }
        int wid = tid >> 5, lane = tid & 31;
        if (lane == 0) {
#pragma unroll
            for (int i = 0; i < 8; i++) s_wm[wid][i] = lm[i];
        }
        __syncthreads();
        if (tid < 8) {
            float m = s_wm[0][tid];
#pragma unroll
            for (int w = 1; w < 8; w++) m = fmaxf(m, s_wm[w][tid]);
            if (tid < nb) atomicMax(&g_hmaxbits[s_ei[tid]], __float_as_uint(m));
        }
        __syncthreads();
    }
}

// ---------------------------------------------------------------------------
// 4-step FFT passes (262144 = 512 x 512). zB holds spectra in NATURAL
// frequency order (MODE1 stores zB[k1 + 512*k2], true k = k1+512*k2).
// MODE 0: fwd pass1. slot<32: pack (m_{2s}, m_{2s+1}) normalized;
//                    slot>=32: pack (h_{2q}, h_{2q+1}) scaled by 1/hmax.
// MODE 1: fwd pass2 -> zB[slot] raw spectrum.
// MODE 2: inv pass1 on product spectra (zB slots 0..31) -> zA.
// MODE 3: inv pass2 + epilogue: Re -> event 2s (x hmax/MF), Im -> event 2s+1.
// ---------------------------------------------------------------------------
template <int MODE>
__global__ void __launch_bounds__(512) k_fft2(float* __restrict__ out) {
    __shared__ float sRe[8 * 584];
    __shared__ float sIm[8 * 584];
    __shared__ float2 sW[512];
    int slot = blockIdx.y, tile = blockIdx.x, tid = threadIdx.x;
    int c0 = tile * 8;
    const bool INV = (MODE >= 2);

    if (tid < 512) sW[tid] = g_twA[tid];

    if (MODE == 0) {
        const float *s1, *s2;
        float f1, f2;
        if (slot < 32) {
            int e1 = 2 * slot, e2 = 2 * slot + 1;
            s1 = g_mixed + (size_t)e1 * NS;
            s2 = g_mixed + (size_t)e2 * NS;
            f1 = 1.0f / (__uint_as_float(g_normbits[e1]) + 1e-8f);
            f2 = 1.0f / (__uint_as_float(g_normbits[e2]) + 1e-8f);
        } else {
            int e1 = 2 * (slot - 32), e2 = e1 + 1;
            s1 = g_h + (size_t)e1 * NS;
            s2 = g_h + (size_t)e2 * NS;
            f1 = 1.0f / (__uint_as_float(g_hmaxbits[e1]) + 1e-20f);
            f2 = 1.0f / (__uint_as_float(g_hmaxbits[e2]) + 1e-20f);
        }
#pragma unroll
        for (int it = 0; it < 8; it++) {
            int lin = tid + 512 * it;
            int f = lin & 7, r = lin >> 3;
            int n = c0 + f + 512 * r;
            float re = 0.f, im = 0.f;
            if (n < NS) { re = s1[n] * f1; im = s2[n] * f2; }
            sRe[f * 584 + r] = re; sIm[f * 584 + r] = im;
        }
    } else if (MODE == 2) {
#pragma unroll
        for (int it = 0; it < 8; it++) {
            int lin = tid + 512 * it;
            int f = lin & 7, r = lin >> 3;
            float2 z = g_zB[(size_t)slot * MF + (c0 + f) + 512 * r];
            sRe[f * 584 + r] = z.x; sIm[f * 584 + r] = z.y;
        }
    } else {   // MODE 1, 3: rows of zA, contiguous
#pragma unroll
        for (int it = 0; it < 8; it++) {
            int lin = tid + 512 * it;
            int f = lin >> 9, n1 = lin & 511;
            float2 z = g_zA[(size_t)slot * MF + (c0 + f) * 512 + n1];
            sRe[f * 584 + n1] = z.x; sIm[f * 584 + n1] = z.y;
        }
    }
    __syncthreads();

    fft512<INV>(sRe, sIm, sW, tid);

    if (MODE == 0 || MODE == 2) {
#pragma unroll
        for (int it = 0; it < 8; it++) {
            int lin = tid + 512 * it;
            int f = lin & 7, k = lin >> 3;
            float2 v = make_float2(sRe[f * 584 + k], sIm[f * 584 + k]);
            float2 w = g_tw2[(c0 + f) * 512 + k];   // W_MF^((c0+f)*k), coalesced
            if (INV) w.y = -w.y;
            g_zA[(size_t)slot * MF + k * 512 + (c0 + f)] = cmul(v, w);
        }
    } else if (MODE == 1) {
#pragma unroll
        for (int it = 0; it < 8; it++) {
            int lin = tid + 512 * it;
            int f = lin & 7, k = lin >> 3;
            g_zB[(size_t)slot * MF + (c0 + f) + 512 * k] =
                make_float2(sRe[f * 584 + k], sIm[f * 584 + k]);
        }
    } else {
        int e1 = 2 * slot, e2 = 2 * slot + 1;
        const float invm = 1.0f / (float)MF;
        float sc1 = (__uint_as_float(g_hmaxbits[e1]) + 1e-20f) * invm;
        float sc2 = (__uint_as_float(g_hmaxbits[e2]) + 1e-20f) * invm;
        float* o1 = out + (size_t)e1 * NS;
        float* o2 = out + (size_t)e2 * NS;
#pragma unroll
        for (int it = 0; it < 4; it++) {   // only k < 256 -> t < NS
            int lin = tid + 512 * it;
            int f = lin & 7, k = lin >> 3;
            int t = (c0 + f) + 512 * k;
            o1[t] = sRe[f * 584 + k] * sc1;
            o2[t] = sIm[f * 584 + k] * sc2;
        }
    }
}

// ---------------------------------------------------------------------------
// Combine: unpack (M1,M2) and (H1,H2) via conjugate symmetry at the natural
// mirror jp = (MF-k) & (MF-1); P_e = M_e * H_e; repack (P1 + i*P2) in place.
// ---------------------------------------------------------------------------
__global__ void __launch_bounds__(512) k_combine() {
    int p = blockIdx.y;
    int k = blockIdx.x * 512 + threadIdx.x;    // [0, MF/2)
    float2* Zm = g_zB + (size_t)p * MF;
    const float2* Zh = g_zB + (size_t)(32 + p) * MF;
    int reps = (k == 0) ? 2 : 1;               // thread 0 also handles Nyquist
    for (int rep = 0; rep < reps; rep++) {
        int kk = (rep == 0) ? k : (MF / 2);
        int j = kk, jp = (MF - kk) & (MF - 1);
        float2 Za = Zm[j], Zb = Zm[jp];
        float2 Ha = Zh[j], Hb = Zh[jp];
        float2 M1 = make_float2(0.5f * (Za.x + Zb.x), 0.5f * (Za.y - Zb.y));
        float2 M2 = make_float2(0.5f * (Za.y + Zb.y), 0.5f * (Zb.x - Za.x));
        float2 H1 = make_float2(0.5f * (Ha.x + Hb.x), 0.5f * (Ha.y - Hb.y));
        float2 H2 = make_float2(0.5f * (Ha.y + Hb.y), 0.5f * (Hb.x - Ha.x));
        float2 P1 = cmul(M1, H1);
        float2 P2 = cmul(M2, H2);
        Zm[j] = make_float2(P1.x - P2.y, P1.y + P2.x);            // P1 + i*P2
        if (jp != j)
            Zm[jp] = make_float2(P1.x + P2.y, P2.x - P1.y);       // conj(P1) + i*conj(P2)
    }
}

// ---------------------------------------------------------------------------
extern "C" void kernel_launch(void* const* d_in, const int* in_sizes, int n_in,
                              void* d_out, int out_size) {
    const float* voice    = (const float*)d_in[0];
    const float* cpc      = (const float*)d_in[1];
    const float* amp      = (const float*)d_in[2];
    const float* rooml    = (const float*)d_in[3];
    const float* rmix     = (const float*)d_in[4];
    const float* times    = (const float*)d_in[5];
    const float* cp_items = (const float*)d_in[6];
    const float* verbs    = (const float*)d_in[7];
    const float* w1       = (const float*)d_in[8];
    const float* w2       = (const float*)d_in[9];
    const float* amaps    = (const float*)d_in[10];
    const float* decays   = (const float*)d_in[11];
    const float* gains    = (const float*)d_in[12];
    const float* mix      = (const float*)d_in[13];
    float* out = (float*)d_out;

    k_tw1<<<1, 512>>>();
    k_tw2<<<512, 512>>>();
    k_prep<<<64, 256>>>(voice, cpc, amp, rooml, rmix, cp_items, w1, w2, decays, gains, mix);
    k_audio<<<dim3(8, 64), 256>>>(amaps);
    k_h2<<<dim3(128, 8), 256>>>(verbs, times);
    k_fft2<0><<<dim3(64, 64), 512>>>(out);   // 32 m-pairs + 32 h-pairs
    k_fft2<1><<<dim3(64, 64), 512>>>(out);
    k_combine<<<dim3(256, 32), 512>>>();
    k_fft2<2><<<dim3(64, 32), 512>>>(out);   // 32 product pairs
    k_fft2<3><<<dim3(64, 32), 512>>>(out);
}

// round 9
// speedup vs baseline: 2.6477x; 1.1452x over previous
#include <cuda_runtime.h>
#include <math.h>

#define NS 131072           // N_SAMPLES
#define NEV 64              // B*E
#define MF 262144           // FFT length = 2*NS
#define NFRAMES 128
#define CPD 16

struct EvScalars { int vidx; int ridx; float av0; float av1; };

__device__ EvScalars g_sc[NEV];
__device__ unsigned  g_normbits[NEV];   // max |mixed|
__device__ unsigned  g_hmaxbits[NEV];   // max |h|
__device__ int       g_vcount[8];       // events per verb
__device__ int       g_vlist[8 * 64];   // event ids grouped by verb
__device__ float     g_cpw[NEV * 3 * CPD * NFRAMES];   // smix-weighted cp_out
__device__ float     g_mixed[NEV * NS];
__device__ float     g_h[NEV * NS];
__device__ float2    g_twA[512];        // W_512^a
__device__ float2    g_twB[512];        // W_MF^b
__device__ float2    g_tw2[MF];         // [n1*512+k2] = W_MF^(n1*k2)
// zA: inter-pass scratch (64 fwd slots / 32 inv slots).
// zB: PRODUCT spectra only, slots 0..31, ROW-MAJOR: [k1*512 + k2], k = k1+512*k2.
__device__ float2    g_zA[NEV * MF];
__device__ float2    g_zB[NEV * MF];

__device__ __forceinline__ float2 cmul(float2 a, float2 b) {
    return make_float2(a.x * b.x - a.y * b.y, a.x * b.y + a.y * b.x);
}
__device__ __forceinline__ float2 cadd(float2 a, float2 b){return make_float2(a.x+b.x,a.y+b.y);}
__device__ __forceinline__ float2 csub(float2 a, float2 b){return make_float2(a.x-b.x,a.y-b.y);}

template<bool INV>
__device__ __forceinline__ float2 mulj(float2 a) {  // * (-i) fwd, * (+i) inv
    return INV ? make_float2(-a.y, a.x) : make_float2(a.y, -a.x);
}

// 8-point DFT, natural-order in/out
template<bool INV>
__device__ __forceinline__ void dft8(float2 v[8]) {
    const float C = 0.70710678118654752f;
    float2 b0=cadd(v[0],v[4]), b4=csub(v[0],v[4]);
    float2 b1=cadd(v[1],v[5]), b5=csub(v[1],v[5]);
    float2 b2=cadd(v[2],v[6]), b6=csub(v[2],v[6]);
    float2 b3=cadd(v[3],v[7]), b7=csub(v[3],v[7]);
    b5 = INV ? make_float2(C*(b5.x-b5.y), C*(b5.x+b5.y))
             : make_float2(C*(b5.x+b5.y), C*(b5.y-b5.x));
    b6 = mulj<INV>(b6);
    b7 = INV ? make_float2(-C*(b7.x+b7.y), C*(b7.x-b7.y))
             : make_float2(C*(b7.y-b7.x), -C*(b7.x+b7.y));
    float2 c0=cadd(b0,b2), c2=csub(b0,b2);
    float2 c1=cadd(b1,b3), c3=mulj<INV>(csub(b1,b3));
    float2 c4=cadd(b4,b6), c6=csub(b4,b6);
    float2 c5=cadd(b5,b7), c7=mulj<INV>(csub(b5,b7));
    v[0]=cadd(c0,c1); v[4]=csub(c0,c1);
    v[2]=cadd(c2,c3); v[6]=csub(c2,c3);
    v[1]=cadd(c4,c5); v[5]=csub(c4,c5);
    v[3]=cadd(c6,c7); v[7]=csub(c6,c7);
}

// ---------------------------------------------------------------------------
// 512-point FFT, radix-8^3, 64 threads per FFT (8 FFTs per 512-thread CTA).
// ---------------------------------------------------------------------------
template<bool INV>
__device__ __forceinline__ void fft512(float* sRe, float* sIm, const float2* sW, int tid) {
    int t = tid & 63;
    int base = (tid >> 6) * 584;
    float2 v[8];
#pragma unroll
    for (int j = 0; j < 8; j++) {
        int a = base + t + 64 * j;
        v[j] = make_float2(sRe[a], sIm[a]);
    }
    dft8<INV>(v);
    {
        float2 w1 = sW[t];                 // W_512^t
        if (INV) w1.y = -w1.y;
        float2 wc = w1;
        v[1] = cmul(v[1], wc);
#pragma unroll
        for (int k0 = 2; k0 < 8; k0++) { wc = cmul(wc, w1); v[k0] = cmul(v[k0], wc); }
    }
    __syncthreads();
#pragma unroll
    for (int k0 = 0; k0 < 8; k0++) {
        int a = base + 72 * k0 + t;
        sRe[a] = v[k0].x; sIm[a] = v[k0].y;
    }
    __syncthreads();
    int k0 = t >> 3, r = t & 7;
#pragma unroll
    for (int m1 = 0; m1 < 8; m1++) {
        int a = base + 72 * k0 + r + 8 * m1;
        v[m1] = make_float2(sRe[a], sIm[a]);
    }
    dft8<INV>(v);
    {
        float2 w1 = sW[8 * r];             // W_64^r
        if (INV) w1.y = -w1.y;
        float2 wc = w1;
        v[1] = cmul(v[1], wc);
#pragma unroll
        for (int k1 = 2; k1 < 8; k1++) { wc = cmul(wc, w1); v[k1] = cmul(v[k1], wc); }
    }
    __syncthreads();
#pragma unroll
    for (int k1 = 0; k1 < 8; k1++) {
        int a = base + 72 * k0 + 9 * k1 + r;
        sRe[a] = v[k1].x; sIm[a] = v[k1].y;
    }
    __syncthreads();
#pragma unroll
    for (int m0 = 0; m0 < 8; m0++) {
        int a = base + 72 * k0 + 9 * r + m0;
        v[m0] = make_float2(sRe[a], sIm[a]);
    }
    dft8<INV>(v);
    __syncthreads();
#pragma unroll
    for (int k2 = 0; k2 < 8; k2++) {
        int a = base + k0 + 8 * r + 64 * k2;
        sRe[a] = v[k2].x; sIm[a] = v[k2].y;
    }
    __syncthreads();
}

// ---------------------------------------------------------------------------
__global__ void k_tw1() {
    int t = threadIdx.x;   // 512
    double s, c;
    double angA = -2.0 * 3.14159265358979323846 * (double)t / 512.0;
    sincos(angA, &s, &c);
    g_twA[t] = make_float2((float)c, (float)s);
    double angB = -2.0 * 3.14159265358979323846 * (double)t / (double)MF;
    sincos(angB, &s, &c);
    g_twB[t] = make_float2((float)c, (float)s);
    if (t < 8) g_vcount[t] = 0;
}

__global__ void k_tw2() {
    int n1 = blockIdx.x, k2 = threadIdx.x;
    int p = n1 * k2;
    g_tw2[n1 * 512 + k2] = cmul(g_twA[p >> 9], g_twB[p & 511]);
}

// ---------------------------------------------------------------------------
// Per-event prep: argmaxes, softmaxes, cp select + sparsify, 3-block stack.
// ---------------------------------------------------------------------------
__global__ void k_prep(const float* __restrict__ voice, const float* __restrict__ cpc,
                       const float* __restrict__ amp,   const float* __restrict__ rooml,
                       const float* __restrict__ rmix,  const float* __restrict__ cp_items,
                       const float* __restrict__ w1,    const float* __restrict__ w2,
                       const float* __restrict__ decays,const float* __restrict__ gains,
                       const float* __restrict__ mix) {
    int e = blockIdx.x, tid = threadIdx.x;
    __shared__ float s_cp[2048];
    __shared__ float s_wc[2048];
    __shared__ float s_x[2048];
    __shared__ float s_y[2048];
    __shared__ float s_w1[256], s_w2[256];
    __shared__ float s_d[16], s_g[16];
    __shared__ float s_red[256];
    __shared__ float s_smix[3];
    __shared__ int   s_vidx, s_cidx;

    if (tid == 0) {
        const float* v = voice + e * 8;
        int vi = 0; float bv = v[0];
        for (int i = 1; i < 8; i++) if (v[i] > bv) { bv = v[i]; vi = i; }
        s_vidx = vi;
        const float* c = cpc + e * 512;
        int ci = 0; float bc = c[0];
        for (int i = 1; i < 512; i++) if (c[i] > bc) { bc = c[i]; ci = i; }
        s_cidx = ci;
        const float* r = rooml + e * 8;
        int ri = 0; float br = r[0];
        for (int i = 1; i < 8; i++) if (r[i] > br) { br = r[i]; ri = i; }
        float m0 = rmix[e * 2 + 0], m1 = rmix[e * 2 + 1];
        float mx = fmaxf(m0, m1);
        float e0 = expf(m0 - mx), e1 = expf(m1 - mx);
        float vm0 = e0 / (e0 + e1), vm1 = e1 / (e0 + e1);
        float a = fabsf(amp[e]);
        g_sc[e].vidx = vi; g_sc[e].ridx = ri;
        g_sc[e].av0 = a * vm0; g_sc[e].av1 = a * vm1;
        int pos = atomicAdd(&g_vcount[ri], 1);
        g_vlist[ri * 64 + pos] = e;
        float q0 = mix[vi * 3 + 0], q1 = mix[vi * 3 + 1], q2 = mix[vi * 3 + 2];
        float qm = fmaxf(q0, fmaxf(q1, q2));
        float f0 = expf(q0 - qm), f1 = expf(q1 - qm), f2 = expf(q2 - qm);
        float fs = f0 + f1 + f2;
        s_smix[0] = f0 / fs; s_smix[1] = f1 / fs; s_smix[2] = f2 / fs;
        g_normbits[e] = 0u;
        g_hmaxbits[e] = 0u;
    }
    __syncthreads();
    int vi = s_vidx, ci = s_cidx;

    float ls = 0.f;
    for (int i = tid; i < 2048; i += 256) {
        float v = cp_items[ci * 2048 + i];
        s_cp[i] = v; ls += v;
    }
    s_red[tid] = ls; __syncthreads();
    for (int o = 128; o > 0; o >>= 1) {
        if (tid < o) s_red[tid] += s_red[tid + o];
        __syncthreads();
    }
    float inv = 1.0f / (s_red[0] + 1e-8f);

    float vloc[8]; int cnt[8];
#pragma unroll
    for (int u = 0; u < 8; u++) { vloc[u] = s_cp[tid + 256 * u]; cnt[u] = 0; }
    for (int j = 0; j < 2048; j++) {
        float vj = s_cp[j];
#pragma unroll
        for (int u = 0; u < 8; u++) cnt[u] += (vj > vloc[u]) ? 1 : 0;
    }
#pragma unroll
    for (int u = 0; u < 8; u++)
        s_wc[tid + 256 * u] = (cnt[u] < 32) ? vloc[u] * inv : 0.f;
    __syncthreads();

    for (int blk = 0; blk < 3; blk++) {
        s_w1[tid] = w1[(vi * 3 + blk) * 256 + tid];
        s_w2[tid] = w2[(vi * 3 + blk) * 256 + tid];
        if (tid < 16) {
            float dp = decays[(vi * 3 + blk) * 16 + tid];
            s_d[tid] = 0.5f + (1.f / (1.f + expf(-dp))) * 0.5f;
            float gp = gains[(vi * 3 + blk) * 16 + tid];
            s_g[tid] = (1.f / (1.f + expf(-gp))) * 5.f;
        }
        __syncthreads();
#pragma unroll
        for (int u = 0; u < 8; u++) {
            int idx = tid + 256 * u;
            int c = idx >> 7, f = idx & 127;
            float acc = 0.f;
#pragma unroll
            for (int k = 0; k < 16; k++)
                acc += s_w1[c * 16 + k] * fmaxf(s_wc[k * 128 + f], 0.f);
            s_x[idx] = acc;
        }
        __syncthreads();
        if (tid < 16) {
            float d = s_d[tid];
            float y = 0.f;
            for (int f = 0; f < 128; f++) {
                y = d * (s_x[tid * 128 + f] + y);
                s_y[tid * 128 + f] = y;
            }
        }
        __syncthreads();
#pragma unroll
        for (int u = 0; u < 8; u++) {
            int idx = tid + 256 * u;
            int c = idx >> 7, f = idx & 127;
            float acc = s_x[idx];
#pragma unroll
            for (int k = 0; k < 16; k++)
                acc += s_w2[c * 16 + k] * s_y[k * 128 + f];
            float co = tanhf(acc * s_g[c]);
            g_cpw[((e * 3 + blk) * 16 + c) * 128 + f] = s_smix[blk] * co;
            s_wc[idx] = co;
        }
        __syncthreads();
    }
}

// ---------------------------------------------------------------------------
// Audio synthesis + mix + per-event max(|mixed|). 8 frames x 4 samples per
// thread: each s_c smem load is reused across the 4 q-samples (LDS:FMA = 1:4).
// ---------------------------------------------------------------------------
__global__ void k_audio(const float* __restrict__ audio_maps) {
    int fg = blockIdx.x, e = blockIdx.y, tid = threadIdx.x;
    __shared__ float s_c[8][48];
    __shared__ float s_red[256];
    __shared__ int s_v;
    if (tid == 0) s_v = g_sc[e].vidx;
    for (int s = tid; s < 384; s += 256) {
        int fr = s / 48, ic = s % 48;
        int i = ic >> 4, c = ic & 15;
        s_c[fr][ic] = g_cpw[((e * 3 + i) * 16 + c) * 128 + (fg * 8 + fr)];
    }
    __syncthreads();
    const float* am = audio_maps + (size_t)s_v * 3 * 1024 * 16;
    float acc[8][4];
#pragma unroll
    for (int fr = 0; fr < 8; fr++)
#pragma unroll
        for (int q = 0; q < 4; q++) acc[fr][q] = 0.f;

#pragma unroll
    for (int i = 0; i < 3; i++) {
#pragma unroll
        for (int r = 0; r < 4; r++) {
            float4 a[4];
#pragma unroll
            for (int q = 0; q < 4; q++)
                a[q] = __ldg(reinterpret_cast<const float4*>(
                           am + (i * 1024 + tid + 256 * q) * 16) + r);
#pragma unroll
            for (int fr = 0; fr < 8; fr++) {
                float c0 = s_c[fr][i * 16 + 4 * r + 0];
                float c1 = s_c[fr][i * 16 + 4 * r + 1];
                float c2 = s_c[fr][i * 16 + 4 * r + 2];
                float c3 = s_c[fr][i * 16 + 4 * r + 3];
#pragma unroll
                for (int q = 0; q < 4; q++)
                    acc[fr][q] += a[q].x * c0 + a[q].y * c1 + a[q].z * c2 + a[q].w * c3;
            }
        }
    }
    float lmax = 0.f;
#pragma unroll
    for (int fr = 0; fr < 8; fr++) {
#pragma unroll
        for (int q = 0; q < 4; q++) {
            float v = acc[fr][q];
            g_mixed[e * NS + (fg * 8 + fr) * 1024 + tid + 256 * q] = v;
            lmax = fmaxf(lmax, fabsf(v));
        }
    }
    s_red[tid] = lmax; __syncthreads();
    for (int o = 128; o > 0; o >>= 1) {
        if (tid < o) s_red[tid] = fmaxf(s_red[tid], s_red[tid + o]);
        __syncthreads();
    }
    if (tid == 0) atomicMax(&g_normbits[e], __float_as_uint(s_red[0]));
}

// ---------------------------------------------------------------------------
// h = amp*(vm0*(verb (x) impulse) + vm1*impulse), grouped by verb.
// ---------------------------------------------------------------------------
__global__ void k_h2(const float* __restrict__ verbs, const float* __restrict__ times) {
    int r = blockIdx.y;
    int cnt = g_vcount[r];
    if (cnt == 0) return;
    int chunk = blockIdx.x;
    int t0 = chunk << 10;
    int tid = threadIdx.x;
    __shared__ float s_t[8][128];
    __shared__ int   s_ei[8];
    __shared__ float s_av0[8], s_av1[8];
    __shared__ float s_wm[8][8];
    const float* vb = verbs + (size_t)r * NS;

    for (int b = 0; b < cnt; b += 8) {
        int nb = min(8, cnt - b);
        if (tid < 8) {
            if (tid < nb) {
                int e = g_vlist[r * 64 + b + tid];
                s_ei[tid] = e;
                s_av0[tid] = g_sc[e].av0;
                s_av1[tid] = g_sc[e].av1;
            } else s_ei[tid] = -1;
        }
        __syncthreads();
        for (int s = tid; s < 1024; s += 256) {
            int i = s >> 7, f = s & 127;
            s_t[i][f] = (i < nb) ? times[(size_t)g_vlist[r * 64 + b + i] * 128 + f] : 0.f;
        }
        __syncthreads();

        float acc0[8], acc1[8], acc2[8], acc3[8];
#pragma unroll
        for (int i = 0; i < 8; i++) { acc0[i]=0.f; acc1[i]=0.f; acc2[i]=0.f; acc3[i]=0.f; }
        const float* vbase = vb + t0 + tid;
        for (int f = 0; f <= chunk; f++) {
            const float* vp = vbase - (f << 10);
            float v0 = vp[0], v1 = vp[256], v2 = vp[512], v3 = vp[768];
#pragma unroll
            for (int i = 0; i < 8; i++) {
                float tf = s_t[i][f];
                acc0[i] += v0 * tf; acc1[i] += v1 * tf;
                acc2[i] += v2 * tf; acc3[i] += v3 * tf;
            }
        }

        float lm[8];
#pragma unroll
        for (int i = 0; i < 8; i++) lm[i] = 0.f;
        for (int i = 0; i < nb; i++) {
            int e = s_ei[i];
            float a0 = s_av0[i];
            float v0 = a0 * acc0[i];
            if (tid == 0) v0 += s_av1[i] * s_t[i][chunk];
            float v1 = a0 * acc1[i], v2 = a0 * acc2[i], v3 = a0 * acc3[i];
            size_t o = (size_t)e * NS + t0 + tid;
            g_h[o] = v0; g_h[o + 256] = v1; g_h[o + 512] = v2; g_h[o + 768] = v3;
            lm[i] = fmaxf(fmaxf(fabsf(v0), fabsf(v1)), fmaxf(fabsf(v2), fabsf(v3)));
        }
#pragma unroll
        for (int i = 0; i < 8; i++) {
#pragma unroll
            for (int off = 16; off; off >>= 1)
                lm[i] = fmaxf(lm[i], __shfl_xor_sync(0xffffffffu, lm[i], off));
        }
        int wid = tid >> 5, lane = tid & 31;
        if (lane == 0) {
#pragma unroll
            for (int i = 0; i < 8; i++) s_wm[wid][i] = lm[i];
        }
        __syncthreads();
        if (tid < 8) {
            float m = s_wm[0][tid];
#pragma unroll
            for (int w = 1; w < 8; w++) m = fmaxf(m, s_wm[w][tid]);
            if (tid < nb) atomicMax(&g_hmaxbits[s_ei[tid]], __float_as_uint(m));
        }
        __syncthreads();
    }
}

// ---------------------------------------------------------------------------
// FFT passes. MODE 0: fwd pass1 (64 slots: 32 m-pairs + 32 h-pairs) -> zA.
// MODE 2: inv pass1 on product spectra (zB, ROW-MAJOR [k1*512+k2]) -> zA.
// MODE 3: inv pass2 + epilogue.
// ---------------------------------------------------------------------------
template <int MODE>
__global__ void __launch_bounds__(512) k_fft2(float* __restrict__ out) {
    __shared__ float sRe[8 * 584];
    __shared__ float sIm[8 * 584];
    __shared__ float2 sW[512];
    int slot = blockIdx.y, tile = blockIdx.x, tid = threadIdx.x;
    int c0 = tile * 8;
    const bool INV = (MODE >= 2);

    sW[tid] = g_twA[tid];

    if (MODE == 0) {
        const float *s1, *s2;
        float f1, f2;
        if (slot < 32) {
            int e1 = 2 * slot, e2 = 2 * slot + 1;
            s1 = g_mixed + (size_t)e1 * NS;
            s2 = g_mixed + (size_t)e2 * NS;
            f1 = 1.0f / (__uint_as_float(g_normbits[e1]) + 1e-8f);
            f2 = 1.0f / (__uint_as_float(g_normbits[e2]) + 1e-8f);
        } else {
            int e1 = 2 * (slot - 32), e2 = e1 + 1;
            s1 = g_h + (size_t)e1 * NS;
            s2 = g_h + (size_t)e2 * NS;
            f1 = 1.0f / (__uint_as_float(g_hmaxbits[e1]) + 1e-20f);
            f2 = 1.0f / (__uint_as_float(g_hmaxbits[e2]) + 1e-20f);
        }
#pragma unroll
        for (int it = 0; it < 8; it++) {
            int lin = tid + 512 * it;
            int f = lin & 7, r = lin >> 3;
            int n = c0 + f + 512 * r;
            float re = 0.f, im = 0.f;
            if (n < NS) { re = s1[n] * f1; im = s2[n] * f2; }
            sRe[f * 584 + r] = re; sIm[f * 584 + r] = im;
        }
    } else if (MODE == 2) {   // rows of zB (row-major products), contiguous
#pragma unroll
        for (int it = 0; it < 8; it++) {
            int lin = tid + 512 * it;
            int f = lin >> 9, r = lin & 511;
            float2 z = g_zB[(size_t)slot * MF + (c0 + f) * 512 + r];
            sRe[f * 584 + r] = z.x; sIm[f * 584 + r] = z.y;
        }
    } else {   // MODE 3: rows of zA, contiguous
#pragma unroll
        for (int it = 0; it < 8; it++) {
            int lin = tid + 512 * it;
            int f = lin >> 9, n1 = lin & 511;
            float2 z = g_zA[(size_t)slot * MF + (c0 + f) * 512 + n1];
            sRe[f * 584 + n1] = z.x; sIm[f * 584 + n1] = z.y;
        }
    }
    __syncthreads();

    fft512<INV>(sRe, sIm, sW, tid);

    if (MODE == 0 || MODE == 2) {
#pragma unroll
        for (int it = 0; it < 8; it++) {
            int lin = tid + 512 * it;
            int f = lin & 7, k = lin >> 3;
            float2 v = make_float2(sRe[f * 584 + k], sIm[f * 584 + k]);
            float2 w = g_tw2[(c0 + f) * 512 + k];
            if (INV) w.y = -w.y;
            g_zA[(size_t)slot * MF + k * 512 + (c0 + f)] = cmul(v, w);
        }
    } else {
        int e1 = 2 * slot, e2 = 2 * slot + 1;
        const float invm = 1.0f / (float)MF;
        float sc1 = (__uint_as_float(g_hmaxbits[e1]) + 1e-20f) * invm;
        float sc2 = (__uint_as_float(g_hmaxbits[e2]) + 1e-20f) * invm;
        float* o1 = out + (size_t)e1 * NS;
        float* o2 = out + (size_t)e2 * NS;
#pragma unroll
        for (int it = 0; it < 4; it++) {   // only k < 256 -> t < NS
            int lin = tid + 512 * it;
            int f = lin & 7, k = lin >> 3;
            int t = (c0 + f) + 512 * k;
            o1[t] = sRe[f * 584 + k] * sc1;
            o2[t] = sIm[f * 584 + k] * sc2;
        }
    }
}

// ---------------------------------------------------------------------------
// Fused forward pass-2 + combine. CTA handles rows {a, 512-a, b, 512-b} of
// BOTH the m-slot (p) and h-slot (32+p): 8 fft512s, then in-smem unpack
// (conjugate symmetry pairs row a[k2] with row 512-a[511-k2]; rows 0 and 256
// are self-mirrored), P_e = M_e*H_e, repack (P1 + i*P2), write product rows
// ROW-MAJOR to zB slot p. Fully coalesced reads and writes.
// ---------------------------------------------------------------------------
__device__ __forceinline__ float2 ldbuf(const float* sRe, const float* sIm, int i, int k) {
    return make_float2(sRe[i * 584 + k], sIm[i * 584 + k]);
}

__global__ void __launch_bounds__(512) k_fc() {
    __shared__ float sRe[8 * 584];
    __shared__ float sIm[8 * 584];
    __shared__ float2 sW[512];
    int p = blockIdx.y, tile = blockIdx.x, tid = threadIdx.x;
    sW[tid] = g_twA[tid];

    int rows[4];
    if (tile == 0) { rows[0] = 0; rows[1] = 256; rows[2] = 1; rows[3] = 511; }
    else { rows[0] = 2 * tile; rows[1] = 512 - 2 * tile;
           rows[2] = 2 * tile + 1; rows[3] = 511 - 2 * tile; }

#pragma unroll
    for (int it = 0; it < 8; it++) {
        int sl = (it < 4) ? p : (32 + p);
        int rr = rows[it & 3];
        float2 z = g_zA[(size_t)sl * MF + rr * 512 + tid];
        sRe[it * 584 + tid] = z.x; sIm[it * 584 + tid] = z.y;
    }
    __syncthreads();

    fft512<false>(sRe, sIm, sW, tid);

    float2* Zo = g_zB + (size_t)p * MF;
    int k2 = tid;

    if (tile == 0) {
        // self rows: 0 (mirror k2' = (512-k2)&511) and 256 (mirror 511-k2)
        {
            int kp = (512 - k2) & 511;
            float2 Za = ldbuf(sRe, sIm, 0, k2), Zb = ldbuf(sRe, sIm, 0, kp);
            float2 Ha = ldbuf(sRe, sIm, 4, k2), Hb = ldbuf(sRe, sIm, 4, kp);
            float2 M1 = make_float2(0.5f*(Za.x+Zb.x), 0.5f*(Za.y-Zb.y));
            float2 M2 = make_float2(0.5f*(Za.y+Zb.y), 0.5f*(Zb.x-Za.x));
            float2 H1 = make_float2(0.5f*(Ha.x+Hb.x), 0.5f*(Ha.y-Hb.y));
            float2 H2 = make_float2(0.5f*(Ha.y+Hb.y), 0.5f*(Hb.x-Ha.x));
            float2 P1 = cmul(M1, H1), P2 = cmul(M2, H2);
            Zo[0 * 512 + k2] = make_float2(P1.x - P2.y, P1.y + P2.x);
        }
        {
            int kp = 511 - k2;
            float2 Za = ldbuf(sRe, sIm, 1, k2), Zb = ldbuf(sRe, sIm, 1, kp);
            float2 Ha = ldbuf(sRe, sIm, 5, k2), Hb = ldbuf(sRe, sIm, 5, kp);
            float2 M1 = make_float2(0.5f*(Za.x+Zb.x), 0.5f*(Za.y-Zb.y));
            float2 M2 = make_float2(0.5f*(Za.y+Zb.y), 0.5f*(Zb.x-Za.x));
            float2 H1 = make_float2(0.5f*(Ha.x+Hb.x), 0.5f*(Ha.y-Hb.y));
            float2 H2 = make_float2(0.5f*(Ha.y+Hb.y), 0.5f*(Hb.x-Ha.x));
            float2 P1 = cmul(M1, H1), P2 = cmul(M2, H2);
            Zo[256 * 512 + k2] = make_float2(P1.x - P2.y, P1.y + P2.x);
        }
        // pair (1, 511): buf 2/3 (m), 6/7 (h)
        {
            int kp = 511 - k2;
            float2 Za = ldbuf(sRe, sIm, 2, k2), Zb = ldbuf(sRe, sIm, 3, kp);
            float2 Ha = ldbuf(sRe, sIm, 6, k2), Hb = ldbuf(sRe, sIm, 7, kp);
            float2 M1 = make_float2(0.5f*(Za.x+Zb.x), 0.5f*(Za.y-Zb.y));
            float2 M2 = make_float2(0.5f*(Za.y+Zb.y), 0.5f*(Zb.x-Za.x));
            float2 H1 = make_float2(0.5f*(Ha.x+Hb.x), 0.5f*(Ha.y-Hb.y));
            float2 H2 = make_float2(0.5f*(Ha.y+Hb.y), 0.5f*(Hb.x-Ha.x));
            float2 P1 = cmul(M1, H1), P2 = cmul(M2, H2);
            Zo[1 * 512 + k2]   = make_float2(P1.x - P2.y, P1.y + P2.x);
            Zo[511 * 512 + kp] = make_float2(P1.x + P2.y, P2.x - P1.y);
        }
    } else {
#pragma unroll
        for (int pr = 0; pr < 2; pr++) {
            int ia = 2 * pr, ib = 2 * pr + 1;
            int ra = rows[ia], rb = rows[ib];
            int kp = 511 - k2;
            float2 Za = ldbuf(sRe, sIm, ia, k2), Zb = ldbuf(sRe, sIm, ib, kp);
            float2 Ha = ldbuf(sRe, sIm, ia + 4, k2), Hb = ldbuf(sRe, sIm, ib + 4, kp);
            float2 M1 = make_float2(0.5f*(Za.x+Zb.x), 0.5f*(Za.y-Zb.y));
            float2 M2 = make_float2(0.5f*(Za.y+Zb.y), 0.5f*(Zb.x-Za.x));
            float2 H1 = make_float2(0.5f*(Ha.x+Hb.x), 0.5f*(Ha.y-Hb.y));
            float2 H2 = make_float2(0.5f*(Ha.y+Hb.y), 0.5f*(Hb.x-Ha.x));
            float2 P1 = cmul(M1, H1), P2 = cmul(M2, H2);
            Zo[ra * 512 + k2] = make_float2(P1.x - P2.y, P1.y + P2.x);
            Zo[rb * 512 + kp] = make_float2(P1.x + P2.y, P2.x - P1.y);
        }
    }
}

// ---------------------------------------------------------------------------
extern "C" void kernel_launch(void* const* d_in, const int* in_sizes, int n_in,
                              void* d_out, int out_size) {
    const float* voice    = (const float*)d_in[0];
    const float* cpc      = (const float*)d_in[1];
    const float* amp      = (const float*)d_in[2];
    const float* rooml    = (const float*)d_in[3];
    const float* rmix     = (const float*)d_in[4];
    const float* times    = (const float*)d_in[5];
    const float* cp_items = (const float*)d_in[6];
    const float* verbs    = (const float*)d_in[7];
    const float* w1       = (const float*)d_in[8];
    const float* w2       = (const float*)d_in[9];
    const float* amaps    = (const float*)d_in[10];
    const float* decays   = (const float*)d_in[11];
    const float* gains    = (const float*)d_in[12];
    const float* mix      = (const float*)d_in[13];
    float* out = (float*)d_out;

    k_tw1<<<1, 512>>>();
    k_tw2<<<512, 512>>>();
    k_prep<<<64, 256>>>(voice, cpc, amp, rooml, rmix, cp_items, w1, w2, decays, gains, mix);
    k_audio<<<dim3(16, 64), 256>>>(amaps);
    k_h2<<<dim3(128, 8), 256>>>(verbs, times);
    k_fft2<0><<<dim3(64, 64), 512>>>(out);   // 32 m-pairs + 32 h-pairs -> zA
    k_fc<<<dim3(128, 32), 512>>>();          // fwd pass2 + combine -> zB products
    k_fft2<2><<<dim3(64, 32), 512>>>(out);   // inv pass1
    k_fft2<3><<<dim3(64, 32), 512>>>(out);   // inv pass2 + epilogue
}

// round 10
// speedup vs baseline: 2.8527x; 1.0774x over previous
#include <cuda_runtime.h>
#include <math.h>

#define NS 131072           // N_SAMPLES
#define NEV 64              // B*E
#define MF 262144           // FFT length = 2*NS
#define NFRAMES 128
#define CPD 16

struct EvScalars { int vidx; int ridx; float av0; float av1; };

__device__ EvScalars g_sc[NEV];
__device__ unsigned  g_normbits[NEV];   // max |mixed|
__device__ unsigned  g_hmaxbits[NEV];   // max |h|
__device__ int       g_vcount[8];       // events per verb
__device__ int       g_vlist[8 * 64];   // event ids grouped by verb
__device__ float     g_cpw[NEV * 3 * CPD * NFRAMES];   // smix-weighted cp_out
__device__ float     g_mixed[NEV * NS];
__device__ float     g_h[NEV * NS];
__device__ float2    g_twA[512];        // W_512^a = W_MF^(512a)
__device__ float2    g_twB[512];        // W_MF^b
// zA: inter-pass scratch (64 fwd slots / 32 inv slots).
// zB: PRODUCT spectra only, slots 0..31, ROW-MAJOR: [k1*512 + k2], k = k1+512*k2.
__device__ float2    g_zA[NEV * MF];
__device__ float2    g_zB[NEV * MF];

__device__ __forceinline__ float2 cmul(float2 a, float2 b) {
    return make_float2(a.x * b.x - a.y * b.y, a.x * b.y + a.y * b.x);
}
__device__ __forceinline__ float2 cadd(float2 a, float2 b){return make_float2(a.x+b.x,a.y+b.y);}
__device__ __forceinline__ float2 csub(float2 a, float2 b){return make_float2(a.x-b.x,a.y-b.y);}

template<bool INV>
__device__ __forceinline__ float2 mulj(float2 a) {  // * (-i) fwd, * (+i) inv
    return INV ? make_float2(-a.y, a.x) : make_float2(a.y, -a.x);
}

// 8-point DFT, natural-order in/out
template<bool INV>
__device__ __forceinline__ void dft8(float2 v[8]) {
    const float C = 0.70710678118654752f;
    float2 b0=cadd(v[0],v[4]), b4=csub(v[0],v[4]);
    float2 b1=cadd(v[1],v[5]), b5=csub(v[1],v[5]);
    float2 b2=cadd(v[2],v[6]), b6=csub(v[2],v[6]);
    float2 b3=cadd(v[3],v[7]), b7=csub(v[3],v[7]);
    b5 = INV ? make_float2(C*(b5.x-b5.y), C*(b5.x+b5.y))
             : make_float2(C*(b5.x+b5.y), C*(b5.y-b5.x));
    b6 = mulj<INV>(b6);
    b7 = INV ? make_float2(-C*(b7.x+b7.y), C*(b7.x-b7.y))
             : make_float2(C*(b7.y-b7.x), -C*(b7.x+b7.y));
    float2 c0=cadd(b0,b2), c2=csub(b0,b2);
    float2 c1=cadd(b1,b3), c3=mulj<INV>(csub(b1,b3));
    float2 c4=cadd(b4,b6), c6=csub(b4,b6);
    float2 c5=cadd(b5,b7), c7=mulj<INV>(csub(b5,b7));
    v[0]=cadd(c0,c1); v[4]=csub(c0,c1);
    v[2]=cadd(c2,c3); v[6]=csub(c2,c3);
    v[1]=cadd(c4,c5); v[5]=csub(c4,c5);
    v[3]=cadd(c6,c7); v[7]=csub(c6,c7);
}

// ---------------------------------------------------------------------------
// 512-point FFT, radix-8^3, 64 threads per FFT (8 FFTs per 512-thread CTA).
// ---------------------------------------------------------------------------
template<bool INV>
__device__ __forceinline__ void fft512(float* sRe, float* sIm, const float2* sW, int tid) {
    int t = tid & 63;
    int base = (tid >> 6) * 584;
    float2 v[8];
#pragma unroll
    for (int j = 0; j < 8; j++) {
        int a = base + t + 64 * j;
        v[j] = make_float2(sRe[a], sIm[a]);
    }
    dft8<INV>(v);
    {
        float2 w1 = sW[t];                 // W_512^t
        if (INV) w1.y = -w1.y;
        float2 wc = w1;
        v[1] = cmul(v[1], wc);
#pragma unroll
        for (int k0 = 2; k0 < 8; k0++) { wc = cmul(wc, w1); v[k0] = cmul(v[k0], wc); }
    }
    __syncthreads();
#pragma unroll
    for (int k0 = 0; k0 < 8; k0++) {
        int a = base + 72 * k0 + t;
        sRe[a] = v[k0].x; sIm[a] = v[k0].y;
    }
    __syncthreads();
    int k0 = t >> 3, r = t & 7;
#pragma unroll
    for (int m1 = 0; m1 < 8; m1++) {
        int a = base + 72 * k0 + r + 8 * m1;
        v[m1] = make_float2(sRe[a], sIm[a]);
    }
    dft8<INV>(v);
    {
        float2 w1 = sW[8 * r];             // W_64^r
        if (INV) w1.y = -w1.y;
        float2 wc = w1;
        v[1] = cmul(v[1], wc);
#pragma unroll
        for (int k1 = 2; k1 < 8; k1++) { wc = cmul(wc, w1); v[k1] = cmul(v[k1], wc); }
    }
    __syncthreads();
#pragma unroll
    for (int k1 = 0; k1 < 8; k1++) {
        int a = base + 72 * k0 + 9 * k1 + r;
        sRe[a] = v[k1].x; sIm[a] = v[k1].y;
    }
    __syncthreads();
#pragma unroll
    for (int m0 = 0; m0 < 8; m0++) {
        int a = base + 72 * k0 + 9 * r + m0;
        v[m0] = make_float2(sRe[a], sIm[a]);
    }
    dft8<INV>(v);
    __syncthreads();
#pragma unroll
    for (int k2 = 0; k2 < 8; k2++) {
        int a = base + k0 + 8 * r + 64 * k2;
        sRe[a] = v[k2].x; sIm[a] = v[k2].y;
    }
    __syncthreads();
}

// ---------------------------------------------------------------------------
__global__ void k_tw1() {
    int t = threadIdx.x;   // 512
    double s, c;
    double angA = -2.0 * 3.14159265358979323846 * (double)t / 512.0;
    sincos(angA, &s, &c);
    g_twA[t] = make_float2((float)c, (float)s);
    double angB = -2.0 * 3.14159265358979323846 * (double)t / (double)MF;
    sincos(angB, &s, &c);
    g_twB[t] = make_float2((float)c, (float)s);
    if (t < 8) g_vcount[t] = 0;
}

// ---------------------------------------------------------------------------
// Per-event prep: argmaxes, softmaxes, cp select + sparsify, 3-block stack.
// ---------------------------------------------------------------------------
__global__ void k_prep(const float* __restrict__ voice, const float* __restrict__ cpc,
                       const float* __restrict__ amp,   const float* __restrict__ rooml,
                       const float* __restrict__ rmix,  const float* __restrict__ cp_items,
                       const float* __restrict__ w1,    const float* __restrict__ w2,
                       const float* __restrict__ decays,const float* __restrict__ gains,
                       const float* __restrict__ mix) {
    int e = blockIdx.x, tid = threadIdx.x;
    __shared__ float s_cp[2048];
    __shared__ float s_wc[2048];
    __shared__ float s_x[2048];
    __shared__ float s_y[2048];
    __shared__ float s_w1[256], s_w2[256];
    __shared__ float s_d[16], s_g[16];
    __shared__ float s_red[256];
    __shared__ float s_smix[3];
    __shared__ int   s_vidx, s_cidx;

    if (tid == 0) {
        const float* v = voice + e * 8;
        int vi = 0; float bv = v[0];
        for (int i = 1; i < 8; i++) if (v[i] > bv) { bv = v[i]; vi = i; }
        s_vidx = vi;
        const float* c = cpc + e * 512;
        int ci = 0; float bc = c[0];
        for (int i = 1; i < 512; i++) if (c[i] > bc) { bc = c[i]; ci = i; }
        s_cidx = ci;
        const float* r = rooml + e * 8;
        int ri = 0; float br = r[0];
        for (int i = 1; i < 8; i++) if (r[i] > br) { br = r[i]; ri = i; }
        float m0 = rmix[e * 2 + 0], m1 = rmix[e * 2 + 1];
        float mx = fmaxf(m0, m1);
        float e0 = expf(m0 - mx), e1 = expf(m1 - mx);
        float vm0 = e0 / (e0 + e1), vm1 = e1 / (e0 + e1);
        float a = fabsf(amp[e]);
        g_sc[e].vidx = vi; g_sc[e].ridx = ri;
        g_sc[e].av0 = a * vm0; g_sc[e].av1 = a * vm1;
        int pos = atomicAdd(&g_vcount[ri], 1);
        g_vlist[ri * 64 + pos] = e;
        float q0 = mix[vi * 3 + 0], q1 = mix[vi * 3 + 1], q2 = mix[vi * 3 + 2];
        float qm = fmaxf(q0, fmaxf(q1, q2));
        float f0 = expf(q0 - qm), f1 = expf(q1 - qm), f2 = expf(q2 - qm);
        float fs = f0 + f1 + f2;
        s_smix[0] = f0 / fs; s_smix[1] = f1 / fs; s_smix[2] = f2 / fs;
        g_normbits[e] = 0u;
        g_hmaxbits[e] = 0u;
    }
    __syncthreads();
    int vi = s_vidx, ci = s_cidx;

    float ls = 0.f;
    for (int i = tid; i < 2048; i += 256) {
        float v = cp_items[ci * 2048 + i];
        s_cp[i] = v; ls += v;
    }
    s_red[tid] = ls; __syncthreads();
    for (int o = 128; o > 0; o >>= 1) {
        if (tid < o) s_red[tid] += s_red[tid + o];
        __syncthreads();
    }
    float inv = 1.0f / (s_red[0] + 1e-8f);

    float vloc[8]; int cnt[8];
#pragma unroll
    for (int u = 0; u < 8; u++) { vloc[u] = s_cp[tid + 256 * u]; cnt[u] = 0; }
    for (int j = 0; j < 2048; j++) {
        float vj = s_cp[j];
#pragma unroll
        for (int u = 0; u < 8; u++) cnt[u] += (vj > vloc[u]) ? 1 : 0;
    }
#pragma unroll
    for (int u = 0; u < 8; u++)
        s_wc[tid + 256 * u] = (cnt[u] < 32) ? vloc[u] * inv : 0.f;
    __syncthreads();

    for (int blk = 0; blk < 3; blk++) {
        s_w1[tid] = w1[(vi * 3 + blk) * 256 + tid];
        s_w2[tid] = w2[(vi * 3 + blk) * 256 + tid];
        if (tid < 16) {
            float dp = decays[(vi * 3 + blk) * 16 + tid];
            s_d[tid] = 0.5f + (1.f / (1.f + expf(-dp))) * 0.5f;
            float gp = gains[(vi * 3 + blk) * 16 + tid];
            s_g[tid] = (1.f / (1.f + expf(-gp))) * 5.f;
        }
        __syncthreads();
#pragma unroll
        for (int u = 0; u < 8; u++) {
            int idx = tid + 256 * u;
            int c = idx >> 7, f = idx & 127;
            float acc = 0.f;
#pragma unroll
            for (int k = 0; k < 16; k++)
                acc += s_w1[c * 16 + k] * fmaxf(s_wc[k * 128 + f], 0.f);
            s_x[idx] = acc;
        }
        __syncthreads();
        if (tid < 16) {
            float d = s_d[tid];
            float y = 0.f;
            for (int f = 0; f < 128; f++) {
                y = d * (s_x[tid * 128 + f] + y);
                s_y[tid * 128 + f] = y;
            }
        }
        __syncthreads();
#pragma unroll
        for (int u = 0; u < 8; u++) {
            int idx = tid + 256 * u;
            int c = idx >> 7, f = idx & 127;
            float acc = s_x[idx];
#pragma unroll
            for (int k = 0; k < 16; k++)
                acc += s_w2[c * 16 + k] * s_y[k * 128 + f];
            float co = tanhf(acc * s_g[c]);
            g_cpw[((e * 3 + blk) * 16 + c) * 128 + f] = s_smix[blk] * co;
            s_wc[idx] = co;
        }
        __syncthreads();
    }
}

// ---------------------------------------------------------------------------
// Audio synthesis + mix + per-event max(|mixed|). 8 frames x 4 samples per
// thread. __launch_bounds__(256,3): cap regs so 3 CTAs fit per SM.
// ---------------------------------------------------------------------------
__global__ void __launch_bounds__(256, 3) k_audio(const float* __restrict__ audio_maps) {
    int fg = blockIdx.x, e = blockIdx.y, tid = threadIdx.x;
    __shared__ float s_c[8][48];
    __shared__ float s_red[256];
    __shared__ int s_v;
    if (tid == 0) s_v = g_sc[e].vidx;
    for (int s = tid; s < 384; s += 256) {
        int fr = s / 48, ic = s % 48;
        int i = ic >> 4, c = ic & 15;
        s_c[fr][ic] = g_cpw[((e * 3 + i) * 16 + c) * 128 + (fg * 8 + fr)];
    }
    __syncthreads();
    const float* am = audio_maps + (size_t)s_v * 3 * 1024 * 16;
    float acc[8][4];
#pragma unroll
    for (int fr = 0; fr < 8; fr++)
#pragma unroll
        for (int q = 0; q < 4; q++) acc[fr][q] = 0.f;

#pragma unroll
    for (int i = 0; i < 3; i++) {
#pragma unroll
        for (int r = 0; r < 4; r++) {
            float4 a[4];
#pragma unroll
            for (int q = 0; q < 4; q++)
                a[q] = __ldg(reinterpret_cast<const float4*>(
                           am + (i * 1024 + tid + 256 * q) * 16) + r);
#pragma unroll
            for (int fr = 0; fr < 8; fr++) {
                float c0 = s_c[fr][i * 16 + 4 * r + 0];
                float c1 = s_c[fr][i * 16 + 4 * r + 1];
                float c2 = s_c[fr][i * 16 + 4 * r + 2];
                float c3 = s_c[fr][i * 16 + 4 * r + 3];
#pragma unroll
                for (int q = 0; q < 4; q++)
                    acc[fr][q] += a[q].x * c0 + a[q].y * c1 + a[q].z * c2 + a[q].w * c3;
            }
        }
    }
    float lmax = 0.f;
#pragma unroll
    for (int fr = 0; fr < 8; fr++) {
#pragma unroll
        for (int q = 0; q < 4; q++) {
            float v = acc[fr][q];
            g_mixed[e * NS + (fg * 8 + fr) * 1024 + tid + 256 * q] = v;
            lmax = fmaxf(lmax, fabsf(v));
        }
    }
    s_red[tid] = lmax; __syncthreads();
    for (int o = 128; o > 0; o >>= 1) {
        if (tid < o) s_red[tid] = fmaxf(s_red[tid], s_red[tid + o]);
        __syncthreads();
    }
    if (tid == 0) atomicMax(&g_normbits[e], __float_as_uint(s_red[0]));
}

// ---------------------------------------------------------------------------
// h = amp*(vm0*(verb (x) impulse) + vm1*impulse), grouped by verb.
// ---------------------------------------------------------------------------
__global__ void k_h2(const float* __restrict__ verbs, const float* __restrict__ times) {
    int r = blockIdx.y;
    int cnt = g_vcount[r];
    if (cnt == 0) return;
    int chunk = blockIdx.x;
    int t0 = chunk << 10;
    int tid = threadIdx.x;
    __shared__ float s_t[8][128];
    __shared__ int   s_ei[8];
    __shared__ float s_av0[8], s_av1[8];
    __shared__ float s_wm[8][8];
    const float* vb = verbs + (size_t)r * NS;

    for (int b = 0; b < cnt; b += 8) {
        int nb = min(8, cnt - b);
        if (tid < 8) {
            if (tid < nb) {
                int e = g_vlist[r * 64 + b + tid];
                s_ei[tid] = e;
                s_av0[tid] = g_sc[e].av0;
                s_av1[tid] = g_sc[e].av1;
            } else s_ei[tid] = -1;
        }
        __syncthreads();
        for (int s = tid; s < 1024; s += 256) {
            int i = s >> 7, f = s & 127;
            s_t[i][f] = (i < nb) ? times[(size_t)g_vlist[r * 64 + b + i] * 128 + f] : 0.f;
        }
        __syncthreads();

        float acc0[8], acc1[8], acc2[8], acc3[8];
#pragma unroll
        for (int i = 0; i < 8; i++) { acc0[i]=0.f; acc1[i]=0.f; acc2[i]=0.f; acc3[i]=0.f; }
        const float* vbase = vb + t0 + tid;
#pragma unroll 2
        for (int f = 0; f <= chunk; f++) {
            const float* vp = vbase - (f << 10);
            float v0 = vp[0], v1 = vp[256], v2 = vp[512], v3 = vp[768];
#pragma unroll
            for (int i = 0; i < 8; i++) {
                float tf = s_t[i][f];
                acc0[i] += v0 * tf; acc1[i] += v1 * tf;
                acc2[i] += v2 * tf; acc3[i] += v3 * tf;
            }
        }

        float lm[8];
#pragma unroll
        for (int i = 0; i < 8; i++) lm[i] = 0.f;
        for (int i = 0; i < nb; i++) {
            int e = s_ei[i];
            float a0 = s_av0[i];
            float v0 = a0 * acc0[i];
            if (tid == 0) v0 += s_av1[i] * s_t[i][chunk];
            float v1 = a0 * acc1[i], v2 = a0 * acc2[i], v3 = a0 * acc3[i];
            size_t o = (size_t)e * NS + t0 + tid;
            g_h[o] = v0; g_h[o + 256] = v1; g_h[o + 512] = v2; g_h[o + 768] = v3;
            lm[i] = fmaxf(fmaxf(fabsf(v0), fabsf(v1)), fmaxf(fabsf(v2), fabsf(v3)));
        }
#pragma unroll
        for (int i = 0; i < 8; i++) {
#pragma unroll
            for (int off = 16; off; off >>= 1)
                lm[i] = fmaxf(lm[i], __shfl_xor_sync(0xffffffffu, lm[i], off));
        }
        int wid = tid >> 5, lane = tid & 31;
        if (lane == 0) {
#pragma unroll
            for (int i = 0; i < 8; i++) s_wm[wid][i] = lm[i];
        }
        __syncthreads();
        if (tid < 8) {
            float m = s_wm[0][tid];
#pragma unroll
            for (int w = 1; w < 8; w++) m = fmaxf(m, s_wm[w][tid]);
            if (tid < nb) atomicMax(&g_hmaxbits[s_ei[tid]], __float_as_uint(m));
        }
        __syncthreads();
    }
}

// ---------------------------------------------------------------------------
// FFT passes. MODE 0: fwd pass1 (64 slots: 32 m-pairs + 32 h-pairs) -> zA.
// MODE 2: inv pass1 on product spectra (zB, ROW-MAJOR [k1*512+k2]) -> zA.
// MODE 3: inv pass2 + epilogue.
// Inter-pass twiddle W_MF^(n1*k) via register power chain (exact base from
// the two 4KB tables: W^p = twA[p>>9]*twB[p&511]); no big table, no gmem.
// ---------------------------------------------------------------------------
template <int MODE>
__global__ void __launch_bounds__(512) k_fft2(float* __restrict__ out) {
    __shared__ float sRe[8 * 584];
    __shared__ float sIm[8 * 584];
    __shared__ float2 sW[512];
    __shared__ float2 sWB[512];
    int slot = blockIdx.y, tile = blockIdx.x, tid = threadIdx.x;
    int c0 = tile * 8;
    const bool INV = (MODE >= 2);

    sW[tid] = g_twA[tid];
    if (MODE == 0 || MODE == 2) sWB[tid] = g_twB[tid];

    if (MODE == 0) {
        const float *s1, *s2;
        float f1, f2;
        if (slot < 32) {
            int e1 = 2 * slot, e2 = 2 * slot + 1;
            s1 = g_mixed + (size_t)e1 * NS;
            s2 = g_mixed + (size_t)e2 * NS;
            f1 = 1.0f / (__uint_as_float(g_normbits[e1]) + 1e-8f);
            f2 = 1.0f / (__uint_as_float(g_normbits[e2]) + 1e-8f);
        } else {
            int e1 = 2 * (slot - 32), e2 = e1 + 1;
            s1 = g_h + (size_t)e1 * NS;
            s2 = g_h + (size_t)e2 * NS;
            f1 = 1.0f / (__uint_as_float(g_hmaxbits[e1]) + 1e-20f);
            f2 = 1.0f / (__uint_as_float(g_hmaxbits[e2]) + 1e-20f);
        }
#pragma unroll
        for (int it = 0; it < 8; it++) {
            int lin = tid + 512 * it;
            int f = lin & 7, r = lin >> 3;
            int n = c0 + f + 512 * r;
            float re = 0.f, im = 0.f;
            if (n < NS) { re = s1[n] * f1; im = s2[n] * f2; }
            sRe[f * 584 + r] = re; sIm[f * 584 + r] = im;
        }
    } else if (MODE == 2) {   // rows of zB (row-major products), contiguous
#pragma unroll
        for (int it = 0; it < 8; it++) {
            int lin = tid + 512 * it;
            int f = lin >> 9, r = lin & 511;
            float2 z = g_zB[(size_t)slot * MF + (c0 + f) * 512 + r];
            sRe[f * 584 + r] = z.x; sIm[f * 584 + r] = z.y;
        }
    } else {   // MODE 3: rows of zA, contiguous
#pragma unroll
        for (int it = 0; it < 8; it++) {
            int lin = tid + 512 * it;
            int f = lin >> 9, n1 = lin & 511;
            float2 z = g_zA[(size_t)slot * MF + (c0 + f) * 512 + n1];
            sRe[f * 584 + n1] = z.x; sIm[f * 584 + n1] = z.y;
        }
    }
    __syncthreads();

    fft512<INV>(sRe, sIm, sW, tid);

    if (MODE == 0 || MODE == 2) {
        int f = tid & 7, k0 = tid >> 3;
        int n1 = c0 + f;
        int pb = n1 * k0;          // < 512*64
        int ps = n1 * 64;          // < 512*64
        float2 w  = cmul(sW[pb >> 9], sWB[pb & 511]);   // W_MF^(n1*k0)
        float2 st = cmul(sW[ps >> 9], sWB[ps & 511]);   // W_MF^(n1*64)
        if (INV) { w.y = -w.y; st.y = -st.y; }
#pragma unroll
        for (int it = 0; it < 8; it++) {
            int k = k0 + 64 * it;
            float2 v = make_float2(sRe[f * 584 + k], sIm[f * 584 + k]);
            g_zA[(size_t)slot * MF + k * 512 + n1] = cmul(v, w);
            w = cmul(w, st);
        }
    } else {
        int e1 = 2 * slot, e2 = 2 * slot + 1;
        const float invm = 1.0f / (float)MF;
        float sc1 = (__uint_as_float(g_hmaxbits[e1]) + 1e-20f) * invm;
        float sc2 = (__uint_as_float(g_hmaxbits[e2]) + 1e-20f) * invm;
        float* o1 = out + (size_t)e1 * NS;
        float* o2 = out + (size_t)e2 * NS;
#pragma unroll
        for (int it = 0; it < 4; it++) {   // only k < 256 -> t < NS
            int lin = tid + 512 * it;
            int f = lin & 7, k = lin >> 3;
            int t = (c0 + f) + 512 * k;
            o1[t] = sRe[f * 584 + k] * sc1;
            o2[t] = sIm[f * 584 + k] * sc2;
        }
    }
}

// ---------------------------------------------------------------------------
// Fused forward pass-2 + combine (rows {a,512-a,b,512-b} of m-slot p and
// h-slot 32+p; unpack via conjugate symmetry in smem; write products
// row-major to zB slot p).
// ---------------------------------------------------------------------------
__device__ __forceinline__ float2 ldbuf(const float* sRe, const float* sIm, int i, int k) {
    return make_float2(sRe[i * 584 + k], sIm[i * 584 + k]);
}

__global__ void __launch_bounds__(512) k_fc() {
    __shared__ float sRe[8 * 584];
    __shared__ float sIm[8 * 584];
    __shared__ float2 sW[512];
    int p = blockIdx.y, tile = blockIdx.x, tid = threadIdx.x;
    sW[tid] = g_twA[tid];

    int rows[4];
    if (tile == 0) { rows[0] = 0; rows[1] = 256; rows[2] = 1; rows[3] = 511; }
    else { rows[0] = 2 * tile; rows[1] = 512 - 2 * tile;
           rows[2] = 2 * tile + 1; rows[3] = 511 - 2 * tile; }

#pragma unroll
    for (int it = 0; it < 8; it++) {
        int sl = (it < 4) ? p : (32 + p);
        int rr = rows[it & 3];
        float2 z = g_zA[(size_t)sl * MF + rr * 512 + tid];
        sRe[it * 584 + tid] = z.x; sIm[it * 584 + tid] = z.y;
    }
    __syncthreads();

    fft512<false>(sRe, sIm, sW, tid);

    float2* Zo = g_zB + (size_t)p * MF;
    int k2 = tid;

    if (tile == 0) {
        {
            int kp = (512 - k2) & 511;
            float2 Za = ldbuf(sRe, sIm, 0, k2), Zb = ldbuf(sRe, sIm, 0, kp);
            float2 Ha = ldbuf(sRe, sIm, 4, k2), Hb = ldbuf(sRe, sIm, 4, kp);
            float2 M1 = make_float2(0.5f*(Za.x+Zb.x), 0.5f*(Za.y-Zb.y));
            float2 M2 = make_float2(0.5f*(Za.y+Zb.y), 0.5f*(Zb.x-Za.x));
            float2 H1 = make_float2(0.5f*(Ha.x+Hb.x), 0.5f*(Ha.y-Hb.y));
            float2 H2 = make_float2(0.5f*(Ha.y+Hb.y), 0.5f*(Hb.x-Ha.x));
            float2 P1 = cmul(M1, H1), P2 = cmul(M2, H2);
            Zo[0 * 512 + k2] = make_float2(P1.x - P2.y, P1.y + P2.x);
        }
        {
            int kp = 511 - k2;
            float2 Za = ldbuf(sRe, sIm, 1, k2), Zb = ldbuf(sRe, sIm, 1, kp);
            float2 Ha = ldbuf(sRe, sIm, 5, k2), Hb = ldbuf(sRe, sIm, 5, kp);
            float2 M1 = make_float2(0.5f*(Za.x+Zb.x), 0.5f*(Za.y-Zb.y));
            float2 M2 = make_float2(0.5f*(Za.y+Zb.y), 0.5f*(Zb.x-Za.x));
            float2 H1 = make_float2(0.5f*(Ha.x+Hb.x), 0.5f*(Ha.y-Hb.y));
            float2 H2 = make_float2(0.5f*(Ha.y+Hb.y), 0.5f*(Hb.x-Ha.x));
            float2 P1 = cmul(M1, H1), P2 = cmul(M2, H2);
            Zo[256 * 512 + k2] = make_float2(P1.x - P2.y, P1.y + P2.x);
        }
        {
            int kp = 511 - k2;
            float2 Za = ldbuf(sRe, sIm, 2, k2), Zb = ldbuf(sRe, sIm, 3, kp);
            float2 Ha = ldbuf(sRe, sIm, 6, k2), Hb = ldbuf(sRe, sIm, 7, kp);
            float2 M1 = make_float2(0.5f*(Za.x+Zb.x), 0.5f*(Za.y-Zb.y));
            float2 M2 = make_float2(0.5f*(Za.y+Zb.y), 0.5f*(Zb.x-Za.x));
            float2 H1 = make_float2(0.5f*(Ha.x+Hb.x), 0.5f*(Ha.y-Hb.y));
            float2 H2 = make_float2(0.5f*(Ha.y+Hb.y), 0.5f*(Hb.x-Ha.x));
            float2 P1 = cmul(M1, H1), P2 = cmul(M2, H2);
            Zo[1 * 512 + k2]   = make_float2(P1.x - P2.y, P1.y + P2.x);
            Zo[511 * 512 + kp] = make_float2(P1.x + P2.y, P2.x - P1.y);
        }
    } else {
#pragma unroll
        for (int pr = 0; pr < 2; pr++) {
            int ia = 2 * pr, ib = 2 * pr + 1;
            int ra = rows[ia], rb = rows[ib];
            int kp = 511 - k2;
            float2 Za = ldbuf(sRe, sIm, ia, k2), Zb = ldbuf(sRe, sIm, ib, kp);
            float2 Ha = ldbuf(sRe, sIm, ia + 4, k2), Hb = ldbuf(sRe, sIm, ib + 4, kp);
            float2 M1 = make_float2(0.5f*(Za.x+Zb.x), 0.5f*(Za.y-Zb.y));
            float2 M2 = make_float2(0.5f*(Za.y+Zb.y), 0.5f*(Zb.x-Za.x));
            float2 H1 = make_float2(0.5f*(Ha.x+Hb.x), 0.5f*(Ha.y-Hb.y));
            float2 H2 = make_float2(0.5f*(Ha.y+Hb.y), 0.5f*(Hb.x-Ha.x));
            float2 P1 = cmul(M1, H1), P2 = cmul(M2, H2);
            Zo[ra * 512 + k2] = make_float2(P1.x - P2.y, P1.y + P2.x);
            Zo[rb * 512 + kp] = make_float2(P1.x + P2.y, P2.x - P1.y);
        }
    }
}

// ---------------------------------------------------------------------------
extern "C" void kernel_launch(void* const* d_in, const int* in_sizes, int n_in,
                              void* d_out, int out_size) {
    const float* voice    = (const float*)d_in[0];
    const float* cpc      = (const float*)d_in[1];
    const float* amp      = (const float*)d_in[2];
    const float* rooml    = (const float*)d_in[3];
    const float* rmix     = (const float*)d_in[4];
    const float* times    = (const float*)d_in[5];
    const float* cp_items = (const float*)d_in[6];
    const float* verbs    = (const float*)d_in[7];
    const float* w1       = (const float*)d_in[8];
    const float* w2       = (const float*)d_in[9];
    const float* amaps    = (const float*)d_in[10];
    const float* decays   = (const float*)d_in[11];
    const float* gains    = (const float*)d_in[12];
    const float* mix      = (const float*)d_in[13];
    float* out = (float*)d_out;

    k_tw1<<<1, 512>>>();
    k_prep<<<64, 256>>>(voice, cpc, amp, rooml, rmix, cp_items, w1, w2, decays, gains, mix);
    k_audio<<<dim3(16, 64), 256>>>(amaps);
    k_h2<<<dim3(128, 8), 256>>>(verbs, times);
    k_fft2<0><<<dim3(64, 64), 512>>>(out);   // 32 m-pairs + 32 h-pairs -> zA
    k_fc<<<dim3(128, 32), 512>>>();          // fwd pass2 + combine -> zB products
    k_fft2<2><<<dim3(64, 32), 512>>>(out);   // inv pass1
    k_fft2<3><<<dim3(64, 32), 512>>>(out);   // inv pass2 + epilogue
}

// round 11
// speedup vs baseline: 3.0206x; 1.0588x over previous
#include <cuda_runtime.h>
#include <math.h>

#define NS 131072           // N_SAMPLES
#define NEV 64              // B*E
#define MF 262144           // FFT length = 2*NS
#define NFRAMES 128
#define CPD 16

struct EvScalars { int vidx; int ridx; float av0; float av1; };

__device__ EvScalars g_sc[NEV];
__device__ unsigned  g_normbits[NEV];   // max |mixed|
__device__ unsigned  g_hmaxbits[NEV];   // max |h|
__device__ int       g_vcount[8];       // events per verb
__device__ int       g_vlist[8 * 64];   // event ids grouped by verb
__device__ float     g_cpw[NEV * 3 * CPD * NFRAMES];   // smix-weighted cp_out
__device__ float     g_mixed[NEV * NS];
__device__ float     g_h[NEV * NS];
__device__ float2    g_twA[512];        // W_512^a = W_MF^(512a)
__device__ float2    g_twB[512];        // W_MF^b
// zA: forward pass-1 output (64 slots: 32 m-pairs, 32 h-pairs).
// zB: inverse pass-1 output (32 slots), layout [k*512 + n1].
__device__ float2    g_zA[NEV * MF];
__device__ float2    g_zB[NEV * MF];

__device__ __forceinline__ float2 cmul(float2 a, float2 b) {
    return make_float2(a.x * b.x - a.y * b.y, a.x * b.y + a.y * b.x);
}
__device__ __forceinline__ float2 cadd(float2 a, float2 b){return make_float2(a.x+b.x,a.y+b.y);}
__device__ __forceinline__ float2 csub(float2 a, float2 b){return make_float2(a.x-b.x,a.y-b.y);}

template<bool INV>
__device__ __forceinline__ float2 mulj(float2 a) {  // * (-i) fwd, * (+i) inv
    return INV ? make_float2(-a.y, a.x) : make_float2(a.y, -a.x);
}

// 8-point DFT, natural-order in/out
template<bool INV>
__device__ __forceinline__ void dft8(float2 v[8]) {
    const float C = 0.70710678118654752f;
    float2 b0=cadd(v[0],v[4]), b4=csub(v[0],v[4]);
    float2 b1=cadd(v[1],v[5]), b5=csub(v[1],v[5]);
    float2 b2=cadd(v[2],v[6]), b6=csub(v[2],v[6]);
    float2 b3=cadd(v[3],v[7]), b7=csub(v[3],v[7]);
    b5 = INV ? make_float2(C*(b5.x-b5.y), C*(b5.x+b5.y))
             : make_float2(C*(b5.x+b5.y), C*(b5.y-b5.x));
    b6 = mulj<INV>(b6);
    b7 = INV ? make_float2(-C*(b7.x+b7.y), C*(b7.x-b7.y))
             : make_float2(C*(b7.y-b7.x), -C*(b7.x+b7.y));
    float2 c0=cadd(b0,b2), c2=csub(b0,b2);
    float2 c1=cadd(b1,b3), c3=mulj<INV>(csub(b1,b3));
    float2 c4=cadd(b4,b6), c6=csub(b4,b6);
    float2 c5=cadd(b5,b7), c7=mulj<INV>(csub(b5,b7));
    v[0]=cadd(c0,c1); v[4]=csub(c0,c1);
    v[2]=cadd(c2,c3); v[6]=csub(c2,c3);
    v[1]=cadd(c4,c5); v[5]=csub(c4,c5);
    v[3]=cadd(c6,c7); v[7]=csub(c6,c7);
}

// ---------------------------------------------------------------------------
// 512-point FFT, radix-8^3, 64 threads per FFT (8 FFTs per 512-thread CTA).
// ---------------------------------------------------------------------------
template<bool INV>
__device__ __forceinline__ void fft512(float* sRe, float* sIm, const float2* sW, int tid) {
    int t = tid & 63;
    int base = (tid >> 6) * 584;
    float2 v[8];
#pragma unroll
    for (int j = 0; j < 8; j++) {
        int a = base + t + 64 * j;
        v[j] = make_float2(sRe[a], sIm[a]);
    }
    dft8<INV>(v);
    {
        float2 w1 = sW[t];                 // W_512^t
        if (INV) w1.y = -w1.y;
        float2 wc = w1;
        v[1] = cmul(v[1], wc);
#pragma unroll
        for (int k0 = 2; k0 < 8; k0++) { wc = cmul(wc, w1); v[k0] = cmul(v[k0], wc); }
    }
    __syncthreads();
#pragma unroll
    for (int k0 = 0; k0 < 8; k0++) {
        int a = base + 72 * k0 + t;
        sRe[a] = v[k0].x; sIm[a] = v[k0].y;
    }
    __syncthreads();
    int k0 = t >> 3, r = t & 7;
#pragma unroll
    for (int m1 = 0; m1 < 8; m1++) {
        int a = base + 72 * k0 + r + 8 * m1;
        v[m1] = make_float2(sRe[a], sIm[a]);
    }
    dft8<INV>(v);
    {
        float2 w1 = sW[8 * r];             // W_64^r
        if (INV) w1.y = -w1.y;
        float2 wc = w1;
        v[1] = cmul(v[1], wc);
#pragma unroll
        for (int k1 = 2; k1 < 8; k1++) { wc = cmul(wc, w1); v[k1] = cmul(v[k1], wc); }
    }
    __syncthreads();
#pragma unroll
    for (int k1 = 0; k1 < 8; k1++) {
        int a = base + 72 * k0 + 9 * k1 + r;
        sRe[a] = v[k1].x; sIm[a] = v[k1].y;
    }
    __syncthreads();
#pragma unroll
    for (int m0 = 0; m0 < 8; m0++) {
        int a = base + 72 * k0 + 9 * r + m0;
        v[m0] = make_float2(sRe[a], sIm[a]);
    }
    dft8<INV>(v);
    __syncthreads();
#pragma unroll
    for (int k2 = 0; k2 < 8; k2++) {
        int a = base + k0 + 8 * r + 64 * k2;
        sRe[a] = v[k2].x; sIm[a] = v[k2].y;
    }
    __syncthreads();
}

// ---------------------------------------------------------------------------
__global__ void k_tw1() {
    int t = threadIdx.x;   // 512
    double s, c;
    double angA = -2.0 * 3.14159265358979323846 * (double)t / 512.0;
    sincos(angA, &s, &c);
    g_twA[t] = make_float2((float)c, (float)s);
    double angB = -2.0 * 3.14159265358979323846 * (double)t / (double)MF;
    sincos(angB, &s, &c);
    g_twB[t] = make_float2((float)c, (float)s);
    if (t < 8) g_vcount[t] = 0;
}

// ---------------------------------------------------------------------------
// Per-event prep: argmaxes, softmaxes, cp select + sparsify, 3-block stack.
// ---------------------------------------------------------------------------
__global__ void k_prep(const float* __restrict__ voice, const float* __restrict__ cpc,
                       const float* __restrict__ amp,   const float* __restrict__ rooml,
                       const float* __restrict__ rmix,  const float* __restrict__ cp_items,
                       const float* __restrict__ w1,    const float* __restrict__ w2,
                       const float* __restrict__ decays,const float* __restrict__ gains,
                       const float* __restrict__ mix) {
    int e = blockIdx.x, tid = threadIdx.x;
    __shared__ float s_cp[2048];
    __shared__ float s_wc[2048];
    __shared__ float s_x[2048];
    __shared__ float s_y[2048];
    __shared__ float s_w1[256], s_w2[256];
    __shared__ float s_d[16], s_g[16];
    __shared__ float s_red[256];
    __shared__ float s_smix[3];
    __shared__ int   s_vidx, s_cidx;

    if (tid == 0) {
        const float* v = voice + e * 8;
        int vi = 0; float bv = v[0];
        for (int i = 1; i < 8; i++) if (v[i] > bv) { bv = v[i]; vi = i; }
        s_vidx = vi;
        const float* c = cpc + e * 512;
        int ci = 0; float bc = c[0];
        for (int i = 1; i < 512; i++) if (c[i] > bc) { bc = c[i]; ci = i; }
        s_cidx = ci;
        const float* r = rooml + e * 8;
        int ri = 0; float br = r[0];
        for (int i = 1; i < 8; i++) if (r[i] > br) { br = r[i]; ri = i; }
        float m0 = rmix[e * 2 + 0], m1 = rmix[e * 2 + 1];
        float mx = fmaxf(m0, m1);
        float e0 = expf(m0 - mx), e1 = expf(m1 - mx);
        float vm0 = e0 / (e0 + e1), vm1 = e1 / (e0 + e1);
        float a = fabsf(amp[e]);
        g_sc[e].vidx = vi; g_sc[e].ridx = ri;
        g_sc[e].av0 = a * vm0; g_sc[e].av1 = a * vm1;
        int pos = atomicAdd(&g_vcount[ri], 1);
        g_vlist[ri * 64 + pos] = e;
        float q0 = mix[vi * 3 + 0], q1 = mix[vi * 3 + 1], q2 = mix[vi * 3 + 2];
        float qm = fmaxf(q0, fmaxf(q1, q2));
        float f0 = expf(q0 - qm), f1 = expf(q1 - qm), f2 = expf(q2 - qm);
        float fs = f0 + f1 + f2;
        s_smix[0] = f0 / fs; s_smix[1] = f1 / fs; s_smix[2] = f2 / fs;
        g_normbits[e] = 0u;
        g_hmaxbits[e] = 0u;
    }
    __syncthreads();
    int vi = s_vidx, ci = s_cidx;

    float ls = 0.f;
    for (int i = tid; i < 2048; i += 256) {
        float v = cp_items[ci * 2048 + i];
        s_cp[i] = v; ls += v;
    }
    s_red[tid] = ls; __syncthreads();
    for (int o = 128; o > 0; o >>= 1) {
        if (tid < o) s_red[tid] += s_red[tid + o];
        __syncthreads();
    }
    float inv = 1.0f / (s_red[0] + 1e-8f);

    float vloc[8]; int cnt[8];
#pragma unroll
    for (int u = 0; u < 8; u++) { vloc[u] = s_cp[tid + 256 * u]; cnt[u] = 0; }
    for (int j = 0; j < 2048; j++) {
        float vj = s_cp[j];
#pragma unroll
        for (int u = 0; u < 8; u++) cnt[u] += (vj > vloc[u]) ? 1 : 0;
    }
#pragma unroll
    for (int u = 0; u < 8; u++)
        s_wc[tid + 256 * u] = (cnt[u] < 32) ? vloc[u] * inv : 0.f;
    __syncthreads();

    for (int blk = 0; blk < 3; blk++) {
        s_w1[tid] = w1[(vi * 3 + blk) * 256 + tid];
        s_w2[tid] = w2[(vi * 3 + blk) * 256 + tid];
        if (tid < 16) {
            float dp = decays[(vi * 3 + blk) * 16 + tid];
            s_d[tid] = 0.5f + (1.f / (1.f + expf(-dp))) * 0.5f;
            float gp = gains[(vi * 3 + blk) * 16 + tid];
            s_g[tid] = (1.f / (1.f + expf(-gp))) * 5.f;
        }
        __syncthreads();
#pragma unroll
        for (int u = 0; u < 8; u++) {
            int idx = tid + 256 * u;
            int c = idx >> 7, f = idx & 127;
            float acc = 0.f;
#pragma unroll
            for (int k = 0; k < 16; k++)
                acc += s_w1[c * 16 + k] * fmaxf(s_wc[k * 128 + f], 0.f);
            s_x[idx] = acc;
        }
        __syncthreads();
        if (tid < 16) {
            float d = s_d[tid];
            float y = 0.f;
            for (int f = 0; f < 128; f++) {
                y = d * (s_x[tid * 128 + f] + y);
                s_y[tid * 128 + f] = y;
            }
        }
        __syncthreads();
#pragma unroll
        for (int u = 0; u < 8; u++) {
            int idx = tid + 256 * u;
            int c = idx >> 7, f = idx & 127;
            float acc = s_x[idx];
#pragma unroll
            for (int k = 0; k < 16; k++)
                acc += s_w2[c * 16 + k] * s_y[k * 128 + f];
            float co = tanhf(acc * s_g[c]);
            g_cpw[((e * 3 + blk) * 16 + c) * 128 + f] = s_smix[blk] * co;
            s_wc[idx] = co;
        }
        __syncthreads();
    }
}

// ---------------------------------------------------------------------------
// MERGED audio-synthesis + h-computation kernel. Flat grid of 2048 blocks:
//   bid < 1024 : h path (chunk = bid&127, verb = bid>>7), float4 verb loads
//   bid >= 1024: audio path (fg = (bid-1024)&15, e = (bid-1024)>>4)
// Independent outputs (g_h vs g_mixed) -> natural SM-level overlap.
// ---------------------------------------------------------------------------
__global__ void __launch_bounds__(256, 3) k_ah(const float* __restrict__ audio_maps,
                                               const float* __restrict__ verbs,
                                               const float* __restrict__ times) {
    int bid = blockIdx.x, tid = threadIdx.x;
    __shared__ float s_c[8][48];
    __shared__ float s_red[256];
    __shared__ int s_v;
    __shared__ float s_t[8][128];
    __shared__ int   s_ei[8];
    __shared__ float s_av0[8], s_av1[8];
    __shared__ float s_wm[8][8];

    if (bid < 1024) {
        // ------------- h path -------------
        int chunk = bid & 127, r = bid >> 7;
        int cnt = g_vcount[r];
        if (cnt == 0) return;
        int t0 = chunk << 10;
        const float* vb = verbs + (size_t)r * NS;

        for (int b = 0; b < cnt; b += 8) {
            int nb = min(8, cnt - b);
            if (tid < 8) {
                if (tid < nb) {
                    int e = g_vlist[r * 64 + b + tid];
                    s_ei[tid] = e;
                    s_av0[tid] = g_sc[e].av0;
                    s_av1[tid] = g_sc[e].av1;
                } else s_ei[tid] = -1;
            }
            __syncthreads();
            for (int s = tid; s < 1024; s += 256) {
                int i = s >> 7, f = s & 127;
                s_t[i][f] = (i < nb) ? times[(size_t)g_vlist[r * 64 + b + i] * 128 + f] : 0.f;
            }
            __syncthreads();

            float4 acc[8];
#pragma unroll
            for (int i = 0; i < 8; i++) acc[i] = make_float4(0.f, 0.f, 0.f, 0.f);
            const float4* vbase = reinterpret_cast<const float4*>(vb + t0) + tid;
#pragma unroll 2
            for (int f = 0; f <= chunk; f++) {
                float4 v = vbase[-(f << 8)];
#pragma unroll
                for (int i = 0; i < 8; i++) {
                    float tf = s_t[i][f];
                    acc[i].x += v.x * tf; acc[i].y += v.y * tf;
                    acc[i].z += v.z * tf; acc[i].w += v.w * tf;
                }
            }

            float lm[8];
#pragma unroll
            for (int i = 0; i < 8; i++) lm[i] = 0.f;
            for (int i = 0; i < nb; i++) {
                float a0 = s_av0[i];
                float4 val = make_float4(a0 * acc[i].x, a0 * acc[i].y,
                                         a0 * acc[i].z, a0 * acc[i].w);
                if (tid == 0) val.x += s_av1[i] * s_t[i][chunk];
                reinterpret_cast<float4*>(g_h + (size_t)s_ei[i] * NS + t0)[tid] = val;
                lm[i] = fmaxf(fmaxf(fabsf(val.x), fabsf(val.y)),
                              fmaxf(fabsf(val.z), fabsf(val.w)));
            }
#pragma unroll
            for (int i = 0; i < 8; i++) {
#pragma unroll
                for (int off = 16; off; off >>= 1)
                    lm[i] = fmaxf(lm[i], __shfl_xor_sync(0xffffffffu, lm[i], off));
            }
            int wid = tid >> 5, lane = tid & 31;
            if (lane == 0) {
#pragma unroll
                for (int i = 0; i < 8; i++) s_wm[wid][i] = lm[i];
            }
            __syncthreads();
            if (tid < 8) {
                float m = s_wm[0][tid];
#pragma unroll
                for (int w = 1; w < 8; w++) m = fmaxf(m, s_wm[w][tid]);
                if (tid < nb) atomicMax(&g_hmaxbits[s_ei[tid]], __float_as_uint(m));
            }
            __syncthreads();
        }
    } else {
        // ------------- audio path -------------
        int bid2 = bid - 1024;
        int fg = bid2 & 15, e = bid2 >> 4;
        if (tid == 0) s_v = g_sc[e].vidx;
        for (int s = tid; s < 384; s += 256) {
            int fr = s / 48, ic = s % 48;
            int i = ic >> 4, c = ic & 15;
            s_c[fr][ic] = g_cpw[((e * 3 + i) * 16 + c) * 128 + (fg * 8 + fr)];
        }
        __syncthreads();
        const float* am = audio_maps + (size_t)s_v * 3 * 1024 * 16;
        float acc[8][4];
#pragma unroll
        for (int fr = 0; fr < 8; fr++)
#pragma unroll
            for (int q = 0; q < 4; q++) acc[fr][q] = 0.f;

#pragma unroll
        for (int i = 0; i < 3; i++) {
#pragma unroll
            for (int r = 0; r < 4; r++) {
                float4 a[4];
#pragma unroll
                for (int q = 0; q < 4; q++)
                    a[q] = __ldg(reinterpret_cast<const float4*>(
                               am + (i * 1024 + tid + 256 * q) * 16) + r);
#pragma unroll
                for (int fr = 0; fr < 8; fr++) {
                    float c0 = s_c[fr][i * 16 + 4 * r + 0];
                    float c1 = s_c[fr][i * 16 + 4 * r + 1];
                    float c2 = s_c[fr][i * 16 + 4 * r + 2];
                    float c3 = s_c[fr][i * 16 + 4 * r + 3];
#pragma unroll
                    for (int q = 0; q < 4; q++)
                        acc[fr][q] += a[q].x * c0 + a[q].y * c1 + a[q].z * c2 + a[q].w * c3;
                }
            }
        }
        float lmax = 0.f;
#pragma unroll
        for (int fr = 0; fr < 8; fr++) {
#pragma unroll
            for (int q = 0; q < 4; q++) {
                float v = acc[fr][q];
                g_mixed[e * NS + (fg * 8 + fr) * 1024 + tid + 256 * q] = v;
                lmax = fmaxf(lmax, fabsf(v));
            }
        }
        s_red[tid] = lmax; __syncthreads();
        for (int o = 128; o > 0; o >>= 1) {
            if (tid < o) s_red[tid] = fmaxf(s_red[tid], s_red[tid + o]);
            __syncthreads();
        }
        if (tid == 0) atomicMax(&g_normbits[e], __float_as_uint(s_red[0]));
    }
}

// ---------------------------------------------------------------------------
// FFT passes. MODE 0: fwd pass1 (64 slots: 32 m-pairs + 32 h-pairs) -> zA.
// MODE 3: inv pass2 + epilogue (reads zB rows written by k_fc2).
// ---------------------------------------------------------------------------
template <int MODE>
__global__ void __launch_bounds__(512) k_fft2(float* __restrict__ out) {
    __shared__ float sRe[8 * 584];
    __shared__ float sIm[8 * 584];
    __shared__ float2 sW[512];
    __shared__ float2 sWB[512];
    int slot = blockIdx.y, tile = blockIdx.x, tid = threadIdx.x;
    int c0 = tile * 8;
    const bool INV = (MODE >= 2);

    sW[tid] = g_twA[tid];
    if (MODE == 0) sWB[tid] = g_twB[tid];

    if (MODE == 0) {
        const float *s1, *s2;
        float f1, f2;
        if (slot < 32) {
            int e1 = 2 * slot, e2 = 2 * slot + 1;
            s1 = g_mixed + (size_t)e1 * NS;
            s2 = g_mixed + (size_t)e2 * NS;
            f1 = 1.0f / (__uint_as_float(g_normbits[e1]) + 1e-8f);
            f2 = 1.0f / (__uint_as_float(g_normbits[e2]) + 1e-8f);
        } else {
            int e1 = 2 * (slot - 32), e2 = e1 + 1;
            s1 = g_h + (size_t)e1 * NS;
            s2 = g_h + (size_t)e2 * NS;
            f1 = 1.0f / (__uint_as_float(g_hmaxbits[e1]) + 1e-20f);
            f2 = 1.0f / (__uint_as_float(g_hmaxbits[e2]) + 1e-20f);
        }
#pragma unroll
        for (int it = 0; it < 8; it++) {
            int lin = tid + 512 * it;
            int f = lin & 7, r = lin >> 3;
            int n = c0 + f + 512 * r;
            float re = 0.f, im = 0.f;
            if (n < NS) { re = s1[n] * f1; im = s2[n] * f2; }
            sRe[f * 584 + r] = re; sIm[f * 584 + r] = im;
        }
    } else {   // MODE 3: rows of zB, contiguous
#pragma unroll
        for (int it = 0; it < 8; it++) {
            int lin = tid + 512 * it;
            int f = lin >> 9, n1 = lin & 511;
            float2 z = g_zB[(size_t)slot * MF + (c0 + f) * 512 + n1];
            sRe[f * 584 + n1] = z.x; sIm[f * 584 + n1] = z.y;
        }
    }
    __syncthreads();

    fft512<INV>(sRe, sIm, sW, tid);

    if (MODE == 0) {
        int f = tid & 7, k0 = tid >> 3;
        int n1 = c0 + f;
        int pb = n1 * k0;
        int ps = n1 * 64;
        float2 w  = cmul(sW[pb >> 9], sWB[pb & 511]);   // W_MF^(n1*k0)
        float2 st = cmul(sW[ps >> 9], sWB[ps & 511]);   // W_MF^(n1*64)
#pragma unroll
        for (int it = 0; it < 8; it++) {
            int k = k0 + 64 * it;
            float2 v = make_float2(sRe[f * 584 + k], sIm[f * 584 + k]);
            g_zA[(size_t)slot * MF + k * 512 + n1] = cmul(v, w);
            w = cmul(w, st);
        }
    } else {
        int e1 = 2 * slot, e2 = 2 * slot + 1;
        const float invm = 1.0f / (float)MF;
        float sc1 = (__uint_as_float(g_hmaxbits[e1]) + 1e-20f) * invm;
        float sc2 = (__uint_as_float(g_hmaxbits[e2]) + 1e-20f) * invm;
        float* o1 = out + (size_t)e1 * NS;
        float* o2 = out + (size_t)e2 * NS;
#pragma unroll
        for (int it = 0; it < 4; it++) {   // only k < 256 -> t < NS
            int lin = tid + 512 * it;
            int f = lin & 7, k = lin >> 3;
            int t = (c0 + f) + 512 * k;
            o1[t] = sRe[f * 584 + k] * sc1;
            o2[t] = sIm[f * 584 + k] * sc2;
        }
    }
}

// ---------------------------------------------------------------------------
// Fused forward pass-2 + combine + INVERSE pass-1. CTA = two old tiles
// (2T, 2T+1): product rows {4T..4T+3} u {509-4T..512-4T} (contiguous groups).
// Flow: fwd batch half0 -> 4 products to regs; fwd batch half1 -> 4 more;
// scatter all 8 product rows into the smem buffers; inverse fft512 batch;
// conjugate inter-pass twiddle; transposed store to zB (MODE3 reads zB).
// ---------------------------------------------------------------------------
__device__ __forceinline__ float2 ldbuf(const float* sRe, const float* sIm, int i, int k) {
    return make_float2(sRe[i * 584 + k], sIm[i * 584 + k]);
}
__device__ __forceinline__ void stbuf(float* sRe, float* sIm, int i, int k, float2 v) {
    sRe[i * 584 + k] = v.x; sIm[i * 584 + k] = v.y;
}

__global__ void __launch_bounds__(512, 2) k_fc2() {
    __shared__ float sRe[8 * 584];
    __shared__ float sIm[8 * 584];
    __shared__ float2 sW[512];
    int p = blockIdx.y, T = blockIdx.x, tid = threadIdx.x;
    sW[tid] = g_twA[tid];

    float2 park[8];

#pragma unroll
    for (int half = 0; half < 2; half++) {
        int t = 2 * T + half;
        int rows4[4];
        if (t == 0) { rows4[0] = 0; rows4[1] = 256; rows4[2] = 1; rows4[3] = 511; }
        else { rows4[0] = 2 * t; rows4[1] = 512 - 2 * t;
               rows4[2] = 2 * t + 1; rows4[3] = 511 - 2 * t; }
        if (half) __syncthreads();    // half0 product reads complete before overwrite
#pragma unroll
        for (int it = 0; it < 8; it++) {
            int sl = (it < 4) ? p : (32 + p);
            float2 z = g_zA[(size_t)sl * MF + rows4[it & 3] * 512 + tid];
            sRe[it * 584 + tid] = z.x; sIm[it * 584 + tid] = z.y;
        }
        __syncthreads();

        fft512<false>(sRe, sIm, sW, tid);

        int o = half * 4;
        if (t == 0) {
            {   // row 0 (self-mirror: col (512-k2)&511)
                int kp = (512 - tid) & 511;
                float2 Za = ldbuf(sRe, sIm, 0, tid), Zb = ldbuf(sRe, sIm, 0, kp);
                float2 Ha = ldbuf(sRe, sIm, 4, tid), Hb = ldbuf(sRe, sIm, 4, kp);
                float2 M1 = make_float2(0.5f*(Za.x+Zb.x), 0.5f*(Za.y-Zb.y));
                float2 M2 = make_float2(0.5f*(Za.y+Zb.y), 0.5f*(Zb.x-Za.x));
                float2 H1 = make_float2(0.5f*(Ha.x+Hb.x), 0.5f*(Ha.y-Hb.y));
                float2 H2 = make_float2(0.5f*(Ha.y+Hb.y), 0.5f*(Hb.x-Ha.x));
                float2 P1 = cmul(M1, H1), P2 = cmul(M2, H2);
                park[o + 0] = make_float2(P1.x - P2.y, P1.y + P2.x);   // row 0 @ tid
            }
            {   // row 256 (self-mirror: col 511-k2)
                int kp = 511 - tid;
                float2 Za = ldbuf(sRe, sIm, 1, tid), Zb = ldbuf(sRe, sIm, 1, kp);
                float2 Ha = ldbuf(sRe, sIm, 5, tid), Hb = ldbuf(sRe, sIm, 5, kp);
                float2 M1 = make_float2(0.5f*(Za.x+Zb.x), 0.5f*(Za.y-Zb.y));
                float2 M2 = make_float2(0.5f*(Za.y+Zb.y), 0.5f*(Zb.x-Za.x));
                float2 H1 = make_float2(0.5f*(Ha.x+Hb.x), 0.5f*(Ha.y-Hb.y));
                float2 H2 = make_float2(0.5f*(Ha.y+Hb.y), 0.5f*(Hb.x-Ha.x));
                float2 P1 = cmul(M1, H1), P2 = cmul(M2, H2);
                park[o + 1] = make_float2(P1.x - P2.y, P1.y + P2.x);   // row 256 @ tid
            }
            {   // pair (1, 511)
                int kp = 511 - tid;
                float2 Za = ldbuf(sRe, sIm, 2, tid), Zb = ldbuf(sRe, sIm, 3, kp);
                float2 Ha = ldbuf(sRe, sIm, 6, tid), Hb = ldbuf(sRe, sIm, 7, kp);
                float2 M1 = make_float2(0.5f*(Za.x+Zb.x), 0.5f*(Za.y-Zb.y));
                float2 M2 = make_float2(0.5f*(Za.y+Zb.y), 0.5f*(Zb.x-Za.x));
                float2 H1 = make_float2(0.5f*(Ha.x+Hb.x), 0.5f*(Ha.y-Hb.y));
                float2 H2 = make_float2(0.5f*(Ha.y+Hb.y), 0.5f*(Hb.x-Ha.x));
                float2 P1 = cmul(M1, H1), P2 = cmul(M2, H2);
                park[o + 2] = make_float2(P1.x - P2.y, P1.y + P2.x);   // row 1 @ tid
                park[o + 3] = make_float2(P1.x + P2.y, P2.x - P1.y);   // row 511 @ 511-tid
            }
        } else {
#pragma unroll
            for (int pr = 0; pr < 2; pr++) {
                int ia = 2 * pr, ib = 2 * pr + 1;
                int kp = 511 - tid;
                float2 Za = ldbuf(sRe, sIm, ia, tid), Zb = ldbuf(sRe, sIm, ib, kp);
                float2 Ha = ldbuf(sRe, sIm, ia + 4, tid), Hb = ldbuf(sRe, sIm, ib + 4, kp);
                float2 M1 = make_float2(0.5f*(Za.x+Zb.x), 0.5f*(Za.y-Zb.y));
                float2 M2 = make_float2(0.5f*(Za.y+Zb.y), 0.5f*(Zb.x-Za.x));
                float2 H1 = make_float2(0.5f*(Ha.x+Hb.x), 0.5f*(Ha.y-Hb.y));
                float2 H2 = make_float2(0.5f*(Ha.y+Hb.y), 0.5f*(Hb.x-Ha.x));
                float2 P1 = cmul(M1, H1), P2 = cmul(M2, H2);
                park[o + 2 * pr + 0] = make_float2(P1.x - P2.y, P1.y + P2.x);  // rows4[ia] @ tid
                park[o + 2 * pr + 1] = make_float2(P1.x + P2.y, P2.x - P1.y);  // rows4[ib] @ 511-tid
            }
        }
    }
    __syncthreads();   // all product reads done before buffer overwrite

    // Scatter the 8 product rows into buffers (buf f -> row n1(f) below).
    int kinv = 511 - tid;
    int c7 = (T == 0) ? tid : kinv;          // T=0: park[1] is row 256 @ tid
    stbuf(sRe, sIm, 0, tid,  park[0]);       // row 4T      (T=0: row 0)
    stbuf(sRe, sIm, 7, c7,   park[1]);       // row 512-4T  (T=0: row 256)
    stbuf(sRe, sIm, 1, tid,  park[2]);       // row 4T+1    (T=0: row 1)
    stbuf(sRe, sIm, 6, kinv, park[3]);       // row 511-4T  (T=0: row 511)
    stbuf(sRe, sIm, 2, tid,  park[4]);       // row 4T+2
    stbuf(sRe, sIm, 5, kinv, park[5]);       // row 510-4T
    stbuf(sRe, sIm, 3, tid,  park[6]);       // row 4T+3
    stbuf(sRe, sIm, 4, kinv, park[7]);       // row 509-4T
    __syncthreads();

    fft512<true>(sRe, sIm, sW, tid);

    // inverse inter-pass twiddle + transposed store to zB
    int f = tid & 7, k0 = tid >> 3;
    int n1;
    if (T == 0) n1 = (f < 4) ? f : (f == 7 ? 256 : 505 + f);
    else        n1 = (f < 4) ? (4 * T + f) : (505 - 4 * T + f);
    int pb = n1 * k0, ps = n1 * 64;
    float2 w  = cmul(sW[pb >> 9], g_twB[pb & 511]); w.y  = -w.y;
    float2 st = cmul(sW[ps >> 9], g_twB[ps & 511]); st.y = -st.y;
#pragma unroll
    for (int it = 0; it < 8; it++) {
        int k = k0 + 64 * it;
        float2 v = make_float2(sRe[f * 584 + k], sIm[f * 584 + k]);
        g_zB[(size_t)p * MF + k * 512 + n1] = cmul(v, w);
        w = cmul(w, st);
    }
}

// ---------------------------------------------------------------------------
extern "C" void kernel_launch(void* const* d_in, const int* in_sizes, int n_in,
                              void* d_out, int out_size) {
    const float* voice    = (const float*)d_in[0];
    const float* cpc      = (const float*)d_in[1];
    const float* amp      = (const float*)d_in[2];
    const float* rooml    = (const float*)d_in[3];
    const float* rmix     = (const float*)d_in[4];
    const float* times    = (const float*)d_in[5];
    const float* cp_items = (const float*)d_in[6];
    const float* verbs    = (const float*)d_in[7];
    const float* w1       = (const float*)d_in[8];
    const float* w2       = (const float*)d_in[9];
    const float* amaps    = (const float*)d_in[10];
    const float* decays   = (const float*)d_in[11];
    const float* gains    = (const float*)d_in[12];
    const float* mix      = (const float*)d_in[13];
    float* out = (float*)d_out;

    k_tw1<<<1, 512>>>();
    k_prep<<<64, 256>>>(voice, cpc, amp, rooml, rmix, cp_items, w1, w2, decays, gains, mix);
    k_ah<<<2048, 256>>>(amaps, verbs, times);     // h (1024 blocks) + audio (1024 blocks)
    k_fft2<0><<<dim3(64, 64), 512>>>(out);        // fwd pass1: 32 m-pairs + 32 h-pairs
    k_fc2<<<dim3(64, 32), 512>>>();               // fwd pass2 + combine + inv pass1 -> zB
    k_fft2<3><<<dim3(64, 32), 512>>>(out);        // inv pass2 + epilogue
}

// round 12
// speedup vs baseline: 3.9414x; 1.3049x over previous
#include <cuda_runtime.h>
#include <math.h>

#define NS 131072           // N_SAMPLES
#define NEV 64              // B*E
#define MF 262144           // FFT length = 2*NS
#define NFRAMES 128
#define CPD 16
#define SP 588              // FFT smem buffer stride (conflict-free: 588%32=12)

struct EvScalars { int vidx; int ridx; float av0; float av1; };

__device__ EvScalars g_sc[NEV];
__device__ unsigned  g_normbits[NEV];   // max |mixed|
__device__ unsigned  g_hmaxbits[NEV];   // max |h|
__device__ int       g_vcount[8];       // events per verb
__device__ int       g_vlist[8 * 64];   // event ids grouped by verb
__device__ float     g_cpw[NEV * 3 * CPD * NFRAMES];   // smix-weighted cp_out
__device__ float     g_mixed[NEV * NS];
__device__ float     g_h[NEV * NS];
__device__ float2    g_twA[512];        // W_512^a = W_MF^(512a)
__device__ float2    g_twB[512];        // W_MF^b
// zA: forward pass-1 output (64 slots: 32 m-pairs, 32 h-pairs).
// zB: inverse pass-1 output (32 slots), layout [k*512 + n1].
__device__ float2    g_zA[NEV * MF];
__device__ float2    g_zB[NEV * MF];

__device__ __forceinline__ float2 cmul(float2 a, float2 b) {
    return make_float2(a.x * b.x - a.y * b.y, a.x * b.y + a.y * b.x);
}
__device__ __forceinline__ float2 cadd(float2 a, float2 b){return make_float2(a.x+b.x,a.y+b.y);}
__device__ __forceinline__ float2 csub(float2 a, float2 b){return make_float2(a.x-b.x,a.y-b.y);}

template<bool INV>
__device__ __forceinline__ float2 mulj(float2 a) {  // * (-i) fwd, * (+i) inv
    return INV ? make_float2(-a.y, a.x) : make_float2(a.y, -a.x);
}

// 8-point DFT, natural-order in/out
template<bool INV>
__device__ __forceinline__ void dft8(float2 v[8]) {
    const float C = 0.70710678118654752f;
    float2 b0=cadd(v[0],v[4]), b4=csub(v[0],v[4]);
    float2 b1=cadd(v[1],v[5]), b5=csub(v[1],v[5]);
    float2 b2=cadd(v[2],v[6]), b6=csub(v[2],v[6]);
    float2 b3=cadd(v[3],v[7]), b7=csub(v[3],v[7]);
    b5 = INV ? make_float2(C*(b5.x-b5.y), C*(b5.x+b5.y))
             : make_float2(C*(b5.x+b5.y), C*(b5.y-b5.x));
    b6 = mulj<INV>(b6);
    b7 = INV ? make_float2(-C*(b7.x+b7.y), C*(b7.x-b7.y))
             : make_float2(C*(b7.y-b7.x), -C*(b7.x+b7.y));
    float2 c0=cadd(b0,b2), c2=csub(b0,b2);
    float2 c1=cadd(b1,b3), c3=mulj<INV>(csub(b1,b3));
    float2 c4=cadd(b4,b6), c6=csub(b4,b6);
    float2 c5=cadd(b5,b7), c7=mulj<INV>(csub(b5,b7));
    v[0]=cadd(c0,c1); v[4]=csub(c0,c1);
    v[2]=cadd(c2,c3); v[6]=csub(c2,c3);
    v[1]=cadd(c4,c5); v[5]=csub(c4,c5);
    v[3]=cadd(c6,c7); v[7]=csub(c6,c7);
}

// 8-point DFT with v[4..7] == 0 implicitly (zero-padded upper half).
// First stage degenerates: b_i = b_{i+4} = v_i. Exact.
template<bool INV>
__device__ __forceinline__ void dft8h(float2 v[8]) {
    const float C = 0.70710678118654752f;
    float2 b0=v[0], b4=v[0];
    float2 b1=v[1], b5=v[1];
    float2 b2=v[2], b6=v[2];
    float2 b3=v[3], b7=v[3];
    b5 = INV ? make_float2(C*(b5.x-b5.y), C*(b5.x+b5.y))
             : make_float2(C*(b5.x+b5.y), C*(b5.y-b5.x));
    b6 = mulj<INV>(b6);
    b7 = INV ? make_float2(-C*(b7.x+b7.y), C*(b7.x-b7.y))
             : make_float2(C*(b7.y-b7.x), -C*(b7.x+b7.y));
    float2 c0=cadd(b0,b2), c2=csub(b0,b2);
    float2 c1=cadd(b1,b3), c3=mulj<INV>(csub(b1,b3));
    float2 c4=cadd(b4,b6), c6=csub(b4,b6);
    float2 c5=cadd(b5,b7), c7=mulj<INV>(csub(b5,b7));
    v[0]=cadd(c0,c1); v[4]=csub(c0,c1);
    v[2]=cadd(c2,c3); v[6]=csub(c2,c3);
    v[1]=cadd(c4,c5); v[5]=csub(c4,c5);
    v[3]=cadd(c6,c7); v[7]=csub(c6,c7);
}

// ---------------------------------------------------------------------------
// 512-point FFT, radix-8^3, 64 threads per FFT (8 FFTs per 512-thread CTA).
// HALF: input positions 256..511 are zero (only lower half staged in smem).
// ---------------------------------------------------------------------------
template<bool INV, bool HALF>
__device__ __forceinline__ void fft512(float* sRe, float* sIm, const float2* sW, int tid) {
    int t = tid & 63;
    int base = (tid >> 6) * SP;
    float2 v[8];
    if (HALF) {
#pragma unroll
        for (int j = 0; j < 4; j++) {
            int a = base + t + 64 * j;
            v[j] = make_float2(sRe[a], sIm[a]);
        }
        dft8h<INV>(v);
    } else {
#pragma unroll
        for (int j = 0; j < 8; j++) {
            int a = base + t + 64 * j;
            v[j] = make_float2(sRe[a], sIm[a]);
        }
        dft8<INV>(v);
    }
    {
        float2 w1 = sW[t];                 // W_512^t
        if (INV) w1.y = -w1.y;
        float2 wc = w1;
        v[1] = cmul(v[1], wc);
#pragma unroll
        for (int k0 = 2; k0 < 8; k0++) { wc = cmul(wc, w1); v[k0] = cmul(v[k0], wc); }
    }
    __syncthreads();
#pragma unroll
    for (int k0 = 0; k0 < 8; k0++) {
        int a = base + 72 * k0 + t;
        sRe[a] = v[k0].x; sIm[a] = v[k0].y;
    }
    __syncthreads();
    int k0 = t >> 3, r = t & 7;
#pragma unroll
    for (int m1 = 0; m1 < 8; m1++) {
        int a = base + 72 * k0 + r + 8 * m1;
        v[m1] = make_float2(sRe[a], sIm[a]);
    }
    dft8<INV>(v);
    {
        float2 w1 = sW[8 * r];             // W_64^r
        if (INV) w1.y = -w1.y;
        float2 wc = w1;
        v[1] = cmul(v[1], wc);
#pragma unroll
        for (int k1 = 2; k1 < 8; k1++) { wc = cmul(wc, w1); v[k1] = cmul(v[k1], wc); }
    }
    __syncthreads();
#pragma unroll
    for (int k1 = 0; k1 < 8; k1++) {
        int a = base + 72 * k0 + 9 * k1 + r;
        sRe[a] = v[k1].x; sIm[a] = v[k1].y;
    }
    __syncthreads();
#pragma unroll
    for (int m0 = 0; m0 < 8; m0++) {
        int a = base + 72 * k0 + 9 * r + m0;
        v[m0] = make_float2(sRe[a], sIm[a]);
    }
    dft8<INV>(v);
    __syncthreads();
#pragma unroll
    for (int k2 = 0; k2 < 8; k2++) {
        int a = base + k0 + 8 * r + 64 * k2;
        sRe[a] = v[k2].x; sIm[a] = v[k2].y;
    }
    __syncthreads();
}

// ---------------------------------------------------------------------------
__global__ void k_tw1() {
    int t = threadIdx.x;   // 512
    double s, c;
    double angA = -2.0 * 3.14159265358979323846 * (double)t / 512.0;
    sincos(angA, &s, &c);
    g_twA[t] = make_float2((float)c, (float)s);
    double angB = -2.0 * 3.14159265358979323846 * (double)t / (double)MF;
    sincos(angB, &s, &c);
    g_twB[t] = make_float2((float)c, (float)s);
    if (t < 8) g_vcount[t] = 0;
}

// ---------------------------------------------------------------------------
// Per-event prep: argmaxes, softmaxes, cp select + sparsify (radix select),
// 3-block stack.
// ---------------------------------------------------------------------------
__global__ void k_prep(const float* __restrict__ voice, const float* __restrict__ cpc,
                       const float* __restrict__ amp,   const float* __restrict__ rooml,
                       const float* __restrict__ rmix,  const float* __restrict__ cp_items,
                       const float* __restrict__ w1,    const float* __restrict__ w2,
                       const float* __restrict__ decays,const float* __restrict__ gains,
                       const float* __restrict__ mix) {
    int e = blockIdx.x, tid = threadIdx.x;
    __shared__ float s_cp[2048];
    __shared__ float s_wc[2048];
    __shared__ float s_x[2048];
    __shared__ float s_y[2048];
    __shared__ float s_w1[256], s_w2[256];
    __shared__ float s_d[16], s_g[16];
    __shared__ float s_red[256];
    __shared__ float s_smix[3];
    __shared__ int   s_vidx, s_cidx;
    __shared__ int   s_hist[256];
    __shared__ unsigned s_pref;
    __shared__ int   s_rem;

    if (tid == 0) {
        const float* v = voice + e * 8;
        int vi = 0; float bv = v[0];
        for (int i = 1; i < 8; i++) if (v[i] > bv) { bv = v[i]; vi = i; }
        s_vidx = vi;
        const float* c = cpc + e * 512;
        int ci = 0; float bc = c[0];
        for (int i = 1; i < 512; i++) if (c[i] > bc) { bc = c[i]; ci = i; }
        s_cidx = ci;
        const float* r = rooml + e * 8;
        int ri = 0; float br = r[0];
        for (int i = 1; i < 8; i++) if (r[i] > br) { br = r[i]; ri = i; }
        float m0 = rmix[e * 2 + 0], m1 = rmix[e * 2 + 1];
        float mx = fmaxf(m0, m1);
        float e0 = expf(m0 - mx), e1 = expf(m1 - mx);
        float vm0 = e0 / (e0 + e1), vm1 = e1 / (e0 + e1);
        float a = fabsf(amp[e]);
        g_sc[e].vidx = vi; g_sc[e].ridx = ri;
        g_sc[e].av0 = a * vm0; g_sc[e].av1 = a * vm1;
        int pos = atomicAdd(&g_vcount[ri], 1);
        g_vlist[ri * 64 + pos] = e;
        float q0 = mix[vi * 3 + 0], q1 = mix[vi * 3 + 1], q2 = mix[vi * 3 + 2];
        float qm = fmaxf(q0, fmaxf(q1, q2));
        float f0 = expf(q0 - qm), f1 = expf(q1 - qm), f2 = expf(q2 - qm);
        float fs = f0 + f1 + f2;
        s_smix[0] = f0 / fs; s_smix[1] = f1 / fs; s_smix[2] = f2 / fs;
        g_normbits[e] = 0u;
        g_hmaxbits[e] = 0u;
        s_pref = 0u; s_rem = 31;
    }
    __syncthreads();
    int vi = s_vidx, ci = s_cidx;

    float ls = 0.f;
    for (int i = tid; i < 2048; i += 256) {
        float v = cp_items[ci * 2048 + i];
        s_cp[i] = v; ls += v;
    }
    s_red[tid] = ls; __syncthreads();
    for (int o = 128; o > 0; o >>= 1) {
        if (tid < o) s_red[tid] += s_red[tid + o];
        __syncthreads();
    }
    float inv = 1.0f / (s_red[0] + 1e-8f);

    // Radix-select V32 = 32nd-largest value (uint keys monotone; values > 0).
    float vloc[8]; unsigned keys[8];
#pragma unroll
    for (int u = 0; u < 8; u++) {
        vloc[u] = s_cp[tid + 256 * u];
        keys[u] = __float_as_uint(vloc[u]);
    }
#pragma unroll
    for (int pass = 0; pass < 4; pass++) {
        int shift = 24 - 8 * pass;
        unsigned mhi = (pass == 0) ? 0u : (0xFFFFFFFFu << (32 - 8 * pass));
        s_hist[tid] = 0;
        __syncthreads();
        unsigned pref = s_pref;
#pragma unroll
        for (int u = 0; u < 8; u++)
            if ((keys[u] & mhi) == pref)
                atomicAdd(&s_hist[(keys[u] >> shift) & 0xFF], 1);
        __syncthreads();
        int rem = s_rem;
        int above = 0;
        for (int b = tid + 1; b < 256; b++) above += s_hist[b];
        if (above <= rem && rem < above + s_hist[tid]) {
            s_pref = pref | ((unsigned)tid << shift);
            s_rem = rem - above;
        }
        __syncthreads();
    }
    unsigned kth = s_pref;
#pragma unroll
    for (int u = 0; u < 8; u++)
        s_wc[tid + 256 * u] = (keys[u] >= kth) ? vloc[u] * inv : 0.f;
    __syncthreads();

    for (int blk = 0; blk < 3; blk++) {
        s_w1[tid] = w1[(vi * 3 + blk) * 256 + tid];
        s_w2[tid] = w2[(vi * 3 + blk) * 256 + tid];
        if (tid < 16) {
            float dp = decays[(vi * 3 + blk) * 16 + tid];
            s_d[tid] = 0.5f + (1.f / (1.f + expf(-dp))) * 0.5f;
            float gp = gains[(vi * 3 + blk) * 16 + tid];
            s_g[tid] = (1.f / (1.f + expf(-gp))) * 5.f;
        }
        __syncthreads();
#pragma unroll
        for (int u = 0; u < 8; u++) {
            int idx = tid + 256 * u;
            int c = idx >> 7, f = idx & 127;
            float acc = 0.f;
#pragma unroll
            for (int k = 0; k < 16; k++)
                acc += s_w1[c * 16 + k] * fmaxf(s_wc[k * 128 + f], 0.f);
            s_x[idx] = acc;
        }
        __syncthreads();
        if (tid < 16) {
            float d = s_d[tid];
            float y = 0.f;
            for (int f = 0; f < 128; f++) {
                y = d * (s_x[tid * 128 + f] + y);
                s_y[tid * 128 + f] = y;
            }
        }
        __syncthreads();
#pragma unroll
        for (int u = 0; u < 8; u++) {
            int idx = tid + 256 * u;
            int c = idx >> 7, f = idx & 127;
            float acc = s_x[idx];
#pragma unroll
            for (int k = 0; k < 16; k++)
                acc += s_w2[c * 16 + k] * s_y[k * 128 + f];
            float co = tanhf(acc * s_g[c]);
            g_cpw[((e * 3 + blk) * 16 + c) * 128 + f] = s_smix[blk] * co;
            s_wc[idx] = co;
        }
        __syncthreads();
    }
}

// ---------------------------------------------------------------------------
// MERGED audio-synthesis + h-computation kernel (flat grid, 2048 blocks).
// ---------------------------------------------------------------------------
__global__ void __launch_bounds__(256, 3) k_ah(const float* __restrict__ audio_maps,
                                               const float* __restrict__ verbs,
                                               const float* __restrict__ times) {
    int bid = blockIdx.x, tid = threadIdx.x;
    __shared__ float s_c[8][48];
    __shared__ float s_red[256];
    __shared__ int s_v;
    __shared__ float s_t[8][128];
    __shared__ int   s_ei[8];
    __shared__ float s_av0[8], s_av1[8];
    __shared__ float s_wm[8][8];

    if (bid < 1024) {
        // ------------- h path -------------
        int chunk = bid & 127, r = bid >> 7;
        int cnt = g_vcount[r];
        if (cnt == 0) return;
        int t0 = chunk << 10;
        const float* vb = verbs + (size_t)r * NS;

        for (int b = 0; b < cnt; b += 8) {
            int nb = min(8, cnt - b);
            if (tid < 8) {
                if (tid < nb) {
                    int e = g_vlist[r * 64 + b + tid];
                    s_ei[tid] = e;
                    s_av0[tid] = g_sc[e].av0;
                    s_av1[tid] = g_sc[e].av1;
                } else s_ei[tid] = -1;
            }
            __syncthreads();
            for (int s = tid; s < 1024; s += 256) {
                int i = s >> 7, f = s & 127;
                s_t[i][f] = (i < nb) ? times[(size_t)g_vlist[r * 64 + b + i] * 128 + f] : 0.f;
            }
            __syncthreads();

            float4 acc[8];
#pragma unroll
            for (int i = 0; i < 8; i++) acc[i] = make_float4(0.f, 0.f, 0.f, 0.f);
            const float4* vbase = reinterpret_cast<const float4*>(vb + t0) + tid;
#pragma unroll 2
            for (int f = 0; f <= chunk; f++) {
                float4 v = vbase[-(f << 8)];
#pragma unroll
                for (int i = 0; i < 8; i++) {
                    float tf = s_t[i][f];
                    acc[i].x += v.x * tf; acc[i].y += v.y * tf;
                    acc[i].z += v.z * tf; acc[i].w += v.w * tf;
                }
            }

            float lm[8];
#pragma unroll
            for (int i = 0; i < 8; i++) lm[i] = 0.f;
            for (int i = 0; i < nb; i++) {
                float a0 = s_av0[i];
                float4 val = make_float4(a0 * acc[i].x, a0 * acc[i].y,
                                         a0 * acc[i].z, a0 * acc[i].w);
                if (tid == 0) val.x += s_av1[i] * s_t[i][chunk];
                reinterpret_cast<float4*>(g_h + (size_t)s_ei[i] * NS + t0)[tid] = val;
                lm[i] = fmaxf(fmaxf(fabsf(val.x), fabsf(val.y)),
                              fmaxf(fabsf(val.z), fabsf(val.w)));
            }
#pragma unroll
            for (int i = 0; i < 8; i++) {
#pragma unroll
                for (int off = 16; off; off >>= 1)
                    lm[i] = fmaxf(lm[i], __shfl_xor_sync(0xffffffffu, lm[i], off));
            }
            int wid = tid >> 5, lane = tid & 31;
            if (lane == 0) {
#pragma unroll
                for (int i = 0; i < 8; i++) s_wm[wid][i] = lm[i];
            }
            __syncthreads();
            if (tid < 8) {
                float m = s_wm[0][tid];
#pragma unroll
                for (int w = 1; w < 8; w++) m = fmaxf(m, s_wm[w][tid]);
                if (tid < nb) atomicMax(&g_hmaxbits[s_ei[tid]], __float_as_uint(m));
            }
            __syncthreads();
        }
    } else {
        // ------------- audio path -------------
        int bid2 = bid - 1024;
        int fg = bid2 & 15, e = bid2 >> 4;
        if (tid == 0) s_v = g_sc[e].vidx;
        for (int s = tid; s < 384; s += 256) {
            int fr = s / 48, ic = s % 48;
            int i = ic >> 4, c = ic & 15;
            s_c[fr][ic] = g_cpw[((e * 3 + i) * 16 + c) * 128 + (fg * 8 + fr)];
        }
        __syncthreads();
        const float* am = audio_maps + (size_t)s_v * 3 * 1024 * 16;
        float acc[8][4];
#pragma unroll
        for (int fr = 0; fr < 8; fr++)
#pragma unroll
            for (int q = 0; q < 4; q++) acc[fr][q] = 0.f;

#pragma unroll
        for (int i = 0; i < 3; i++) {
#pragma unroll
            for (int r = 0; r < 4; r++) {
                float4 a[4];
#pragma unroll
                for (int q = 0; q < 4; q++)
                    a[q] = __ldg(reinterpret_cast<const float4*>(
                               am + (i * 1024 + tid + 256 * q) * 16) + r);
#pragma unroll
                for (int fr = 0; fr < 8; fr++) {
                    float c0 = s_c[fr][i * 16 + 4 * r + 0];
                    float c1 = s_c[fr][i * 16 + 4 * r + 1];
                    float c2 = s_c[fr][i * 16 + 4 * r + 2];
                    float c3 = s_c[fr][i * 16 + 4 * r + 3];
#pragma unroll
                    for (int q = 0; q < 4; q++)
                        acc[fr][q] += a[q].x * c0 + a[q].y * c1 + a[q].z * c2 + a[q].w * c3;
                }
            }
        }
        float lmax = 0.f;
#pragma unroll
        for (int fr = 0; fr < 8; fr++) {
#pragma unroll
            for (int q = 0; q < 4; q++) {
                float v = acc[fr][q];
                g_mixed[e * NS + (fg * 8 + fr) * 1024 + tid + 256 * q] = v;
                lmax = fmaxf(lmax, fabsf(v));
            }
        }
        s_red[tid] = lmax; __syncthreads();
        for (int o = 128; o > 0; o >>= 1) {
            if (tid < o) s_red[tid] = fmaxf(s_red[tid], s_red[tid + o]);
            __syncthreads();
        }
        if (tid == 0) atomicMax(&g_normbits[e], __float_as_uint(s_red[0]));
    }
}

// ---------------------------------------------------------------------------
// FFT passes. MODE 0: fwd pass1 (64 slots) -> zA, zero-padded upper half
// exploited (HALF fft512). MODE 3: inv pass2 + epilogue (reads zB).
// ---------------------------------------------------------------------------
template <int MODE>
__global__ void __launch_bounds__(512) k_fft2(float* __restrict__ out) {
    __shared__ float sRe[8 * SP];
    __shared__ float sIm[8 * SP];
    __shared__ float2 sW[512];
    __shared__ float2 sWB[512];
    int slot = blockIdx.y, tile = blockIdx.x, tid = threadIdx.x;
    int c0 = tile * 8;
    const bool INV = (MODE >= 2);

    sW[tid] = g_twA[tid];
    if (MODE == 0) sWB[tid] = g_twB[tid];

    if (MODE == 0) {
        const float *s1, *s2;
        float f1, f2;
        if (slot < 32) {
            int e1 = 2 * slot, e2 = 2 * slot + 1;
            s1 = g_mixed + (size_t)e1 * NS;
            s2 = g_mixed + (size_t)e2 * NS;
            f1 = 1.0f / (__uint_as_float(g_normbits[e1]) + 1e-8f);
            f2 = 1.0f / (__uint_as_float(g_normbits[e2]) + 1e-8f);
        } else {
            int e1 = 2 * (slot - 32), e2 = e1 + 1;
            s1 = g_h + (size_t)e1 * NS;
            s2 = g_h + (size_t)e2 * NS;
            f1 = 1.0f / (__uint_as_float(g_hmaxbits[e1]) + 1e-20f);
            f2 = 1.0f / (__uint_as_float(g_hmaxbits[e2]) + 1e-20f);
        }
        // stage only r < 256 (r >= 256 is zero padding, handled by HALF fft)
#pragma unroll
        for (int it = 0; it < 4; it++) {
            int lin = tid + 512 * it;
            int f = lin & 7, r = lin >> 3;          // r < 256
            int n = c0 + f + 512 * r;               // n < NS always
            sRe[f * SP + r] = s1[n] * f1;
            sIm[f * SP + r] = s2[n] * f2;
        }
    } else {   // MODE 3: rows of zB, contiguous
#pragma unroll
        for (int it = 0; it < 8; it++) {
            int lin = tid + 512 * it;
            int f = lin >> 9, n1 = lin & 511;
            float2 z = g_zB[(size_t)slot * MF + (c0 + f) * 512 + n1];
            sRe[f * SP + n1] = z.x; sIm[f * SP + n1] = z.y;
        }
    }
    __syncthreads();

    fft512<INV, MODE == 0>(sRe, sIm, sW, tid);

    if (MODE == 0) {
        int f = tid & 7, k0 = tid >> 3;
        int n1 = c0 + f;
        int pb = n1 * k0;
        int ps = n1 * 64;
        float2 w  = cmul(sW[pb >> 9], sWB[pb & 511]);   // W_MF^(n1*k0)
        float2 st = cmul(sW[ps >> 9], sWB[ps & 511]);   // W_MF^(n1*64)
#pragma unroll
        for (int it = 0; it < 8; it++) {
            int k = k0 + 64 * it;
            float2 v = make_float2(sRe[f * SP + k], sIm[f * SP + k]);
            g_zA[(size_t)slot * MF + k * 512 + n1] = cmul(v, w);
            w = cmul(w, st);
        }
    } else {
        int e1 = 2 * slot, e2 = 2 * slot + 1;
        const float invm = 1.0f / (float)MF;
        float sc1 = (__uint_as_float(g_hmaxbits[e1]) + 1e-20f) * invm;
        float sc2 = (__uint_as_float(g_hmaxbits[e2]) + 1e-20f) * invm;
        float* o1 = out + (size_t)e1 * NS;
        float* o2 = out + (size_t)e2 * NS;
#pragma unroll
        for (int it = 0; it < 4; it++) {   // only k < 256 -> t < NS
            int lin = tid + 512 * it;
            int f = lin & 7, k = lin >> 3;
            int t = (c0 + f) + 512 * k;
            o1[t] = sRe[f * SP + k] * sc1;
            o2[t] = sIm[f * SP + k] * sc2;
        }
    }
}

// ---------------------------------------------------------------------------
// Fused forward pass-2 + combine + INVERSE pass-1 (unchanged logic, SP pad).
// ---------------------------------------------------------------------------
__device__ __forceinline__ float2 ldbuf(const float* sRe, const float* sIm, int i, int k) {
    return make_float2(sRe[i * SP + k], sIm[i * SP + k]);
}
__device__ __forceinline__ void stbuf(float* sRe, float* sIm, int i, int k, float2 v) {
    sRe[i * SP + k] = v.x; sIm[i * SP + k] = v.y;
}

__global__ void __launch_bounds__(512, 2) k_fc2() {
    __shared__ float sRe[8 * SP];
    __shared__ float sIm[8 * SP];
    __shared__ float2 sW[512];
    int p = blockIdx.y, T = blockIdx.x, tid = threadIdx.x;
    sW[tid] = g_twA[tid];

    float2 park[8];

#pragma unroll
    for (int half = 0; half < 2; half++) {
        int t = 2 * T + half;
        int rows4[4];
        if (t == 0) { rows4[0] = 0; rows4[1] = 256; rows4[2] = 1; rows4[3] = 511; }
        else { rows4[0] = 2 * t; rows4[1] = 512 - 2 * t;
               rows4[2] = 2 * t + 1; rows4[3] = 511 - 2 * t; }
        if (half) __syncthreads();    // half0 product reads complete before overwrite
#pragma unroll
        for (int it = 0; it < 8; it++) {
            int sl = (it < 4) ? p : (32 + p);
            float2 z = g_zA[(size_t)sl * MF + rows4[it & 3] * 512 + tid];
            sRe[it * SP + tid] = z.x; sIm[it * SP + tid] = z.y;
        }
        __syncthreads();

        fft512<false, false>(sRe, sIm, sW, tid);

        int o = half * 4;
        if (t == 0) {
            {   // row 0 (self-mirror: col (512-k2)&511)
                int kp = (512 - tid) & 511;
                float2 Za = ldbuf(sRe, sIm, 0, tid), Zb = ldbuf(sRe, sIm, 0, kp);
                float2 Ha = ldbuf(sRe, sIm, 4, tid), Hb = ldbuf(sRe, sIm, 4, kp);
                float2 M1 = make_float2(0.5f*(Za.x+Zb.x), 0.5f*(Za.y-Zb.y));
                float2 M2 = make_float2(0.5f*(Za.y+Zb.y), 0.5f*(Zb.x-Za.x));
                float2 H1 = make_float2(0.5f*(Ha.x+Hb.x), 0.5f*(Ha.y-Hb.y));
                float2 H2 = make_float2(0.5f*(Ha.y+Hb.y), 0.5f*(Hb.x-Ha.x));
                float2 P1 = cmul(M1, H1), P2 = cmul(M2, H2);
                park[o + 0] = make_float2(P1.x - P2.y, P1.y + P2.x);   // row 0 @ tid
            }
            {   // row 256 (self-mirror: col 511-k2)
                int kp = 511 - tid;
                float2 Za = ldbuf(sRe, sIm, 1, tid), Zb = ldbuf(sRe, sIm, 1, kp);
                float2 Ha = ldbuf(sRe, sIm, 5, tid), Hb = ldbuf(sRe, sIm, 5, kp);
                float2 M1 = make_float2(0.5f*(Za.x+Zb.x), 0.5f*(Za.y-Zb.y));
                float2 M2 = make_float2(0.5f*(Za.y+Zb.y), 0.5f*(Zb.x-Za.x));
                float2 H1 = make_float2(0.5f*(Ha.x+Hb.x), 0.5f*(Ha.y-Hb.y));
                float2 H2 = make_float2(0.5f*(Ha.y+Hb.y), 0.5f*(Hb.x-Ha.x));
                float2 P1 = cmul(M1, H1), P2 = cmul(M2, H2);
                park[o + 1] = make_float2(P1.x - P2.y, P1.y + P2.x);   // row 256 @ tid
            }
            {   // pair (1, 511)
                int kp = 511 - tid;
                float2 Za = ldbuf(sRe, sIm, 2, tid), Zb = ldbuf(sRe, sIm, 3, kp);
                float2 Ha = ldbuf(sRe, sIm, 6, tid), Hb = ldbuf(sRe, sIm, 7, kp);
                float2 M1 = make_float2(0.5f*(Za.x+Zb.x), 0.5f*(Za.y-Zb.y));
                float2 M2 = make_float2(0.5f*(Za.y+Zb.y), 0.5f*(Zb.x-Za.x));
                float2 H1 = make_float2(0.5f*(Ha.x+Hb.x), 0.5f*(Ha.y-Hb.y));
                float2 H2 = make_float2(0.5f*(Ha.y+Hb.y), 0.5f*(Hb.x-Ha.x));
                float2 P1 = cmul(M1, H1), P2 = cmul(M2, H2);
                park[o + 2] = make_float2(P1.x - P2.y, P1.y + P2.x);   // row 1 @ tid
                park[o + 3] = make_float2(P1.x + P2.y, P2.x - P1.y);   // row 511 @ 511-tid
            }
        } else {
#pragma unroll
            for (int pr = 0; pr < 2; pr++) {
                int ia = 2 * pr, ib = 2 * pr + 1;
                int kp = 511 - tid;
                float2 Za = ldbuf(sRe, sIm, ia, tid), Zb = ldbuf(sRe, sIm, ib, kp);
                float2 Ha = ldbuf(sRe, sIm, ia + 4, tid), Hb = ldbuf(sRe, sIm, ib + 4, kp);
                float2 M1 = make_float2(0.5f*(Za.x+Zb.x), 0.5f*(Za.y-Zb.y));
                float2 M2 = make_float2(0.5f*(Za.y+Zb.y), 0.5f*(Zb.x-Za.x));
                float2 H1 = make_float2(0.5f*(Ha.x+Hb.x), 0.5f*(Ha.y-Hb.y));
                float2 H2 = make_float2(0.5f*(Ha.y+Hb.y), 0.5f*(Hb.x-Ha.x));
                float2 P1 = cmul(M1, H1), P2 = cmul(M2, H2);
                park[o + 2 * pr + 0] = make_float2(P1.x - P2.y, P1.y + P2.x);  // rows4[ia] @ tid
                park[o + 2 * pr + 1] = make_float2(P1.x + P2.y, P2.x - P1.y);  // rows4[ib] @ 511-tid
            }
        }
    }
    __syncthreads();   // all product reads done before buffer overwrite

    // Scatter the 8 product rows into buffers (buf f -> row n1(f) below).
    int kinv = 511 - tid;
    int c7 = (T == 0) ? tid : kinv;          // T=0: park[1] is row 256 @ tid
    stbuf(sRe, sIm, 0, tid,  park[0]);       // row 4T      (T=0: row 0)
    stbuf(sRe, sIm, 7, c7,   park[1]);       // row 512-4T  (T=0: row 256)
    stbuf(sRe, sIm, 1, tid,  park[2]);       // row 4T+1    (T=0: row 1)
    stbuf(sRe, sIm, 6, kinv, park[3]);       // row 511-4T  (T=0: row 511)
    stbuf(sRe, sIm, 2, tid,  park[4]);       // row 4T+2
    stbuf(sRe, sIm, 5, kinv, park[5]);       // row 510-4T
    stbuf(sRe, sIm, 3, tid,  park[6]);       // row 4T+3
    stbuf(sRe, sIm, 4, kinv, park[7]);       // row 509-4T
    __syncthreads();

    fft512<true, false>(sRe, sIm, sW, tid);

    // inverse inter-pass twiddle + transposed store to zB
    int f = tid & 7, k0 = tid >> 3;
    int n1;
    if (T == 0) n1 = (f < 4) ? f : (f == 7 ? 256 : 505 + f);
    else        n1 = (f < 4) ? (4 * T + f) : (505 - 4 * T + f);
    int pb = n1 * k0, ps = n1 * 64;
    float2 w  = cmul(sW[pb >> 9], g_twB[pb & 511]); w.y  = -w.y;
    float2 st = cmul(sW[ps >> 9], g_twB[ps & 511]); st.y = -st.y;
#pragma unroll
    for (int it = 0; it < 8; it++) {
        int k = k0 + 64 * it;
        float2 v = make_float2(sRe[f * SP + k], sIm[f * SP + k]);
        g_zB[(size_t)p * MF + k * 512 + n1] = cmul(v, w);
        w = cmul(w, st);
    }
}

// ---------------------------------------------------------------------------
extern "C" void kernel_launch(void* const* d_in, const int* in_sizes, int n_in,
                              void* d_out, int out_size) {
    const float* voice    = (const float*)d_in[0];
    const float* cpc      = (const float*)d_in[1];
    const float* amp      = (const float*)d_in[2];
    const float* rooml    = (const float*)d_in[3];
    const float* rmix     = (const float*)d_in[4];
    const float* times    = (const float*)d_in[5];
    const float* cp_items = (const float*)d_in[6];
    const float* verbs    = (const float*)d_in[7];
    const float* w1       = (const float*)d_in[8];
    const float* w2       = (const float*)d_in[9];
    const float* amaps    = (const float*)d_in[10];
    const float* decays   = (const float*)d_in[11];
    const float* gains    = (const float*)d_in[12];
    const float* mix      = (const float*)d_in[13];
    float* out = (float*)d_out;

    k_tw1<<<1, 512>>>();
    k_prep<<<64, 256>>>(voice, cpc, amp, rooml, rmix, cp_items, w1, w2, decays, gains, mix);
    k_ah<<<2048, 256>>>(amaps, verbs, times);     // h (1024 blocks) + audio (1024 blocks)
    k_fft2<0><<<dim3(64, 64), 512>>>(out);        // fwd pass1 (zero-padded half skipped)
    k_fc2<<<dim3(64, 32), 512>>>();               // fwd pass2 + combine + inv pass1 -> zB
    k_fft2<3><<<dim3(64, 32), 512>>>(out);        // inv pass2 + epilogue
}